// round 3
// baseline (speedup 1.0000x reference)
#include <cuda_runtime.h>
#include <cuda_bf16.h>

// =============================================================
// NonLocalBlock: B=16, C=512, Ci=256, H=W=64, N=4096
//   proj  : [g;theta;phi] (768x512) @ x[b] (512x4096) -> proj[b] (768x4096)
//   f     : theta (256x4096) @ phi^T (4096x256) -> f[b] (256x256)  (split-K)
//   softmax rows of f
//   y     : f (256x256) @ g (256x4096) -> y[b] (256x4096)
//   z     : W_w (512x256) @ y (256x4096) + W_b -> z[b] (512x4096)
//   BN(train stats over B,H,W) * gamma + beta + x -> out
// =============================================================

#define BATCH 16
#define CCH   512
#define CI    256
#define NPIX  4096
#define SPLITK 8

// ---- scratch (device globals; no allocation allowed) ----
__device__ float d_proj[(size_t)BATCH * 768 * NPIX];          // 201 MB
__device__ float d_wstack[768 * CCH];                         // 1.5 MB
__device__ float d_bstack[768];
__device__ float d_fpart[(size_t)BATCH * SPLITK * CI * CI];   // 33.5 MB
__device__ float d_f[(size_t)BATCH * CI * CI];                // 4.2 MB
__device__ float d_y[(size_t)BATCH * CI * NPIX];              // 67 MB
__device__ float d_z[(size_t)BATCH * CCH * NPIX];             // 134 MB
__device__ float d_stats[2 * CCH];                            // mean | rstd

// =============================================================
// Generic NN SGEMM: C[b] = A[b] (MxK row-major) * B[b] (KxN row-major) + bias
// BM=128 BN=128 BK=8 TM=8 TN=8, 256 threads. M,N,K multiples of tile dims.
// =============================================================
__global__ __launch_bounds__(256) void sgemm_nn_128(
    const float* __restrict__ Ag, const float* __restrict__ Bg,
    float* __restrict__ Cg, const float* __restrict__ bias,
    int M, int N, int K,
    long long sA, long long sB, long long sC)
{
    const float* A = Ag + (long long)blockIdx.z * sA;
    const float* B = Bg + (long long)blockIdx.z * sB;
    float*       C = Cg + (long long)blockIdx.z * sC;

    const int rowStart = blockIdx.y * 128;
    const int colStart = blockIdx.x * 128;

    __shared__ float As[8][128];
    __shared__ float Bs[8][128];

    const int tid  = threadIdx.x;
    const int tRow = tid >> 4;          // 0..15
    const int tCol = tid & 15;          // 0..15

    // A loader: one float4 along K per thread. aRow 0..127, aK {0,4}
    const int aRow = tid >> 1;
    const int aK   = (tid & 1) * 4;
    // B loader: one float4 along N per thread. bRow 0..7, bCol 0..124
    const int bRow = tid >> 5;
    const int bCol = (tid & 31) * 4;

    float acc[8][8];
    #pragma unroll
    for (int i = 0; i < 8; i++)
        #pragma unroll
        for (int j = 0; j < 8; j++) acc[i][j] = 0.f;

    for (int k0 = 0; k0 < K; k0 += 8) {
        float4 av = *(const float4*)&A[(long long)(rowStart + aRow) * K + k0 + aK];
        As[aK + 0][aRow] = av.x;
        As[aK + 1][aRow] = av.y;
        As[aK + 2][aRow] = av.z;
        As[aK + 3][aRow] = av.w;
        float4 bv = *(const float4*)&B[(long long)(k0 + bRow) * N + colStart + bCol];
        *(float4*)&Bs[bRow][bCol] = bv;
        __syncthreads();

        #pragma unroll
        for (int k = 0; k < 8; k++) {
            float ra[8], rb[8];
            #pragma unroll
            for (int i = 0; i < 8; i++) ra[i] = As[k][tRow * 8 + i];
            #pragma unroll
            for (int j = 0; j < 8; j++) rb[j] = Bs[k][tCol * 8 + j];
            #pragma unroll
            for (int i = 0; i < 8; i++)
                #pragma unroll
                for (int j = 0; j < 8; j++) acc[i][j] += ra[i] * rb[j];
        }
        __syncthreads();
    }

    #pragma unroll
    for (int i = 0; i < 8; i++) {
        const int gr = rowStart + tRow * 8 + i;
        const float bvv = bias ? bias[gr] : 0.f;
        float* cp = C + (long long)gr * N + colStart + tCol * 8;
        #pragma unroll
        for (int j = 0; j < 8; j++) cp[j] = acc[i][j] + bvv;
    }
}

// =============================================================
// NT split-K GEMM for f = theta @ phi^T.
// A = theta base (per-batch stride 768*NPIX applied here), ld=4096
// B = phi base, ld=4096.  M=N=256, K=4096 split into SPLITK chunks.
// Output partials: fpart[p][256][256], p = b*SPLITK + s.
// 64x64 tile, BK=16, 256 threads, 4x4 per thread.
// =============================================================
__global__ __launch_bounds__(256) void sgemm_nt_splitk(
    const float* __restrict__ thetaBase, const float* __restrict__ phiBase,
    float* __restrict__ fpart)
{
    const int p = blockIdx.z;
    const int b = p / SPLITK;
    const int s = p % SPLITK;
    const int Kc = NPIX / SPLITK;           // 512
    const int kStart = s * Kc;

    const float* A = thetaBase + (long long)b * (768LL * NPIX);
    const float* B = phiBase   + (long long)b * (768LL * NPIX);

    const int rowStart = blockIdx.y * 64;
    const int colStart = blockIdx.x * 64;

    __shared__ float As[16][64];
    __shared__ float Bs[16][64];

    const int tid  = threadIdx.x;
    const int tRow = tid >> 4;
    const int tCol = tid & 15;
    const int lRow = tid >> 2;              // 0..63
    const int lK   = (tid & 3) * 4;         // 0,4,8,12

    float acc[4][4];
    #pragma unroll
    for (int i = 0; i < 4; i++)
        #pragma unroll
        for (int j = 0; j < 4; j++) acc[i][j] = 0.f;

    for (int k0 = kStart; k0 < kStart + Kc; k0 += 16) {
        float4 av = *(const float4*)&A[(long long)(rowStart + lRow) * NPIX + k0 + lK];
        As[lK + 0][lRow] = av.x;
        As[lK + 1][lRow] = av.y;
        As[lK + 2][lRow] = av.z;
        As[lK + 3][lRow] = av.w;
        float4 bv = *(const float4*)&B[(long long)(colStart + lRow) * NPIX + k0 + lK];
        Bs[lK + 0][lRow] = bv.x;
        Bs[lK + 1][lRow] = bv.y;
        Bs[lK + 2][lRow] = bv.z;
        Bs[lK + 3][lRow] = bv.w;
        __syncthreads();

        #pragma unroll
        for (int k = 0; k < 16; k++) {
            float ra[4], rb[4];
            #pragma unroll
            for (int i = 0; i < 4; i++) ra[i] = As[k][tRow * 4 + i];
            #pragma unroll
            for (int j = 0; j < 4; j++) rb[j] = Bs[k][tCol * 4 + j];
            #pragma unroll
            for (int i = 0; i < 4; i++)
                #pragma unroll
                for (int j = 0; j < 4; j++) acc[i][j] += ra[i] * rb[j];
        }
        __syncthreads();
    }

    float* Cp = fpart + (long long)p * (CI * CI);
    #pragma unroll
    for (int i = 0; i < 4; i++) {
        float* cp = Cp + (rowStart + tRow * 4 + i) * CI + colStart + tCol * 4;
        #pragma unroll
        for (int j = 0; j < 4; j++) cp[j] = acc[i][j];
    }
}

// =============================================================
// Softmax over rows of f (sums split-K partials first).
// One block (256 threads) per row; row = b*256 + c; element d = tid.
// =============================================================
__global__ __launch_bounds__(256) void softmax_rows(
    const float* __restrict__ fpart, float* __restrict__ f)
{
    const int row = blockIdx.x;             // 0..4095
    const int b = row >> 8;
    const int c = row & 255;
    const int d = threadIdx.x;

    float v = 0.f;
    #pragma unroll
    for (int s = 0; s < SPLITK; s++)
        v += fpart[((long long)(b * SPLITK + s)) * (CI * CI) + c * CI + d];

    __shared__ float red[256];
    red[d] = v;
    __syncthreads();
    for (int off = 128; off > 0; off >>= 1) {
        if (d < off) red[d] = fmaxf(red[d], red[d + off]);
        __syncthreads();
    }
    const float m = red[0];
    __syncthreads();
    const float e = __expf(v - m);
    red[d] = e;
    __syncthreads();
    for (int off = 128; off > 0; off >>= 1) {
        if (d < off) red[d] += red[d + off];
        __syncthreads();
    }
    f[(long long)row * CI + d] = e / red[0];
}

// =============================================================
// Per-channel BN stats over (B, N): one block per channel.
// =============================================================
__global__ __launch_bounds__(256) void bn_stats(
    const float* __restrict__ z, float* __restrict__ stats)
{
    const int c = blockIdx.x;
    const int t = threadIdx.x;
    float s = 0.f, sq = 0.f;
    for (int b = 0; b < BATCH; b++) {
        const float* p = z + ((long long)b * CCH + c) * NPIX;
        for (int n = t; n < NPIX; n += 256) {
            const float v = p[n];
            s  += v;
            sq += v * v;
        }
    }
    __shared__ float rs[256], rq[256];
    rs[t] = s; rq[t] = sq;
    __syncthreads();
    for (int off = 128; off > 0; off >>= 1) {
        if (t < off) { rs[t] += rs[t + off]; rq[t] += rq[t + off]; }
        __syncthreads();
    }
    if (t == 0) {
        const float cnt = (float)(BATCH * NPIX);
        const float m = rs[0] / cnt;
        const float var = rq[0] / cnt - m * m;
        stats[c]       = m;
        stats[CCH + c] = rsqrtf(var + 1e-5f);
    }
}

// =============================================================
// out = (z - mean)*rstd*gamma + beta + x   (float4 vectorized)
// =============================================================
__global__ __launch_bounds__(256) void bn_residual(
    const float* __restrict__ z, const float* __restrict__ x,
    const float* __restrict__ gamma, const float* __restrict__ beta,
    const float* __restrict__ stats, float* __restrict__ out)
{
    const long long i = (long long)blockIdx.x * blockDim.x + threadIdx.x; // float4 idx
    const int c = (int)((i >> 10) & (CCH - 1));   // (i*4 / 4096) % 512
    const float m  = stats[c];
    const float r  = stats[CCH + c];
    const float g  = gamma[c];
    const float bb = beta[c];
    const float4 zv = ((const float4*)z)[i];
    const float4 xv = ((const float4*)x)[i];
    float4 o;
    o.x = (zv.x - m) * r * g + bb + xv.x;
    o.y = (zv.y - m) * r * g + bb + xv.y;
    o.z = (zv.z - m) * r * g + bb + xv.z;
    o.w = (zv.w - m) * r * g + bb + xv.w;
    ((float4*)out)[i] = o;
}

// =============================================================
// Launch
// =============================================================
extern "C" void kernel_launch(void* const* d_in, const int* in_sizes, int n_in,
                              void* d_out, int out_size)
{
    (void)in_sizes; (void)n_in; (void)out_size;
    const float* x     = (const float*)d_in[0];
    const float* g_w   = (const float*)d_in[1];
    const float* g_b   = (const float*)d_in[2];
    const float* th_w  = (const float*)d_in[3];
    const float* th_b  = (const float*)d_in[4];
    const float* ph_w  = (const float*)d_in[5];
    const float* ph_b  = (const float*)d_in[6];
    const float* W_w   = (const float*)d_in[7];
    const float* W_b   = (const float*)d_in[8];
    const float* gamma = (const float*)d_in[9];
    const float* beta  = (const float*)d_in[10];
    float* out = (float*)d_out;

    float *proj, *wstack, *bstack, *fpart, *f, *y, *z, *stats;
    cudaGetSymbolAddress((void**)&proj,   d_proj);
    cudaGetSymbolAddress((void**)&wstack, d_wstack);
    cudaGetSymbolAddress((void**)&bstack, d_bstack);
    cudaGetSymbolAddress((void**)&fpart,  d_fpart);
    cudaGetSymbolAddress((void**)&f,      d_f);
    cudaGetSymbolAddress((void**)&y,      d_y);
    cudaGetSymbolAddress((void**)&z,      d_z);
    cudaGetSymbolAddress((void**)&stats,  d_stats);

    // stack weights [g; theta; phi] and biases (capturable D2D copies)
    cudaMemcpyAsync(wstack,              g_w,  (size_t)CI * CCH * 4, cudaMemcpyDeviceToDevice);
    cudaMemcpyAsync(wstack + 1 * CI*CCH, th_w, (size_t)CI * CCH * 4, cudaMemcpyDeviceToDevice);
    cudaMemcpyAsync(wstack + 2 * CI*CCH, ph_w, (size_t)CI * CCH * 4, cudaMemcpyDeviceToDevice);
    cudaMemcpyAsync(bstack,          g_b,  CI * 4, cudaMemcpyDeviceToDevice);
    cudaMemcpyAsync(bstack + CI,     th_b, CI * 4, cudaMemcpyDeviceToDevice);
    cudaMemcpyAsync(bstack + 2 * CI, ph_b, CI * 4, cudaMemcpyDeviceToDevice);

    const long long xStride    = (long long)CCH * NPIX;     // 2097152
    const long long projStride = 768LL * NPIX;              // 3145728
    const long long yStride    = (long long)CI * NPIX;      // 1048576
    const long long zStride    = (long long)CCH * NPIX;     // 2097152

    // 1) fused projections: proj[b] = wstack @ x[b] + bstack
    sgemm_nn_128<<<dim3(NPIX / 128, 768 / 128, BATCH), 256>>>(
        wstack, x, proj, bstack, 768, NPIX, CCH, 0, xStride, projStride);

    // 2) f partials = theta @ phi^T (split-K)
    sgemm_nt_splitk<<<dim3(CI / 64, CI / 64, BATCH * SPLITK), 256>>>(
        proj + (long long)CI * NPIX,       // theta rows 256..511
        proj + 2LL * CI * NPIX,            // phi rows 512..767
        fpart);

    // 3) softmax over rows
    softmax_rows<<<BATCH * CI, 256>>>(fpart, f);

    // 4) y[b] = f[b] @ g[b]
    sgemm_nn_128<<<dim3(NPIX / 128, CI / 128, BATCH), 256>>>(
        f, proj, y, nullptr, CI, NPIX, CI,
        (long long)CI * CI, projStride, yStride);

    // 5) z[b] = W_w @ y[b] + W_b
    sgemm_nn_128<<<dim3(NPIX / 128, CCH / 128, BATCH), 256>>>(
        W_w, y, z, W_b, CCH, NPIX, CI, 0, yStride, zStride);

    // 6) BN stats
    bn_stats<<<CCH, 256>>>(z, stats);

    // 7) BN + residual
    const long long total4 = (long long)BATCH * CCH * NPIX / 4;   // 8388608
    bn_residual<<<(unsigned)(total4 / 256), 256>>>(z, x, gamma, beta, stats, out);
}

// round 5
// speedup vs baseline: 2.6557x; 2.6557x over previous
#include <cuda_runtime.h>
#include <cuda_bf16.h>
#include <cstdint>

#define BATCH 16
#define CCH   512
#define CI    256
#define NPIX  4096

// ---------------- scratch (device globals; no allocation allowed) ----------------
static const size_t XT_SZ  = (size_t)BATCH * NPIX * CCH;   // per level
static const size_t TP_SZ  = (size_t)BATCH * 512 * NPIX;
static const size_t GT_SZ  = (size_t)BATCH * NPIX * CI;
static const size_t F_SZ   = (size_t)BATCH * CI * CI;
static const size_t YT_SZ  = (size_t)BATCH * NPIX * CI;

__device__ __nv_bfloat16 d_xt [3][(size_t)BATCH * NPIX * CCH];
__device__ __nv_bfloat16 d_wtp[3][512 * 512];
__device__ __nv_bfloat16 d_gw [2][CI * CCH];
__device__ __nv_bfloat16 d_ww [2][CCH * CI];
__device__ __nv_bfloat16 d_tp [3][(size_t)BATCH * 512 * NPIX];
__device__ __nv_bfloat16 d_gt [2][(size_t)BATCH * NPIX * CI];
__device__ float         d_fpart[(size_t)4 * BATCH * CI * CI];
__device__ __nv_bfloat16 d_fsm[2][(size_t)BATCH * CI * CI];
__device__ __nv_bfloat16 d_yt [2][(size_t)BATCH * NPIX * CI];
__device__ float         d_z[(size_t)BATCH * CCH * NPIX];
__device__ float         d_stats[2 * CCH];
__device__ float         d_tpb[512];

// ---------------- helpers (arch-portable PTX only: sm_80+) ----------------
__device__ __forceinline__ uint32_t smem_u32(const void* p) {
    uint32_t a;
    asm("{ .reg .u64 t; cvta.to.shared.u64 t, %1; cvt.u32.u64 %0, t; }" : "=r"(a) : "l"(p));
    return a;
}
#define SMEM_SWIZZLE_128B(o) ((o) ^ (((o) >> 3) & 0x70))

__device__ __forceinline__ void cpasync16(uint32_t dst, const void* src) {
    asm volatile("cp.async.cg.shared.global [%0], [%1], 16;" :: "r"(dst), "l"(src));
}
#define CP_COMMIT() asm volatile("cp.async.commit_group;" ::: "memory")

__device__ __forceinline__ void ldsm4(uint32_t addr, uint32_t& r0, uint32_t& r1,
                                      uint32_t& r2, uint32_t& r3) {
    asm volatile("ldmatrix.sync.aligned.m8n8.x4.shared.b16 {%0,%1,%2,%3}, [%4];"
                 : "=r"(r0), "=r"(r1), "=r"(r2), "=r"(r3) : "r"(addr));
}
__device__ __forceinline__ void mma16816(float* c, const uint32_t* a, uint32_t b0, uint32_t b1) {
    asm volatile(
        "mma.sync.aligned.m16n8k16.row.col.f32.bf16.bf16.f32 "
        "{%0,%1,%2,%3}, {%4,%5,%6,%7}, {%8,%9}, {%0,%1,%2,%3};"
        : "+f"(c[0]), "+f"(c[1]), "+f"(c[2]), "+f"(c[3])
        : "r"(a[0]), "r"(a[1]), "r"(a[2]), "r"(a[3]), "r"(b0), "r"(b1));
}

// =====================================================================
// Generic NT GEMM on tensor cores (mma.sync bf16, fp32 acc):
//   D[M,N] = sum over products  A_i[M,K] * B_j[N,K]^T
// A,B: split-bf16 level arrays, K-major (ld = K).
// CTA tile 128x128, 8 warps (warp tile 64x32), K-chunk 64,
// SW128-swizzled smem, cp.async double buffer.
// MODE: 0 = fp32 out, 1 = hi/lo bf16 out, 2 = hi/mid/lo bf16 out.
// grid = (N/128, M/128, batch*nsplit)
// =====================================================================
template <int L, int MODE>
__global__ __launch_bounds__(256) void mma_nt(
    const __nv_bfloat16* __restrict__ a0, const __nv_bfloat16* __restrict__ a1,
    const __nv_bfloat16* __restrict__ a2,
    const __nv_bfloat16* __restrict__ b0, const __nv_bfloat16* __restrict__ b1,
    const __nv_bfloat16* __restrict__ b2,
    float* __restrict__ cf,
    __nv_bfloat16* __restrict__ c0, __nv_bfloat16* __restrict__ c1,
    __nv_bfloat16* __restrict__ c2,
    const float* __restrict__ biasRow, const float* __restrict__ biasCol,
    int M, int N, int K, int nsplit,
    long long sA, long long sB, long long sC)
{
    constexpr int TILE = 16384;             // 128 rows x 128 bytes (64 bf16)
    constexpr int NT = 2 * L;
    constexpr int PRN = (L == 2) ? 3 : 6;
    constexpr int PA[6] = {0, 0, 1, 0, 2, 1};
    constexpr int PB[6] = {0, 1, 0, 2, 0, 1};
    const int stageBytes = NT * TILE;

    extern __shared__ char smraw[];
    const uint32_t smem_base = (smem_u32(smraw) + 1023u) & ~1023u;

    const int tid = threadIdx.x;
    const int wid = tid >> 5, lid = tid & 31;
    const int warpM = (wid & 1) * 64;       // 2 warps over M
    const int warpN = (wid >> 1) * 32;      // 4 warps over N

    const int bz = blockIdx.z;
    const int b  = bz / nsplit, sp = bz % nsplit;
    const int Ksub = K / nsplit;
    const int nk = Ksub / 64;
    const int k0base = sp * Ksub;
    const int mBase = blockIdx.y * 128;
    const int nBase = blockIdx.x * 128;

    const __nv_bfloat16* ta[NT];
    {
        const __nv_bfloat16* as_[3] = {a0, a1, a2};
        const __nv_bfloat16* bs_[3] = {b0, b1, b2};
        #pragma unroll
        for (int l = 0; l < L; l++) {
            ta[l]     = as_[l] + (size_t)b * sA;
            ta[L + l] = bs_[l] + (size_t)b * sB;
        }
    }

    auto loadChunk = [&](int ci, int st) {
        const int k0 = k0base + ci * 64;
        const uint32_t sb = smem_base + st * stageBytes;
        #pragma unroll
        for (int t = 0; t < NT; t++) {
            const int rb = (t < L) ? mBase : nBase;
            const __nv_bfloat16* src = ta[t] + (size_t)rb * K + k0;
            const uint32_t tb = sb + t * TILE;
            #pragma unroll
            for (int i = tid; i < 1024; i += 256) {
                const int row = i >> 3, seg = i & 7;
                cpasync16(tb + SMEM_SWIZZLE_128B(row * 128 + seg * 16),
                          src + (size_t)row * K + seg * 8);
            }
        }
    };

    float acc[4][4][4];
    #pragma unroll
    for (int i = 0; i < 4; i++)
        #pragma unroll
        for (int j = 0; j < 4; j++)
            #pragma unroll
            for (int k = 0; k < 4; k++) acc[i][j][k] = 0.f;

    loadChunk(0, 0); CP_COMMIT();
    loadChunk(1, 1); CP_COMMIT();

    const int lRow = lid & 15;              // ldmatrix row within 16
    const int lHi  = (lid >> 4) & 1;        // ldmatrix 16B half select

    for (int i = 0; i < nk; i++) {
        const int cur = i & 1;
        if (i + 1 < nk) asm volatile("cp.async.wait_group 1;" ::: "memory");
        else            asm volatile("cp.async.wait_group 0;" ::: "memory");
        __syncthreads();

        const uint32_t sb = smem_base + cur * stageBytes;
        #pragma unroll
        for (int p = 0; p < PRN; p++) {
            const uint32_t Ab = sb + PA[p] * TILE;
            const uint32_t Bb = sb + (L + PB[p]) * TILE;
            #pragma unroll
            for (int ks = 0; ks < 4; ks++) {
                const int colB = ks * 32 + lHi * 16;
                uint32_t a[4][4];
                #pragma unroll
                for (int mi = 0; mi < 4; mi++) {
                    const int row = warpM + 16 * mi + lRow;
                    ldsm4(Ab + SMEM_SWIZZLE_128B(row * 128 + colB),
                          a[mi][0], a[mi][1], a[mi][2], a[mi][3]);
                }
                uint32_t bt[2][4];
                #pragma unroll
                for (int nj = 0; nj < 2; nj++) {
                    const int row = warpN + 16 * nj + lRow;
                    ldsm4(Bb + SMEM_SWIZZLE_128B(row * 128 + colB),
                          bt[nj][0], bt[nj][1], bt[nj][2], bt[nj][3]);
                }
                #pragma unroll
                for (int mi = 0; mi < 4; mi++)
                    #pragma unroll
                    for (int jn = 0; jn < 4; jn++)
                        mma16816(acc[mi][jn], a[mi],
                                 bt[jn >> 1][jn & 1], bt[jn >> 1][2 + (jn & 1)]);
            }
        }
        __syncthreads();
        if (i + 2 < nk) { loadChunk(i + 2, cur); CP_COMMIT(); }
    }

    // ---- epilogue ----
    const int gr = lid >> 2;            // 0..7
    const int gc = (lid & 3) * 2;       // 0,2,4,6
    const size_t cOff = (size_t)bz * sC;

    #pragma unroll
    for (int mi = 0; mi < 4; mi++) {
        const int row0 = mBase + warpM + 16 * mi + gr;
        const int row1 = row0 + 8;
        const float br0 = biasRow ? biasRow[row0] : 0.f;
        const float br1 = biasRow ? biasRow[row1] : 0.f;
        #pragma unroll
        for (int jn = 0; jn < 4; jn++) {
            const int col = nBase + warpN + 8 * jn + gc;
            float v00 = acc[mi][jn][0] + br0;
            float v01 = acc[mi][jn][1] + br0;
            float v10 = acc[mi][jn][2] + br1;
            float v11 = acc[mi][jn][3] + br1;
            if (biasCol) {
                const float bc0 = biasCol[col], bc1 = biasCol[col + 1];
                v00 += bc0; v01 += bc1; v10 += bc0; v11 += bc1;
            }
            const size_t base0 = cOff + (size_t)row0 * N + col;
            const size_t base1 = cOff + (size_t)row1 * N + col;
            if (MODE == 0) {
                *(float2*)(cf + base0) = make_float2(v00, v01);
                *(float2*)(cf + base1) = make_float2(v10, v11);
            } else {
                float vv[2][2] = {{v00, v01}, {v10, v11}};
                const size_t bb[2] = {base0, base1};
                #pragma unroll
                for (int r = 0; r < 2; r++) {
                    __nv_bfloat16 h0 = __float2bfloat16(vv[r][0]);
                    __nv_bfloat16 h1 = __float2bfloat16(vv[r][1]);
                    float r0 = vv[r][0] - __bfloat162float(h0);
                    float r1 = vv[r][1] - __bfloat162float(h1);
                    __nv_bfloat162 th; th.x = h0; th.y = h1;
                    *(__nv_bfloat162*)(c0 + bb[r]) = th;
                    if (MODE == 1) {
                        __nv_bfloat162 tl;
                        tl.x = __float2bfloat16(r0); tl.y = __float2bfloat16(r1);
                        *(__nv_bfloat162*)(c1 + bb[r]) = tl;
                    } else {
                        __nv_bfloat16 m0 = __float2bfloat16(r0);
                        __nv_bfloat16 m1 = __float2bfloat16(r1);
                        r0 -= __bfloat162float(m0);
                        r1 -= __bfloat162float(m1);
                        __nv_bfloat162 tm; tm.x = m0; tm.y = m1;
                        __nv_bfloat162 tl;
                        tl.x = __float2bfloat16(r0); tl.y = __float2bfloat16(r1);
                        *(__nv_bfloat162*)(c1 + bb[r]) = tm;
                        *(__nv_bfloat162*)(c2 + bb[r]) = tl;
                    }
                }
            }
        }
    }
}

// =====================================================================
// prep / elementwise kernels
// =====================================================================
__global__ void transpose_split3(const float* __restrict__ x,
                                 __nv_bfloat16* __restrict__ h,
                                 __nv_bfloat16* __restrict__ m,
                                 __nv_bfloat16* __restrict__ l)
{
    __shared__ float t[32][33];
    const int b = blockIdx.z;
    const int n0 = blockIdx.x * 32, c0 = blockIdx.y * 32;
    const float* xb = x + (size_t)b * CCH * NPIX;
    #pragma unroll
    for (int k = 0; k < 4; k++) {
        const int c = c0 + threadIdx.y + k * 8;
        t[threadIdx.y + k * 8][threadIdx.x] = xb[(size_t)c * NPIX + n0 + threadIdx.x];
    }
    __syncthreads();
    const size_t ob = (size_t)b * NPIX * CCH;
    #pragma unroll
    for (int k = 0; k < 4; k++) {
        const int n = n0 + threadIdx.y + k * 8;
        const float v = t[threadIdx.x][threadIdx.y + k * 8];
        const size_t idx = ob + (size_t)n * CCH + c0 + threadIdx.x;
        __nv_bfloat16 hh = __float2bfloat16(v);
        float r = v - __bfloat162float(hh);
        __nv_bfloat16 mm = __float2bfloat16(r);
        r -= __bfloat162float(mm);
        h[idx] = hh; m[idx] = mm; l[idx] = __float2bfloat16(r);
    }
}

__global__ void conv_split3(const float* __restrict__ s, __nv_bfloat16* __restrict__ h,
                            __nv_bfloat16* __restrict__ m, __nv_bfloat16* __restrict__ l, int n)
{
    const int i = blockIdx.x * 256 + threadIdx.x;
    if (i >= n) return;
    const float v = s[i];
    __nv_bfloat16 hh = __float2bfloat16(v);
    float r = v - __bfloat162float(hh);
    __nv_bfloat16 mm = __float2bfloat16(r);
    r -= __bfloat162float(mm);
    h[i] = hh; m[i] = mm; l[i] = __float2bfloat16(r);
}

__global__ void conv_split2(const float* __restrict__ s, __nv_bfloat16* __restrict__ h,
                            __nv_bfloat16* __restrict__ l, int n)
{
    const int i = blockIdx.x * 256 + threadIdx.x;
    if (i >= n) return;
    const float v = s[i];
    __nv_bfloat16 hh = __float2bfloat16(v);
    h[i] = hh; l[i] = __float2bfloat16(v - __bfloat162float(hh));
}

__global__ __launch_bounds__(256) void softmax_split(
    const float* __restrict__ fp, __nv_bfloat16* __restrict__ h, __nv_bfloat16* __restrict__ l)
{
    const int row = blockIdx.x;        // b*256 + c
    const int b = row >> 8, c = row & 255;
    const int d = threadIdx.x;
    float v = 0.f;
    #pragma unroll
    for (int s = 0; s < 4; s++)
        v += fp[((size_t)(b * 4 + s)) * (CI * CI) + c * CI + d];
    __shared__ float red[256];
    red[d] = v; __syncthreads();
    for (int o = 128; o > 0; o >>= 1) {
        if (d < o) red[d] = fmaxf(red[d], red[d + o]);
        __syncthreads();
    }
    const float mx = red[0];
    __syncthreads();
    const float e = __expf(v - mx);
    red[d] = e; __syncthreads();
    for (int o = 128; o > 0; o >>= 1) {
        if (d < o) red[d] += red[d + o];
        __syncthreads();
    }
    const float p = e / red[0];
    const size_t idx = (size_t)row * CI + d;
    __nv_bfloat16 hh = __float2bfloat16(p);
    h[idx] = hh; l[idx] = __float2bfloat16(p - __bfloat162float(hh));
}

__global__ __launch_bounds__(256) void bn_stats(const float* __restrict__ z, float* __restrict__ stats)
{
    const int c = blockIdx.x, t = threadIdx.x;
    float s = 0.f, sq = 0.f;
    for (int b = 0; b < BATCH; b++) {
        const float* p = z + ((size_t)b * CCH + c) * NPIX;
        for (int n = t; n < NPIX; n += 256) {
            const float v = p[n];
            s += v; sq += v * v;
        }
    }
    __shared__ float rs[256], rq[256];
    rs[t] = s; rq[t] = sq; __syncthreads();
    for (int o = 128; o > 0; o >>= 1) {
        if (t < o) { rs[t] += rs[t + o]; rq[t] += rq[t + o]; }
        __syncthreads();
    }
    if (t == 0) {
        const float cnt = (float)(BATCH * NPIX);
        const float m = rs[0] / cnt;
        const float var = rq[0] / cnt - m * m;
        stats[c] = m;
        stats[CCH + c] = rsqrtf(var + 1e-5f);
    }
}

__global__ __launch_bounds__(256) void bn_residual(
    const float* __restrict__ z, const float* __restrict__ x,
    const float* __restrict__ gamma, const float* __restrict__ beta,
    const float* __restrict__ stats, float* __restrict__ out)
{
    const size_t i = (size_t)blockIdx.x * blockDim.x + threadIdx.x;
    const int c = (int)((i >> 10) & (CCH - 1));
    const float m = stats[c], r = stats[CCH + c], g = gamma[c], bb = beta[c];
    const float4 zv = ((const float4*)z)[i];
    const float4 xv = ((const float4*)x)[i];
    float4 o;
    o.x = (zv.x - m) * r * g + bb + xv.x;
    o.y = (zv.y - m) * r * g + bb + xv.y;
    o.z = (zv.z - m) * r * g + bb + xv.z;
    o.w = (zv.w - m) * r * g + bb + xv.w;
    ((float4*)out)[i] = o;
}

// =====================================================================
// launch
// =====================================================================
extern "C" void kernel_launch(void* const* d_in, const int* in_sizes, int n_in,
                              void* d_out, int out_size)
{
    (void)in_sizes; (void)n_in; (void)out_size;
    const float* x     = (const float*)d_in[0];
    const float* g_w   = (const float*)d_in[1];
    const float* g_b   = (const float*)d_in[2];
    const float* th_w  = (const float*)d_in[3];
    const float* th_b  = (const float*)d_in[4];
    const float* ph_w  = (const float*)d_in[5];
    const float* ph_b  = (const float*)d_in[6];
    const float* W_w   = (const float*)d_in[7];
    const float* gamma = (const float*)d_in[9];
    const float* beta  = (const float*)d_in[10];
    float* out = (float*)d_out;

    __nv_bfloat16 *xt, *wtp, *gw, *ww, *tp, *gt, *fsm, *yt;
    float *fpart, *z, *stats, *tpb;
    cudaGetSymbolAddress((void**)&xt,    d_xt);
    cudaGetSymbolAddress((void**)&wtp,   d_wtp);
    cudaGetSymbolAddress((void**)&gw,    d_gw);
    cudaGetSymbolAddress((void**)&ww,    d_ww);
    cudaGetSymbolAddress((void**)&tp,    d_tp);
    cudaGetSymbolAddress((void**)&gt,    d_gt);
    cudaGetSymbolAddress((void**)&fpart, d_fpart);
    cudaGetSymbolAddress((void**)&fsm,   d_fsm);
    cudaGetSymbolAddress((void**)&yt,    d_yt);
    cudaGetSymbolAddress((void**)&z,     d_z);
    cudaGetSymbolAddress((void**)&stats, d_stats);
    cudaGetSymbolAddress((void**)&tpb,   d_tpb);

    __nv_bfloat16 *xt0 = xt, *xt1 = xt + XT_SZ, *xt2 = xt + 2 * XT_SZ;
    __nv_bfloat16 *wtp0 = wtp, *wtp1 = wtp + 512 * 512, *wtp2 = wtp + 2 * 512 * 512;
    __nv_bfloat16 *gw0 = gw, *gw1 = gw + CI * CCH;
    __nv_bfloat16 *ww0 = ww, *ww1 = ww + CCH * CI;
    __nv_bfloat16 *tp0 = tp, *tp1 = tp + TP_SZ, *tp2 = tp + 2 * TP_SZ;
    __nv_bfloat16 *gt0 = gt, *gt1 = gt + GT_SZ;
    __nv_bfloat16 *fs0 = fsm, *fs1 = fsm + F_SZ;
    __nv_bfloat16 *yt0 = yt, *yt1 = yt + YT_SZ;

    const int SM3 = 2 * 6 * 16384 + 1024;   // 197632
    const int SM2 = 2 * 4 * 16384 + 1024;   // 132096
    cudaFuncSetAttribute(mma_nt<3, 2>, cudaFuncAttributeMaxDynamicSharedMemorySize, SM3);
    cudaFuncSetAttribute(mma_nt<3, 0>, cudaFuncAttributeMaxDynamicSharedMemorySize, SM3);
    cudaFuncSetAttribute(mma_nt<2, 1>, cudaFuncAttributeMaxDynamicSharedMemorySize, SM2);
    cudaFuncSetAttribute(mma_nt<2, 0>, cudaFuncAttributeMaxDynamicSharedMemorySize, SM2);

    // bias stack [theta_b; phi_b]
    cudaMemcpyAsync(tpb,       th_b, CI * 4, cudaMemcpyDeviceToDevice);
    cudaMemcpyAsync(tpb + CI,  ph_b, CI * 4, cudaMemcpyDeviceToDevice);

    // weight splits
    conv_split3<<<(CI * CCH + 255) / 256, 256>>>(th_w, wtp0, wtp1, wtp2, CI * CCH);
    conv_split3<<<(CI * CCH + 255) / 256, 256>>>(ph_w, wtp0 + CI * CCH, wtp1 + CI * CCH,
                                                 wtp2 + CI * CCH, CI * CCH);
    conv_split2<<<(CI * CCH + 255) / 256, 256>>>(g_w, gw0, gw1, CI * CCH);
    conv_split2<<<(CCH * CI + 255) / 256, 256>>>(W_w, ww0, ww1, CCH * CI);

    // xT tri-split: (B, 4096, 512)
    transpose_split3<<<dim3(NPIX / 32, CCH / 32, BATCH), dim3(32, 8)>>>(x, xt0, xt1, xt2);

    // GEMM1a: tp[b](512,4096) = Wtp(512,512) @ xT[b]^T  (+ [th_b;ph_b] per row), tri out
    mma_nt<3, 2><<<dim3(NPIX / 128, 512 / 128, BATCH), 256, SM3>>>(
        wtp0, wtp1, wtp2, xt0, xt1, xt2,
        nullptr, tp0, tp1, tp2, tpb, nullptr,
        512, NPIX, CCH, 1, 0, (long long)NPIX * CCH, 512LL * NPIX);

    // GEMM1b: gT[b](4096,256) = xT[b] @ g_w^T (+ g_b per col), 2-level out
    mma_nt<2, 1><<<dim3(CI / 128, NPIX / 128, BATCH), 256, SM2>>>(
        xt0, xt1, nullptr, gw0, gw1, nullptr,
        nullptr, gt0, gt1, nullptr, nullptr, g_b,
        NPIX, CI, CCH, 1, (long long)NPIX * CCH, 0, (long long)NPIX * CI);

    // GEMM2: f partials = theta @ phi^T, split-K 4, fp32 out
    mma_nt<3, 0><<<dim3(CI / 128, CI / 128, BATCH * 4), 256, SM3>>>(
        tp0, tp1, tp2,
        tp0 + (size_t)CI * NPIX, tp1 + (size_t)CI * NPIX, tp2 + (size_t)CI * NPIX,
        fpart, nullptr, nullptr, nullptr, nullptr, nullptr,
        CI, CI, NPIX, 4, 512LL * NPIX, 512LL * NPIX, (long long)CI * CI);

    // softmax (sums 4 partials) -> 2-level bf16
    softmax_split<<<BATCH * CI, 256>>>(fpart, fs0, fs1);

    // GEMM3: yT[b](4096,256) = gT[b] @ fsm[b]^T, 2-level out
    mma_nt<2, 1><<<dim3(CI / 128, NPIX / 128, BATCH), 256, SM2>>>(
        gt0, gt1, nullptr, fs0, fs1, nullptr,
        nullptr, yt0, yt1, nullptr, nullptr, nullptr,
        NPIX, CI, CI, 1, (long long)NPIX * CI, (long long)CI * CI, (long long)NPIX * CI);

    // GEMM4: z[b](512,4096) = W_w @ yT[b]^T  (W_b dropped: cancels in BN), fp32 out
    mma_nt<2, 0><<<dim3(NPIX / 128, CCH / 128, BATCH), 256, SM2>>>(
        ww0, ww1, nullptr, yt0, yt1, nullptr,
        z, nullptr, nullptr, nullptr, nullptr, nullptr,
        CCH, NPIX, CI, 1, 0, (long long)NPIX * CI, (long long)CCH * NPIX);

    // BN + residual
    bn_stats<<<CCH, 256>>>(z, stats);
    const size_t total4 = (size_t)BATCH * CCH * NPIX / 4;
    bn_residual<<<(unsigned)(total4 / 256), 256>>>(z, x, gamma, beta, stats, out);
}

// round 6
// speedup vs baseline: 3.6598x; 1.3781x over previous
#include <cuda_runtime.h>
#include <cuda_bf16.h>
#include <cstdint>

#define BATCH 16
#define CCH   512
#define CI    256
#define NPIX  4096

// ---------------- scratch (device globals; no allocation allowed) ----------------
static const size_t XT_SZ  = (size_t)BATCH * NPIX * CCH;   // per level
static const size_t TP_SZ  = (size_t)BATCH * 512 * NPIX;
static const size_t GT_SZ  = (size_t)BATCH * NPIX * CI;
static const size_t F_SZ   = (size_t)BATCH * CI * CI;
static const size_t YT_SZ  = (size_t)BATCH * NPIX * CI;

__device__ __nv_bfloat16 d_xt [2][(size_t)BATCH * NPIX * CCH];   // 134 MB
__device__ __nv_bfloat16 d_wtp[2][512 * 512];
__device__ __nv_bfloat16 d_gw [2][CI * CCH];
__device__ __nv_bfloat16 d_ww [2][CCH * CI];
__device__ __nv_bfloat16 d_tp [2][(size_t)BATCH * 512 * NPIX];   // 134 MB
__device__ __nv_bfloat16 d_gt [2][(size_t)BATCH * NPIX * CI];    // 67 MB
__device__ float         d_fpart[(size_t)4 * BATCH * CI * CI];   // 16.8 MB
__device__ __nv_bfloat16 d_fsm[2][(size_t)BATCH * CI * CI];
__device__ __nv_bfloat16 d_yt [2][(size_t)BATCH * NPIX * CI];    // 67 MB
__device__ float         d_z[(size_t)BATCH * CCH * NPIX];        // 134 MB
__device__ float         d_stats[2 * CCH];
__device__ float         d_tpb[512];

// ---------------- helpers (arch-portable PTX only: sm_80+) ----------------
__device__ __forceinline__ uint32_t smem_u32(const void* p) {
    uint32_t a;
    asm("{ .reg .u64 t; cvta.to.shared.u64 t, %1; cvt.u32.u64 %0, t; }" : "=r"(a) : "l"(p));
    return a;
}
#define SMEM_SWIZZLE_128B(o) ((o) ^ (((o) >> 3) & 0x70))

__device__ __forceinline__ void cpasync16(uint32_t dst, const void* src) {
    asm volatile("cp.async.cg.shared.global [%0], [%1], 16;" :: "r"(dst), "l"(src));
}
#define CP_COMMIT() asm volatile("cp.async.commit_group;" ::: "memory")

__device__ __forceinline__ void ldsm4(uint32_t addr, uint32_t& r0, uint32_t& r1,
                                      uint32_t& r2, uint32_t& r3) {
    asm volatile("ldmatrix.sync.aligned.m8n8.x4.shared.b16 {%0,%1,%2,%3}, [%4];"
                 : "=r"(r0), "=r"(r1), "=r"(r2), "=r"(r3) : "r"(addr));
}
__device__ __forceinline__ void mma16816(float* c, const uint32_t* a, uint32_t b0, uint32_t b1) {
    asm volatile(
        "mma.sync.aligned.m16n8k16.row.col.f32.bf16.bf16.f32 "
        "{%0,%1,%2,%3}, {%4,%5,%6,%7}, {%8,%9}, {%0,%1,%2,%3};"
        : "+f"(c[0]), "+f"(c[1]), "+f"(c[2]), "+f"(c[3])
        : "r"(a[0]), "r"(a[1]), "r"(a[2]), "r"(a[3]), "r"(b0), "r"(b1));
}

// =====================================================================
// NT GEMM on tensor cores (mma.sync bf16, fp32 acc), 2-level split inputs:
//   D[M,N] = A0*B0^T + A0*B1^T + A1*B0^T    (ll term dropped, ~2^-18)
// A,B: K-major (ld = K). CTA tile 128x128, 8 warps (warp tile 64x32),
// K-chunk 64, SW128-swizzled smem, 3-stage cp.async pipeline.
// MODE: 0 = fp32 out, 1 = hi/lo bf16 out.
// grid = (N/128, M/128, batch*nsplit)
// =====================================================================
template <int MODE>
__global__ __launch_bounds__(256) void mma_nt(
    const __nv_bfloat16* __restrict__ a0, const __nv_bfloat16* __restrict__ a1,
    const __nv_bfloat16* __restrict__ b0, const __nv_bfloat16* __restrict__ b1,
    float* __restrict__ cf,
    __nv_bfloat16* __restrict__ c0, __nv_bfloat16* __restrict__ c1,
    const float* __restrict__ biasRow, const float* __restrict__ biasCol,
    int M, int N, int K, int nsplit,
    long long sA, long long sB, long long sC)
{
    constexpr int TILE = 16384;             // 128 rows x 128 bytes (64 bf16)
    constexpr int NT = 4;                   // A0,A1,B0,B1 tiles per chunk
    constexpr int PRN = 3;
    constexpr int PA[3] = {0, 0, 1};
    constexpr int PB[3] = {0, 1, 0};
    constexpr int stageBytes = NT * TILE;   // 64 KB; 3 stages = 192 KB

    extern __shared__ char smraw[];
    const uint32_t smem_base = (smem_u32(smraw) + 1023u) & ~1023u;

    const int tid = threadIdx.x;
    const int wid = tid >> 5, lid = tid & 31;
    const int warpM = (wid & 1) * 64;       // 2 warps over M
    const int warpN = (wid >> 1) * 32;      // 4 warps over N

    const int bz = blockIdx.z;
    const int b  = bz / nsplit, sp = bz % nsplit;
    const int Ksub = K / nsplit;
    const int nk = Ksub / 64;
    const int k0base = sp * Ksub;
    const int mBase = blockIdx.y * 128;
    const int nBase = blockIdx.x * 128;

    const __nv_bfloat16* ta[NT];
    ta[0] = a0 + (size_t)b * sA;
    ta[1] = a1 + (size_t)b * sA;
    ta[2] = b0 + (size_t)b * sB;
    ta[3] = b1 + (size_t)b * sB;

    auto loadChunk = [&](int ci, int st) {
        const int k0 = k0base + ci * 64;
        const uint32_t sb = smem_base + st * stageBytes;
        #pragma unroll
        for (int t = 0; t < NT; t++) {
            const int rb = (t < 2) ? mBase : nBase;
            const __nv_bfloat16* src = ta[t] + (size_t)rb * K + k0;
            const uint32_t tb = sb + t * TILE;
            #pragma unroll
            for (int i = tid; i < 1024; i += 256) {
                const int row = i >> 3, seg = i & 7;
                cpasync16(tb + SMEM_SWIZZLE_128B(row * 128 + seg * 16),
                          src + (size_t)row * K + seg * 8);
            }
        }
    };

    float acc[4][4][4];
    #pragma unroll
    for (int i = 0; i < 4; i++)
        #pragma unroll
        for (int j = 0; j < 4; j++)
            #pragma unroll
            for (int k = 0; k < 4; k++) acc[i][j][k] = 0.f;

    loadChunk(0, 0); CP_COMMIT();
    loadChunk(1, 1); CP_COMMIT();

    const int lRow = lid & 15;              // ldmatrix row within 16
    const int lHi  = (lid >> 4) & 1;        // ldmatrix 16B half select

    int nxt = 2;                            // next chunk to load; buffer nxt%3
    for (int i = 0; i < nk; i++) {
        const int cur = i % 3;
        asm volatile("cp.async.wait_group 1;" ::: "memory");
        __syncthreads();                    // chunk i visible; all done with chunk i-1

        if (nxt < nk) {                     // buffer nxt%3 == (i-1)%3, now free
            loadChunk(nxt, nxt % 3); CP_COMMIT();
            nxt++;
        }

        const uint32_t sb = smem_base + cur * stageBytes;
        #pragma unroll
        for (int p = 0; p < PRN; p++) {
            const uint32_t Ab = sb + PA[p] * TILE;
            const uint32_t Bb = sb + (2 + PB[p]) * TILE;
            #pragma unroll
            for (int ks = 0; ks < 4; ks++) {
                const int colB = ks * 32 + lHi * 16;
                uint32_t a[4][4];
                #pragma unroll
                for (int mi = 0; mi < 4; mi++) {
                    const int row = warpM + 16 * mi + lRow;
                    ldsm4(Ab + SMEM_SWIZZLE_128B(row * 128 + colB),
                          a[mi][0], a[mi][1], a[mi][2], a[mi][3]);
                }
                uint32_t bt[2][4];
                #pragma unroll
                for (int nj = 0; nj < 2; nj++) {
                    const int row = warpN + 16 * nj + lRow;
                    ldsm4(Bb + SMEM_SWIZZLE_128B(row * 128 + colB),
                          bt[nj][0], bt[nj][1], bt[nj][2], bt[nj][3]);
                }
                #pragma unroll
                for (int mi = 0; mi < 4; mi++)
                    #pragma unroll
                    for (int jn = 0; jn < 4; jn++)
                        mma16816(acc[mi][jn], a[mi],
                                 bt[jn >> 1][jn & 1], bt[jn >> 1][2 + (jn & 1)]);
            }
        }
    }

    // ---- epilogue ----
    const int gr = lid >> 2;            // 0..7
    const int gc = (lid & 3) * 2;       // 0,2,4,6
    const size_t cOff = (size_t)bz * sC;

    #pragma unroll
    for (int mi = 0; mi < 4; mi++) {
        const int row0 = mBase + warpM + 16 * mi + gr;
        const int row1 = row0 + 8;
        const float br0 = biasRow ? biasRow[row0] : 0.f;
        const float br1 = biasRow ? biasRow[row1] : 0.f;
        #pragma unroll
        for (int jn = 0; jn < 4; jn++) {
            const int col = nBase + warpN + 8 * jn + gc;
            float v00 = acc[mi][jn][0] + br0;
            float v01 = acc[mi][jn][1] + br0;
            float v10 = acc[mi][jn][2] + br1;
            float v11 = acc[mi][jn][3] + br1;
            if (biasCol) {
                const float bc0 = biasCol[col], bc1 = biasCol[col + 1];
                v00 += bc0; v01 += bc1; v10 += bc0; v11 += bc1;
            }
            const size_t base0 = cOff + (size_t)row0 * N + col;
            const size_t base1 = cOff + (size_t)row1 * N + col;
            if (MODE == 0) {
                *(float2*)(cf + base0) = make_float2(v00, v01);
                *(float2*)(cf + base1) = make_float2(v10, v11);
            } else {
                float vv[2][2] = {{v00, v01}, {v10, v11}};
                const size_t bb[2] = {base0, base1};
                #pragma unroll
                for (int r = 0; r < 2; r++) {
                    __nv_bfloat16 h0 = __float2bfloat16(vv[r][0]);
                    __nv_bfloat16 h1 = __float2bfloat16(vv[r][1]);
                    float r0 = vv[r][0] - __bfloat162float(h0);
                    float r1 = vv[r][1] - __bfloat162float(h1);
                    __nv_bfloat162 th; th.x = h0; th.y = h1;
                    __nv_bfloat162 tl;
                    tl.x = __float2bfloat16(r0); tl.y = __float2bfloat16(r1);
                    *(__nv_bfloat162*)(c0 + bb[r]) = th;
                    *(__nv_bfloat162*)(c1 + bb[r]) = tl;
                }
            }
        }
    }
}

// =====================================================================
// prep / elementwise kernels
// =====================================================================
__global__ void transpose_split2(const float* __restrict__ x,
                                 __nv_bfloat16* __restrict__ h,
                                 __nv_bfloat16* __restrict__ l)
{
    __shared__ float t[32][33];
    const int b = blockIdx.z;
    const int n0 = blockIdx.x * 32, c0 = blockIdx.y * 32;
    const float* xb = x + (size_t)b * CCH * NPIX;
    #pragma unroll
    for (int k = 0; k < 4; k++) {
        const int c = c0 + threadIdx.y + k * 8;
        t[threadIdx.y + k * 8][threadIdx.x] = xb[(size_t)c * NPIX + n0 + threadIdx.x];
    }
    __syncthreads();
    const size_t ob = (size_t)b * NPIX * CCH;
    #pragma unroll
    for (int k = 0; k < 4; k++) {
        const int n = n0 + threadIdx.y + k * 8;
        const float v = t[threadIdx.x][threadIdx.y + k * 8];
        const size_t idx = ob + (size_t)n * CCH + c0 + threadIdx.x;
        __nv_bfloat16 hh = __float2bfloat16(v);
        h[idx] = hh;
        l[idx] = __float2bfloat16(v - __bfloat162float(hh));
    }
}

__global__ void conv_split2(const float* __restrict__ s, __nv_bfloat16* __restrict__ h,
                            __nv_bfloat16* __restrict__ l, int n)
{
    const int i = blockIdx.x * 256 + threadIdx.x;
    if (i >= n) return;
    const float v = s[i];
    __nv_bfloat16 hh = __float2bfloat16(v);
    h[i] = hh; l[i] = __float2bfloat16(v - __bfloat162float(hh));
}

__global__ __launch_bounds__(256) void softmax_split(
    const float* __restrict__ fp, __nv_bfloat16* __restrict__ h, __nv_bfloat16* __restrict__ l)
{
    const int row = blockIdx.x;        // b*256 + c
    const int b = row >> 8, c = row & 255;
    const int d = threadIdx.x;
    float v = 0.f;
    #pragma unroll
    for (int s = 0; s < 4; s++)
        v += fp[((size_t)(b * 4 + s)) * (CI * CI) + c * CI + d];
    __shared__ float red[256];
    red[d] = v; __syncthreads();
    for (int o = 128; o > 0; o >>= 1) {
        if (d < o) red[d] = fmaxf(red[d], red[d + o]);
        __syncthreads();
    }
    const float mx = red[0];
    __syncthreads();
    const float e = __expf(v - mx);
    red[d] = e; __syncthreads();
    for (int o = 128; o > 0; o >>= 1) {
        if (d < o) red[d] += red[d + o];
        __syncthreads();
    }
    const float p = e / red[0];
    const size_t idx = (size_t)row * CI + d;
    __nv_bfloat16 hh = __float2bfloat16(p);
    h[idx] = hh; l[idx] = __float2bfloat16(p - __bfloat162float(hh));
}

__global__ __launch_bounds__(256) void bn_stats(const float* __restrict__ z, float* __restrict__ stats)
{
    const int c = blockIdx.x, t = threadIdx.x;
    float s = 0.f, sq = 0.f;
    for (int b = 0; b < BATCH; b++) {
        const float* p = z + ((size_t)b * CCH + c) * NPIX;
        for (int n = t; n < NPIX; n += 256) {
            const float v = p[n];
            s += v; sq += v * v;
        }
    }
    __shared__ float rs[256], rq[256];
    rs[t] = s; rq[t] = sq; __syncthreads();
    for (int o = 128; o > 0; o >>= 1) {
        if (t < o) { rs[t] += rs[t + o]; rq[t] += rq[t + o]; }
        __syncthreads();
    }
    if (t == 0) {
        const float cnt = (float)(BATCH * NPIX);
        const float m = rs[0] / cnt;
        const float var = rq[0] / cnt - m * m;
        stats[c] = m;
        stats[CCH + c] = rsqrtf(var + 1e-5f);
    }
}

__global__ __launch_bounds__(256) void bn_residual(
    const float* __restrict__ z, const float* __restrict__ x,
    const float* __restrict__ gamma, const float* __restrict__ beta,
    const float* __restrict__ stats, float* __restrict__ out)
{
    const size_t i = (size_t)blockIdx.x * blockDim.x + threadIdx.x;
    const int c = (int)((i >> 10) & (CCH - 1));
    const float m = stats[c], r = stats[CCH + c], g = gamma[c], bb = beta[c];
    const float4 zv = ((const float4*)z)[i];
    const float4 xv = ((const float4*)x)[i];
    float4 o;
    o.x = (zv.x - m) * r * g + bb + xv.x;
    o.y = (zv.y - m) * r * g + bb + xv.y;
    o.z = (zv.z - m) * r * g + bb + xv.z;
    o.w = (zv.w - m) * r * g + bb + xv.w;
    ((float4*)out)[i] = o;
}

// =====================================================================
// launch
// =====================================================================
extern "C" void kernel_launch(void* const* d_in, const int* in_sizes, int n_in,
                              void* d_out, int out_size)
{
    (void)in_sizes; (void)n_in; (void)out_size;
    const float* x     = (const float*)d_in[0];
    const float* g_w   = (const float*)d_in[1];
    const float* g_b   = (const float*)d_in[2];
    const float* th_w  = (const float*)d_in[3];
    const float* th_b  = (const float*)d_in[4];
    const float* ph_w  = (const float*)d_in[5];
    const float* ph_b  = (const float*)d_in[6];
    const float* W_w   = (const float*)d_in[7];
    const float* gamma = (const float*)d_in[9];
    const float* beta  = (const float*)d_in[10];
    float* out = (float*)d_out;

    __nv_bfloat16 *xt, *wtp, *gw, *ww, *tp, *gt, *fsm, *yt;
    float *fpart, *z, *stats, *tpb;
    cudaGetSymbolAddress((void**)&xt,    d_xt);
    cudaGetSymbolAddress((void**)&wtp,   d_wtp);
    cudaGetSymbolAddress((void**)&gw,    d_gw);
    cudaGetSymbolAddress((void**)&ww,    d_ww);
    cudaGetSymbolAddress((void**)&tp,    d_tp);
    cudaGetSymbolAddress((void**)&gt,    d_gt);
    cudaGetSymbolAddress((void**)&fpart, d_fpart);
    cudaGetSymbolAddress((void**)&fsm,   d_fsm);
    cudaGetSymbolAddress((void**)&yt,    d_yt);
    cudaGetSymbolAddress((void**)&z,     d_z);
    cudaGetSymbolAddress((void**)&stats, d_stats);
    cudaGetSymbolAddress((void**)&tpb,   d_tpb);

    __nv_bfloat16 *xt0 = xt, *xt1 = xt + XT_SZ;
    __nv_bfloat16 *wtp0 = wtp, *wtp1 = wtp + 512 * 512;
    __nv_bfloat16 *gw0 = gw, *gw1 = gw + CI * CCH;
    __nv_bfloat16 *ww0 = ww, *ww1 = ww + CCH * CI;
    __nv_bfloat16 *tp0 = tp, *tp1 = tp + TP_SZ;
    __nv_bfloat16 *gt0 = gt, *gt1 = gt + GT_SZ;
    __nv_bfloat16 *fs0 = fsm, *fs1 = fsm + F_SZ;
    __nv_bfloat16 *yt0 = yt, *yt1 = yt + YT_SZ;

    const int SMEM = 3 * 4 * 16384 + 1024;   // 3-stage pipeline: 197632 B
    cudaFuncSetAttribute(mma_nt<0>, cudaFuncAttributeMaxDynamicSharedMemorySize, SMEM);
    cudaFuncSetAttribute(mma_nt<1>, cudaFuncAttributeMaxDynamicSharedMemorySize, SMEM);

    // bias stack [theta_b; phi_b]
    cudaMemcpyAsync(tpb,      th_b, CI * 4, cudaMemcpyDeviceToDevice);
    cudaMemcpyAsync(tpb + CI, ph_b, CI * 4, cudaMemcpyDeviceToDevice);

    // weight splits (2-level everywhere)
    conv_split2<<<(CI * CCH + 255) / 256, 256>>>(th_w, wtp0, wtp1, CI * CCH);
    conv_split2<<<(CI * CCH + 255) / 256, 256>>>(ph_w, wtp0 + CI * CCH, wtp1 + CI * CCH, CI * CCH);
    conv_split2<<<(CI * CCH + 255) / 256, 256>>>(g_w, gw0, gw1, CI * CCH);
    conv_split2<<<(CCH * CI + 255) / 256, 256>>>(W_w, ww0, ww1, CCH * CI);

    // xT 2-level split: (B, 4096, 512)
    transpose_split2<<<dim3(NPIX / 32, CCH / 32, BATCH), dim3(32, 8)>>>(x, xt0, xt1);

    // GEMM1a: tp[b](512,4096) = Wtp(512,512) @ xT[b]^T (+ [th_b;ph_b] per row), hi/lo out
    mma_nt<1><<<dim3(NPIX / 128, 512 / 128, BATCH), 256, SMEM>>>(
        wtp0, wtp1, xt0, xt1,
        nullptr, tp0, tp1, tpb, nullptr,
        512, NPIX, CCH, 1, 0, (long long)NPIX * CCH, 512LL * NPIX);

    // GEMM1b: gT[b](4096,256) = xT[b] @ g_w^T (+ g_b per col), hi/lo out
    mma_nt<1><<<dim3(CI / 128, NPIX / 128, BATCH), 256, SMEM>>>(
        xt0, xt1, gw0, gw1,
        nullptr, gt0, gt1, nullptr, g_b,
        NPIX, CI, CCH, 1, (long long)NPIX * CCH, 0, (long long)NPIX * CI);

    // GEMM2: f partials = theta @ phi^T, split-K 4, fp32 out
    mma_nt<0><<<dim3(CI / 128, CI / 128, BATCH * 4), 256, SMEM>>>(
        tp0, tp1,
        tp0 + (size_t)CI * NPIX, tp1 + (size_t)CI * NPIX,
        fpart, nullptr, nullptr, nullptr, nullptr,
        CI, CI, NPIX, 4, 512LL * NPIX, 512LL * NPIX, (long long)CI * CI);

    // softmax (sums 4 partials) -> hi/lo bf16
    softmax_split<<<BATCH * CI, 256>>>(fpart, fs0, fs1);

    // GEMM3: yT[b](4096,256) = gT[b] @ fsm[b]^T, hi/lo out
    mma_nt<1><<<dim3(CI / 128, NPIX / 128, BATCH), 256, SMEM>>>(
        gt0, gt1, fs0, fs1,
        nullptr, yt0, yt1, nullptr, nullptr,
        NPIX, CI, CI, 1, (long long)NPIX * CI, (long long)CI * CI, (long long)NPIX * CI);

    // GEMM4: z[b](512,4096) = W_w @ yT[b]^T  (W_b dropped: cancels in BN), fp32 out
    mma_nt<0><<<dim3(NPIX / 128, CCH / 128, BATCH), 256, SMEM>>>(
        ww0, ww1, yt0, yt1,
        z, nullptr, nullptr, nullptr, nullptr,
        CCH, NPIX, CI, 1, 0, (long long)NPIX * CI, (long long)CCH * NPIX);

    // BN + residual
    bn_stats<<<CCH, 256>>>(z, stats);
    const size_t total4 = (size_t)BATCH * CCH * NPIX / 4;
    bn_residual<<<(unsigned)(total4 / 256), 256>>>(z, x, gamma, beta, stats, out);
}

// round 7
// speedup vs baseline: 3.8773x; 1.0594x over previous
#include <cuda_runtime.h>
#include <cuda_bf16.h>
#include <cstdint>

#define BATCH 16
#define CCH   512
#define CI    256
#define NPIX  4096

// ---------------- scratch (device globals; no allocation allowed) ----------------
static const size_t XT_SZ  = (size_t)BATCH * NPIX * CCH;   // per level
static const size_t TP_SZ  = (size_t)BATCH * 512 * NPIX;
static const size_t GT_SZ  = (size_t)BATCH * NPIX * CI;
static const size_t F_SZ   = (size_t)BATCH * CI * CI;
static const size_t YT_SZ  = (size_t)BATCH * NPIX * CI;

__device__ __nv_bfloat16 d_xt [2][(size_t)BATCH * NPIX * CCH];   // 134 MB
__device__ __nv_bfloat16 d_wtp[2][512 * 512];
__device__ __nv_bfloat16 d_gw [2][CI * CCH];
__device__ __nv_bfloat16 d_ww [2][CCH * CI];
__device__ __nv_bfloat16 d_tp [2][(size_t)BATCH * 512 * NPIX];   // 134 MB
__device__ __nv_bfloat16 d_gt [2][(size_t)BATCH * NPIX * CI];    // 67 MB
__device__ float         d_fpart[(size_t)4 * BATCH * CI * CI];   // 16.8 MB
__device__ __nv_bfloat16 d_fsm[2][(size_t)BATCH * CI * CI];
__device__ __nv_bfloat16 d_yt [2][(size_t)BATCH * NPIX * CI];    // 67 MB
__device__ float         d_z[(size_t)BATCH * CCH * NPIX];        // 134 MB
__device__ float         d_stats[2 * CCH];                       // partials -> mean|rstd
__device__ float         d_tpb[512];

// ---------------- helpers (arch-portable PTX only: sm_80+) ----------------
__device__ __forceinline__ uint32_t smem_u32(const void* p) {
    uint32_t a;
    asm("{ .reg .u64 t; cvta.to.shared.u64 t, %1; cvt.u32.u64 %0, t; }" : "=r"(a) : "l"(p));
    return a;
}
#define SMEM_SWIZZLE_128B(o) ((o) ^ (((o) >> 3) & 0x70))

__device__ __forceinline__ void cpasync16(uint32_t dst, const void* src) {
    asm volatile("cp.async.cg.shared.global [%0], [%1], 16;" :: "r"(dst), "l"(src));
}
#define CP_COMMIT() asm volatile("cp.async.commit_group;" ::: "memory")

__device__ __forceinline__ void ldsm4(uint32_t addr, uint32_t& r0, uint32_t& r1,
                                      uint32_t& r2, uint32_t& r3) {
    asm volatile("ldmatrix.sync.aligned.m8n8.x4.shared.b16 {%0,%1,%2,%3}, [%4];"
                 : "=r"(r0), "=r"(r1), "=r"(r2), "=r"(r3) : "r"(addr));
}
__device__ __forceinline__ void mma16816(float* c, const uint32_t* a, uint32_t b0, uint32_t b1) {
    asm volatile(
        "mma.sync.aligned.m16n8k16.row.col.f32.bf16.bf16.f32 "
        "{%0,%1,%2,%3}, {%4,%5,%6,%7}, {%8,%9}, {%0,%1,%2,%3};"
        : "+f"(c[0]), "+f"(c[1]), "+f"(c[2]), "+f"(c[3])
        : "r"(a[0]), "r"(a[1]), "r"(a[2]), "r"(a[3]), "r"(b0), "r"(b1));
}

// =====================================================================
// NT GEMM on tensor cores (mma.sync bf16, fp32 acc), 2-level split inputs:
//   D[M,N] = A0*B0^T + A0*B1^T + A1*B0^T    (ll term dropped, ~2^-18)
// A,B: K-major (ld = K). CTA tile 128x128, 8 warps (warp tile 64x32),
// K-chunk 64, SW128-swizzled smem, 3-stage cp.async pipeline.
// Fragments for all 4 tiles hoisted once per k-step; 3 product batches reuse.
// MODE: 0 = fp32 out (optional fused per-row stats atomics), 1 = hi/lo bf16 out.
// grid = (N/128, M/128, batch*nsplit)
// =====================================================================
template <int MODE>
__global__ __launch_bounds__(256) void mma_nt(
    const __nv_bfloat16* __restrict__ a0, const __nv_bfloat16* __restrict__ a1,
    const __nv_bfloat16* __restrict__ b0, const __nv_bfloat16* __restrict__ b1,
    float* __restrict__ cf,
    __nv_bfloat16* __restrict__ c0, __nv_bfloat16* __restrict__ c1,
    const float* __restrict__ biasRow, const float* __restrict__ biasCol,
    float* __restrict__ statsPart,
    int M, int N, int K, int nsplit,
    long long sA, long long sB, long long sC)
{
    constexpr int TILE = 16384;             // 128 rows x 128 bytes (64 bf16)
    constexpr int NT = 4;                   // A0,A1,B0,B1 tiles per chunk
    constexpr int stageBytes = NT * TILE;   // 64 KB; 3 stages = 192 KB

    extern __shared__ char smraw[];
    const uint32_t smem_base = (smem_u32(smraw) + 1023u) & ~1023u;

    const int tid = threadIdx.x;
    const int wid = tid >> 5, lid = tid & 31;
    const int warpM = (wid & 1) * 64;       // 2 warps over M
    const int warpN = (wid >> 1) * 32;      // 4 warps over N

    const int bz = blockIdx.z;
    const int b  = bz / nsplit, sp = bz % nsplit;
    const int Ksub = K / nsplit;
    const int nk = Ksub / 64;
    const int k0base = sp * Ksub;
    const int mBase = blockIdx.y * 128;
    const int nBase = blockIdx.x * 128;

    const __nv_bfloat16* ta[NT];
    ta[0] = a0 + (size_t)b * sA;
    ta[1] = a1 + (size_t)b * sA;
    ta[2] = b0 + (size_t)b * sB;
    ta[3] = b1 + (size_t)b * sB;

    auto loadChunk = [&](int ci, int st) {
        const int k0 = k0base + ci * 64;
        const uint32_t sb = smem_base + st * stageBytes;
        #pragma unroll
        for (int t = 0; t < NT; t++) {
            const int rb = (t < 2) ? mBase : nBase;
            const __nv_bfloat16* src = ta[t] + (size_t)rb * K + k0;
            const uint32_t tb = sb + t * TILE;
            #pragma unroll
            for (int i = tid; i < 1024; i += 256) {
                const int row = i >> 3, seg = i & 7;
                cpasync16(tb + SMEM_SWIZZLE_128B(row * 128 + seg * 16),
                          src + (size_t)row * K + seg * 8);
            }
        }
    };

    float acc[4][4][4];
    #pragma unroll
    for (int i = 0; i < 4; i++)
        #pragma unroll
        for (int j = 0; j < 4; j++)
            #pragma unroll
            for (int k = 0; k < 4; k++) acc[i][j][k] = 0.f;

    loadChunk(0, 0); CP_COMMIT();
    loadChunk(1, 1); CP_COMMIT();

    const int lRow = lid & 15;              // ldmatrix row within 16
    const int lHi  = (lid >> 4) & 1;        // ldmatrix 16B half select

    int nxt = 2;                            // next chunk to load; buffer nxt%3
    for (int i = 0; i < nk; i++) {
        const int cur = i % 3;
        asm volatile("cp.async.wait_group 1;" ::: "memory");
        __syncthreads();                    // chunk i visible; all done with chunk i-1

        if (nxt < nk) {                     // buffer nxt%3 == (i-1)%3, now free
            loadChunk(nxt, nxt % 3); CP_COMMIT();
            nxt++;
        }

        const uint32_t sb = smem_base + cur * stageBytes;
        const uint32_t A0b = sb, A1b = sb + TILE;
        const uint32_t B0b = sb + 2 * TILE, B1b = sb + 3 * TILE;
        #pragma unroll
        for (int ks = 0; ks < 4; ks++) {
            const int colB = ks * 32 + lHi * 16;
            // hoist all fragments once; reuse across the 3 products
            uint32_t fa0[4][4], fa1[4][4], fb0[2][4], fb1[2][4];
            #pragma unroll
            for (int mi = 0; mi < 4; mi++) {
                const int row = warpM + 16 * mi + lRow;
                const uint32_t off = SMEM_SWIZZLE_128B(row * 128 + colB);
                ldsm4(A0b + off, fa0[mi][0], fa0[mi][1], fa0[mi][2], fa0[mi][3]);
                ldsm4(A1b + off, fa1[mi][0], fa1[mi][1], fa1[mi][2], fa1[mi][3]);
            }
            #pragma unroll
            for (int nj = 0; nj < 2; nj++) {
                const int row = warpN + 16 * nj + lRow;
                const uint32_t off = SMEM_SWIZZLE_128B(row * 128 + colB);
                ldsm4(B0b + off, fb0[nj][0], fb0[nj][1], fb0[nj][2], fb0[nj][3]);
                ldsm4(B1b + off, fb1[nj][0], fb1[nj][1], fb1[nj][2], fb1[nj][3]);
            }
            #pragma unroll
            for (int mi = 0; mi < 4; mi++)
                #pragma unroll
                for (int jn = 0; jn < 4; jn++)
                    mma16816(acc[mi][jn], fa0[mi],
                             fb0[jn >> 1][jn & 1], fb0[jn >> 1][2 + (jn & 1)]);
            #pragma unroll
            for (int mi = 0; mi < 4; mi++)
                #pragma unroll
                for (int jn = 0; jn < 4; jn++)
                    mma16816(acc[mi][jn], fa0[mi],
                             fb1[jn >> 1][jn & 1], fb1[jn >> 1][2 + (jn & 1)]);
            #pragma unroll
            for (int mi = 0; mi < 4; mi++)
                #pragma unroll
                for (int jn = 0; jn < 4; jn++)
                    mma16816(acc[mi][jn], fa1[mi],
                             fb0[jn >> 1][jn & 1], fb0[jn >> 1][2 + (jn & 1)]);
        }
    }

    // ---- epilogue ----
    const int gr = lid >> 2;            // 0..7
    const int gc = (lid & 3) * 2;       // 0,2,4,6
    const size_t cOff = (size_t)bz * sC;

    #pragma unroll
    for (int mi = 0; mi < 4; mi++) {
        const int row0 = mBase + warpM + 16 * mi + gr;
        const int row1 = row0 + 8;
        const float br0 = biasRow ? biasRow[row0] : 0.f;
        const float br1 = biasRow ? biasRow[row1] : 0.f;
        float s0 = 0.f, q0 = 0.f, s1 = 0.f, q1 = 0.f;
        #pragma unroll
        for (int jn = 0; jn < 4; jn++) {
            const int col = nBase + warpN + 8 * jn + gc;
            float v00 = acc[mi][jn][0] + br0;
            float v01 = acc[mi][jn][1] + br0;
            float v10 = acc[mi][jn][2] + br1;
            float v11 = acc[mi][jn][3] + br1;
            if (biasCol) {
                const float bc0 = biasCol[col], bc1 = biasCol[col + 1];
                v00 += bc0; v01 += bc1; v10 += bc0; v11 += bc1;
            }
            const size_t base0 = cOff + (size_t)row0 * N + col;
            const size_t base1 = cOff + (size_t)row1 * N + col;
            if (MODE == 0) {
                *(float2*)(cf + base0) = make_float2(v00, v01);
                *(float2*)(cf + base1) = make_float2(v10, v11);
                if (statsPart) {
                    s0 += v00 + v01; q0 += v00 * v00 + v01 * v01;
                    s1 += v10 + v11; q1 += v10 * v10 + v11 * v11;
                }
            } else {
                float vv[2][2] = {{v00, v01}, {v10, v11}};
                const size_t bb[2] = {base0, base1};
                #pragma unroll
                for (int r = 0; r < 2; r++) {
                    __nv_bfloat16 h0 = __float2bfloat16(vv[r][0]);
                    __nv_bfloat16 h1 = __float2bfloat16(vv[r][1]);
                    float r0 = vv[r][0] - __bfloat162float(h0);
                    float r1 = vv[r][1] - __bfloat162float(h1);
                    __nv_bfloat162 th; th.x = h0; th.y = h1;
                    __nv_bfloat162 tl;
                    tl.x = __float2bfloat16(r0); tl.y = __float2bfloat16(r1);
                    *(__nv_bfloat162*)(c0 + bb[r]) = th;
                    *(__nv_bfloat162*)(c1 + bb[r]) = tl;
                }
            }
        }
        if (MODE == 0 && statsPart) {
            // reduce over the 4 lanes of the quad (same rows, different cols)
            #pragma unroll
            for (int o = 1; o < 4; o <<= 1) {
                s0 += __shfl_xor_sync(0xFFFFFFFFu, s0, o);
                q0 += __shfl_xor_sync(0xFFFFFFFFu, q0, o);
                s1 += __shfl_xor_sync(0xFFFFFFFFu, s1, o);
                q1 += __shfl_xor_sync(0xFFFFFFFFu, q1, o);
            }
            if ((lid & 3) == 0) {
                atomicAdd(&statsPart[row0], s0);
                atomicAdd(&statsPart[CCH + row0], q0);
                atomicAdd(&statsPart[row1], s1);
                atomicAdd(&statsPart[CCH + row1], q1);
            }
        }
    }
}

// =====================================================================
// prep / elementwise kernels
// =====================================================================
__global__ void transpose_split2(const float* __restrict__ x,
                                 __nv_bfloat16* __restrict__ h,
                                 __nv_bfloat16* __restrict__ l)
{
    __shared__ float t[32][33];
    const int b = blockIdx.z;
    const int n0 = blockIdx.x * 32, c0 = blockIdx.y * 32;
    const float* xb = x + (size_t)b * CCH * NPIX;
    #pragma unroll
    for (int k = 0; k < 4; k++) {
        const int c = c0 + threadIdx.y + k * 8;
        t[threadIdx.y + k * 8][threadIdx.x] = xb[(size_t)c * NPIX + n0 + threadIdx.x];
    }
    __syncthreads();
    const size_t ob = (size_t)b * NPIX * CCH;
    #pragma unroll
    for (int k = 0; k < 4; k++) {
        const int n = n0 + threadIdx.y + k * 8;
        const float v = t[threadIdx.x][threadIdx.y + k * 8];
        const size_t idx = ob + (size_t)n * CCH + c0 + threadIdx.x;
        __nv_bfloat16 hh = __float2bfloat16(v);
        h[idx] = hh;
        l[idx] = __float2bfloat16(v - __bfloat162float(hh));
    }
}

__global__ void conv_split2(const float* __restrict__ s, __nv_bfloat16* __restrict__ h,
                            __nv_bfloat16* __restrict__ l, int n)
{
    const int i = blockIdx.x * 256 + threadIdx.x;
    if (i >= n) return;
    const float v = s[i];
    __nv_bfloat16 hh = __float2bfloat16(v);
    h[i] = hh; l[i] = __float2bfloat16(v - __bfloat162float(hh));
}

__global__ __launch_bounds__(256) void softmax_split(
    const float* __restrict__ fp, __nv_bfloat16* __restrict__ h, __nv_bfloat16* __restrict__ l)
{
    const int row = blockIdx.x;        // b*256 + c
    const int b = row >> 8, c = row & 255;
    const int d = threadIdx.x;
    float v = 0.f;
    #pragma unroll
    for (int s = 0; s < 4; s++)
        v += fp[((size_t)(b * 4 + s)) * (CI * CI) + c * CI + d];
    __shared__ float red[256];
    red[d] = v; __syncthreads();
    for (int o = 128; o > 0; o >>= 1) {
        if (d < o) red[d] = fmaxf(red[d], red[d + o]);
        __syncthreads();
    }
    const float mx = red[0];
    __syncthreads();
    const float e = __expf(v - mx);
    red[d] = e; __syncthreads();
    for (int o = 128; o > 0; o >>= 1) {
        if (d < o) red[d] += red[d + o];
        __syncthreads();
    }
    const float p = e / red[0];
    const size_t idx = (size_t)row * CI + d;
    __nv_bfloat16 hh = __float2bfloat16(p);
    h[idx] = hh; l[idx] = __float2bfloat16(p - __bfloat162float(hh));
}

// finalize: stats[c] (sum) -> mean, stats[CCH+c] (sumsq) -> rstd, in place
__global__ void bn_finalize(float* __restrict__ stats)
{
    const int c = threadIdx.x;   // 512 threads
    const float cnt = (float)(BATCH * NPIX);
    const float ps = stats[c];
    const float pq = stats[CCH + c];
    const float m = ps / cnt;
    const float var = pq / cnt - m * m;
    stats[c] = m;
    stats[CCH + c] = rsqrtf(var + 1e-5f);
}

__global__ __launch_bounds__(256) void bn_residual(
    const float* __restrict__ z, const float* __restrict__ x,
    const float* __restrict__ gamma, const float* __restrict__ beta,
    const float* __restrict__ stats, float* __restrict__ out)
{
    const size_t i = (size_t)blockIdx.x * blockDim.x + threadIdx.x;
    const int c = (int)((i >> 10) & (CCH - 1));
    const float m = stats[c], r = stats[CCH + c], g = gamma[c], bb = beta[c];
    const float4 zv = ((const float4*)z)[i];
    const float4 xv = ((const float4*)x)[i];
    float4 o;
    o.x = (zv.x - m) * r * g + bb + xv.x;
    o.y = (zv.y - m) * r * g + bb + xv.y;
    o.z = (zv.z - m) * r * g + bb + xv.z;
    o.w = (zv.w - m) * r * g + bb + xv.w;
    ((float4*)out)[i] = o;
}

// =====================================================================
// launch
// =====================================================================
extern "C" void kernel_launch(void* const* d_in, const int* in_sizes, int n_in,
                              void* d_out, int out_size)
{
    (void)in_sizes; (void)n_in; (void)out_size;
    const float* x     = (const float*)d_in[0];
    const float* g_w   = (const float*)d_in[1];
    const float* g_b   = (const float*)d_in[2];
    const float* th_w  = (const float*)d_in[3];
    const float* th_b  = (const float*)d_in[4];
    const float* ph_w  = (const float*)d_in[5];
    const float* ph_b  = (const float*)d_in[6];
    const float* W_w   = (const float*)d_in[7];
    const float* gamma = (const float*)d_in[9];
    const float* beta  = (const float*)d_in[10];
    float* out = (float*)d_out;

    __nv_bfloat16 *xt, *wtp, *gw, *ww, *tp, *gt, *fsm, *yt;
    float *fpart, *z, *stats, *tpb;
    cudaGetSymbolAddress((void**)&xt,    d_xt);
    cudaGetSymbolAddress((void**)&wtp,   d_wtp);
    cudaGetSymbolAddress((void**)&gw,    d_gw);
    cudaGetSymbolAddress((void**)&ww,    d_ww);
    cudaGetSymbolAddress((void**)&tp,    d_tp);
    cudaGetSymbolAddress((void**)&gt,    d_gt);
    cudaGetSymbolAddress((void**)&fpart, d_fpart);
    cudaGetSymbolAddress((void**)&fsm,   d_fsm);
    cudaGetSymbolAddress((void**)&yt,    d_yt);
    cudaGetSymbolAddress((void**)&z,     d_z);
    cudaGetSymbolAddress((void**)&stats, d_stats);
    cudaGetSymbolAddress((void**)&tpb,   d_tpb);

    __nv_bfloat16 *xt0 = xt, *xt1 = xt + XT_SZ;
    __nv_bfloat16 *wtp0 = wtp, *wtp1 = wtp + 512 * 512;
    __nv_bfloat16 *gw0 = gw, *gw1 = gw + CI * CCH;
    __nv_bfloat16 *ww0 = ww, *ww1 = ww + CCH * CI;
    __nv_bfloat16 *tp0 = tp, *tp1 = tp + TP_SZ;
    __nv_bfloat16 *gt0 = gt, *gt1 = gt + GT_SZ;
    __nv_bfloat16 *fs0 = fsm, *fs1 = fsm + F_SZ;
    __nv_bfloat16 *yt0 = yt, *yt1 = yt + YT_SZ;

    const int SMEM = 3 * 4 * 16384 + 1024;   // 3-stage pipeline: 197632 B
    cudaFuncSetAttribute(mma_nt<0>, cudaFuncAttributeMaxDynamicSharedMemorySize, SMEM);
    cudaFuncSetAttribute(mma_nt<1>, cudaFuncAttributeMaxDynamicSharedMemorySize, SMEM);

    // bias stack [theta_b; phi_b]
    cudaMemcpyAsync(tpb,      th_b, CI * 4, cudaMemcpyDeviceToDevice);
    cudaMemcpyAsync(tpb + CI, ph_b, CI * 4, cudaMemcpyDeviceToDevice);

    // zero the fused-stats accumulator
    cudaMemsetAsync(stats, 0, 2 * CCH * sizeof(float));

    // weight splits (2-level everywhere)
    conv_split2<<<(CI * CCH + 255) / 256, 256>>>(th_w, wtp0, wtp1, CI * CCH);
    conv_split2<<<(CI * CCH + 255) / 256, 256>>>(ph_w, wtp0 + CI * CCH, wtp1 + CI * CCH, CI * CCH);
    conv_split2<<<(CI * CCH + 255) / 256, 256>>>(g_w, gw0, gw1, CI * CCH);
    conv_split2<<<(CCH * CI + 255) / 256, 256>>>(W_w, ww0, ww1, CCH * CI);

    // xT 2-level split: (B, 4096, 512)
    transpose_split2<<<dim3(NPIX / 32, CCH / 32, BATCH), dim3(32, 8)>>>(x, xt0, xt1);

    // GEMM1a: tp[b](512,4096) = Wtp(512,512) @ xT[b]^T (+ [th_b;ph_b] per row), hi/lo out
    mma_nt<1><<<dim3(NPIX / 128, 512 / 128, BATCH), 256, SMEM>>>(
        wtp0, wtp1, xt0, xt1,
        nullptr, tp0, tp1, tpb, nullptr, nullptr,
        512, NPIX, CCH, 1, 0, (long long)NPIX * CCH, 512LL * NPIX);

    // GEMM1b: gT[b](4096,256) = xT[b] @ g_w^T (+ g_b per col), hi/lo out
    mma_nt<1><<<dim3(CI / 128, NPIX / 128, BATCH), 256, SMEM>>>(
        xt0, xt1, gw0, gw1,
        nullptr, gt0, gt1, nullptr, g_b, nullptr,
        NPIX, CI, CCH, 1, (long long)NPIX * CCH, 0, (long long)NPIX * CI);

    // GEMM2: f partials = theta @ phi^T, split-K 4, fp32 out
    mma_nt<0><<<dim3(CI / 128, CI / 128, BATCH * 4), 256, SMEM>>>(
        tp0, tp1,
        tp0 + (size_t)CI * NPIX, tp1 + (size_t)CI * NPIX,
        fpart, nullptr, nullptr, nullptr, nullptr, nullptr,
        CI, CI, NPIX, 4, 512LL * NPIX, 512LL * NPIX, (long long)CI * CI);

    // softmax (sums 4 partials) -> hi/lo bf16
    softmax_split<<<BATCH * CI, 256>>>(fpart, fs0, fs1);

    // GEMM3: yT[b](4096,256) = gT[b] @ fsm[b]^T, hi/lo out
    mma_nt<1><<<dim3(CI / 128, NPIX / 128, BATCH), 256, SMEM>>>(
        gt0, gt1, fs0, fs1,
        nullptr, yt0, yt1, nullptr, nullptr, nullptr,
        NPIX, CI, CI, 1, (long long)NPIX * CI, (long long)CI * CI, (long long)NPIX * CI);

    // GEMM4: z[b](512,4096) = W_w @ yT[b]^T (W_b dropped: cancels in BN),
    //        fp32 out + fused per-channel stats partials
    mma_nt<0><<<dim3(NPIX / 128, CCH / 128, BATCH), 256, SMEM>>>(
        ww0, ww1, yt0, yt1,
        z, nullptr, nullptr, nullptr, nullptr, stats,
        CCH, NPIX, CI, 1, 0, (long long)NPIX * CI, (long long)CCH * NPIX);

    // finalize stats + BN + residual
    bn_finalize<<<1, CCH>>>(stats);
    const size_t total4 = (size_t)BATCH * CCH * NPIX / 4;
    bn_residual<<<(unsigned)(total4 / 256), 256>>>(z, x, gamma, beta, stats, out);
}

// round 8
// speedup vs baseline: 4.0179x; 1.0363x over previous
#include <cuda_runtime.h>
#include <cuda_bf16.h>
#include <cstdint>

#define BATCH 16
#define CCH   512
#define CI    256
#define NPIX  4096

// ---------------- scratch (device globals; no allocation allowed) ----------------
static const size_t XT_SZ  = (size_t)BATCH * NPIX * CCH;   // per level
static const size_t TP_SZ  = (size_t)BATCH * 512 * NPIX;
static const size_t GT_SZ  = (size_t)BATCH * NPIX * CI;
static const size_t F_SZ   = (size_t)BATCH * CI * CI;
static const size_t YT_SZ  = (size_t)BATCH * NPIX * CI;

__device__ __nv_bfloat16 d_xt [2][(size_t)BATCH * NPIX * CCH];   // 134 MB
__device__ __nv_bfloat16 d_wtp[2][512 * 512];
__device__ __nv_bfloat16 d_gw [2][CI * CCH];
__device__ __nv_bfloat16 d_ww [2][CCH * CI];
__device__ __nv_bfloat16 d_tp [2][(size_t)BATCH * 512 * NPIX];   // 134 MB
__device__ __nv_bfloat16 d_gt [2][(size_t)BATCH * NPIX * CI];    // 67 MB
__device__ float         d_fpart[(size_t)4 * BATCH * CI * CI];   // 16.8 MB
__device__ __nv_bfloat16 d_fsm[2][(size_t)BATCH * CI * CI];
__device__ __nv_bfloat16 d_yt [2][(size_t)BATCH * NPIX * CI];    // 67 MB
__device__ float         d_z[(size_t)BATCH * CCH * NPIX];        // 134 MB
__device__ float         d_stats[2 * CCH];                       // raw partials
__device__ float         d_tpb[512];

// ---------------- helpers (arch-portable PTX only: sm_80+) ----------------
__device__ __forceinline__ uint32_t smem_u32(const void* p) {
    uint32_t a;
    asm("{ .reg .u64 t; cvta.to.shared.u64 t, %1; cvt.u32.u64 %0, t; }" : "=r"(a) : "l"(p));
    return a;
}
#define SMEM_SWIZZLE_128B(o) ((o) ^ (((o) >> 3) & 0x70))

__device__ __forceinline__ void cpasync16(uint32_t dst, const void* src) {
    asm volatile("cp.async.cg.shared.global [%0], [%1], 16;" :: "r"(dst), "l"(src));
}
#define CP_COMMIT() asm volatile("cp.async.commit_group;" ::: "memory")

__device__ __forceinline__ void ldsm4(uint32_t addr, uint32_t& r0, uint32_t& r1,
                                      uint32_t& r2, uint32_t& r3) {
    asm volatile("ldmatrix.sync.aligned.m8n8.x4.shared.b16 {%0,%1,%2,%3}, [%4];"
                 : "=r"(r0), "=r"(r1), "=r"(r2), "=r"(r3) : "r"(addr));
}
__device__ __forceinline__ void mma16816(float* c, const uint32_t* a, uint32_t b0, uint32_t b1) {
    asm volatile(
        "mma.sync.aligned.m16n8k16.row.col.f32.bf16.bf16.f32 "
        "{%0,%1,%2,%3}, {%4,%5,%6,%7}, {%8,%9}, {%0,%1,%2,%3};"
        : "+f"(c[0]), "+f"(c[1]), "+f"(c[2]), "+f"(c[3])
        : "r"(a[0]), "r"(a[1]), "r"(a[2]), "r"(a[3]), "r"(b0), "r"(b1));
}

// =====================================================================
// NT GEMM on tensor cores (mma.sync bf16, fp32 acc), 2-level split inputs:
//   D[M,N] = A0*B0^T + A0*B1^T + A1*B0^T    (ll term dropped, ~2^-18)
// A,B: K-major (ld = K). CTA tile 64x128, 128 threads (4 warps, warp tile
// 32x64), K-chunk 64, SW128-swizzled smem, 2-stage cp.async pipeline,
// 96KB smem -> 2 CTAs/SM (bubble cross-coverage).
// MODE: 0 = fp32 out (optional fused per-row stats atomics), 1 = hi/lo bf16 out.
// grid = (N/128, M/64, batch*nsplit)
// =====================================================================
template <int MODE>
__global__ __launch_bounds__(128) void mma_nt(
    const __nv_bfloat16* __restrict__ a0, const __nv_bfloat16* __restrict__ a1,
    const __nv_bfloat16* __restrict__ b0, const __nv_bfloat16* __restrict__ b1,
    float* __restrict__ cf,
    __nv_bfloat16* __restrict__ c0, __nv_bfloat16* __restrict__ c1,
    const float* __restrict__ biasRow, const float* __restrict__ biasCol,
    float* __restrict__ statsPart,
    int M, int N, int K, int nsplit,
    long long sA, long long sB, long long sC)
{
    // stage layout: A0(8K) A1(8K) B0(16K) B1(16K) = 48KB
    constexpr int stageBytes = 49152;

    extern __shared__ char smraw[];
    const uint32_t smem_base = (smem_u32(smraw) + 1023u) & ~1023u;

    const int tid = threadIdx.x;
    const int wid = tid >> 5, lid = tid & 31;
    const int warpM = (wid & 1) * 32;       // 2 warps over M (64 rows)
    const int warpN = (wid >> 1) * 64;      // 2 warps over N (128 cols)

    const int bz = blockIdx.z;
    const int b  = bz / nsplit, sp = bz % nsplit;
    const int Ksub = K / nsplit;
    const int nk = Ksub / 64;
    const int k0base = sp * Ksub;
    const int mBase = blockIdx.y * 64;
    const int nBase = blockIdx.x * 128;

    const __nv_bfloat16* ta[4];
    ta[0] = a0 + (size_t)b * sA;
    ta[1] = a1 + (size_t)b * sA;
    ta[2] = b0 + (size_t)b * sB;
    ta[3] = b1 + (size_t)b * sB;

    auto loadChunk = [&](int ci, int st) {
        const int k0 = k0base + ci * 64;
        const uint32_t sb = smem_base + st * stageBytes;
        const uint32_t toff[4] = {0u, 8192u, 16384u, 32768u};
        #pragma unroll
        for (int t = 0; t < 4; t++) {
            const int rows = (t < 2) ? 64 : 128;
            const int rb   = (t < 2) ? mBase : nBase;
            const __nv_bfloat16* src = ta[t] + (size_t)rb * K + k0;
            const uint32_t tb = sb + toff[t];
            for (int i = tid; i < rows * 8; i += 128) {
                const int row = i >> 3, seg = i & 7;
                cpasync16(tb + SMEM_SWIZZLE_128B(row * 128 + seg * 16),
                          src + (size_t)row * K + seg * 8);
            }
        }
    };

    float acc[2][8][4];
    #pragma unroll
    for (int i = 0; i < 2; i++)
        #pragma unroll
        for (int j = 0; j < 8; j++)
            #pragma unroll
            for (int k = 0; k < 4; k++) acc[i][j][k] = 0.f;

    loadChunk(0, 0); CP_COMMIT();
    loadChunk(1, 1); CP_COMMIT();

    const int lRow = lid & 15;              // ldmatrix row within 16
    const int lHi  = (lid >> 4) & 1;        // ldmatrix 16B half select

    for (int i = 0; i < nk; i++) {
        const uint32_t sb = smem_base + (i & 1) * stageBytes;
        asm volatile("cp.async.wait_group 1;" ::: "memory");
        __syncthreads();                    // chunk i resident

        const uint32_t A0b = sb, A1b = sb + 8192;
        const uint32_t B0b = sb + 16384, B1b = sb + 32768;
        #pragma unroll
        for (int ks = 0; ks < 4; ks++) {
            const int colB = ks * 32 + lHi * 16;
            uint32_t fa0[2][4], fa1[2][4], fb0[4][4], fb1[4][4];
            #pragma unroll
            for (int mi = 0; mi < 2; mi++) {
                const int row = warpM + 16 * mi + lRow;
                const uint32_t off = SMEM_SWIZZLE_128B(row * 128 + colB);
                ldsm4(A0b + off, fa0[mi][0], fa0[mi][1], fa0[mi][2], fa0[mi][3]);
                ldsm4(A1b + off, fa1[mi][0], fa1[mi][1], fa1[mi][2], fa1[mi][3]);
            }
            #pragma unroll
            for (int nj = 0; nj < 4; nj++) {
                const int row = warpN + 16 * nj + lRow;
                const uint32_t off = SMEM_SWIZZLE_128B(row * 128 + colB);
                ldsm4(B0b + off, fb0[nj][0], fb0[nj][1], fb0[nj][2], fb0[nj][3]);
                ldsm4(B1b + off, fb1[nj][0], fb1[nj][1], fb1[nj][2], fb1[nj][3]);
            }
            #pragma unroll
            for (int mi = 0; mi < 2; mi++)
                #pragma unroll
                for (int jn = 0; jn < 8; jn++)
                    mma16816(acc[mi][jn], fa0[mi],
                             fb0[jn >> 1][jn & 1], fb0[jn >> 1][2 + (jn & 1)]);
            #pragma unroll
            for (int mi = 0; mi < 2; mi++)
                #pragma unroll
                for (int jn = 0; jn < 8; jn++)
                    mma16816(acc[mi][jn], fa0[mi],
                             fb1[jn >> 1][jn & 1], fb1[jn >> 1][2 + (jn & 1)]);
            #pragma unroll
            for (int mi = 0; mi < 2; mi++)
                #pragma unroll
                for (int jn = 0; jn < 8; jn++)
                    mma16816(acc[mi][jn], fa1[mi],
                             fb0[jn >> 1][jn & 1], fb0[jn >> 1][2 + (jn & 1)]);
        }
        __syncthreads();                    // all warps done reading buf i&1
        if (i + 2 < nk) { loadChunk(i + 2, i & 1); CP_COMMIT(); }
    }

    // ---- epilogue ----
    const int gr = lid >> 2;            // 0..7
    const int gc = (lid & 3) * 2;       // 0,2,4,6
    const size_t cOff = (size_t)bz * sC;

    #pragma unroll
    for (int mi = 0; mi < 2; mi++) {
        const int row0 = mBase + warpM + 16 * mi + gr;
        const int row1 = row0 + 8;
        const float br0 = biasRow ? biasRow[row0] : 0.f;
        const float br1 = biasRow ? biasRow[row1] : 0.f;
        float s0 = 0.f, q0 = 0.f, s1 = 0.f, q1 = 0.f;
        #pragma unroll
        for (int jn = 0; jn < 8; jn++) {
            const int col = nBase + warpN + 8 * jn + gc;
            float v00 = acc[mi][jn][0] + br0;
            float v01 = acc[mi][jn][1] + br0;
            float v10 = acc[mi][jn][2] + br1;
            float v11 = acc[mi][jn][3] + br1;
            if (biasCol) {
                const float bc0 = biasCol[col], bc1 = biasCol[col + 1];
                v00 += bc0; v01 += bc1; v10 += bc0; v11 += bc1;
            }
            const size_t base0 = cOff + (size_t)row0 * N + col;
            const size_t base1 = cOff + (size_t)row1 * N + col;
            if (MODE == 0) {
                *(float2*)(cf + base0) = make_float2(v00, v01);
                *(float2*)(cf + base1) = make_float2(v10, v11);
                if (statsPart) {
                    s0 += v00 + v01; q0 += v00 * v00 + v01 * v01;
                    s1 += v10 + v11; q1 += v10 * v10 + v11 * v11;
                }
            } else {
                float vv[2][2] = {{v00, v01}, {v10, v11}};
                const size_t bb[2] = {base0, base1};
                #pragma unroll
                for (int r = 0; r < 2; r++) {
                    __nv_bfloat16 h0 = __float2bfloat16(vv[r][0]);
                    __nv_bfloat16 h1 = __float2bfloat16(vv[r][1]);
                    float r0 = vv[r][0] - __bfloat162float(h0);
                    float r1 = vv[r][1] - __bfloat162float(h1);
                    __nv_bfloat162 th; th.x = h0; th.y = h1;
                    __nv_bfloat162 tl;
                    tl.x = __float2bfloat16(r0); tl.y = __float2bfloat16(r1);
                    *(__nv_bfloat162*)(c0 + bb[r]) = th;
                    *(__nv_bfloat162*)(c1 + bb[r]) = tl;
                }
            }
        }
        if (MODE == 0 && statsPart) {
            #pragma unroll
            for (int o = 1; o < 4; o <<= 1) {
                s0 += __shfl_xor_sync(0xFFFFFFFFu, s0, o);
                q0 += __shfl_xor_sync(0xFFFFFFFFu, q0, o);
                s1 += __shfl_xor_sync(0xFFFFFFFFu, s1, o);
                q1 += __shfl_xor_sync(0xFFFFFFFFu, q1, o);
            }
            if ((lid & 3) == 0) {
                atomicAdd(&statsPart[row0], s0);
                atomicAdd(&statsPart[CCH + row0], q0);
                atomicAdd(&statsPart[row1], s1);
                atomicAdd(&statsPart[CCH + row1], q1);
            }
        }
    }
}

// =====================================================================
// prep: all four weight splits + bias stack + stats zero (ONE launch)
// =====================================================================
__global__ void prep_splits(
    const float* __restrict__ th_w, const float* __restrict__ ph_w,
    const float* __restrict__ g_w,  const float* __restrict__ W_w,
    __nv_bfloat16* __restrict__ wtp0, __nv_bfloat16* __restrict__ wtp1,
    __nv_bfloat16* __restrict__ gw0,  __nv_bfloat16* __restrict__ gw1,
    __nv_bfloat16* __restrict__ ww0,  __nv_bfloat16* __restrict__ ww1,
    const float* __restrict__ th_b, const float* __restrict__ ph_b,
    float* __restrict__ tpb, float* __restrict__ stats)
{
    const int i = blockIdx.x * 256 + threadIdx.x;   // 0 .. 4*131072-1
    const int arr = i >> 17;
    const int off = i & 131071;
    const float* src;
    __nv_bfloat16 *dh, *dl;
    switch (arr) {
        case 0:  src = th_w; dh = wtp0;          dl = wtp1;          break;
        case 1:  src = ph_w; dh = wtp0 + 131072; dl = wtp1 + 131072; break;
        case 2:  src = g_w;  dh = gw0;           dl = gw1;           break;
        default: src = W_w;  dh = ww0;           dl = ww1;           break;
    }
    const float v = src[off];
    const __nv_bfloat16 hh = __float2bfloat16(v);
    dh[off] = hh;
    dl[off] = __float2bfloat16(v - __bfloat162float(hh));

    if (i < 512)  tpb[i]  = (i < 256) ? th_b[i] : ph_b[i - 256];
    if (i < 1024) stats[i] = 0.f;
}

// =====================================================================
// transpose + 2-level split of x
// =====================================================================
__global__ void transpose_split2(const float* __restrict__ x,
                                 __nv_bfloat16* __restrict__ h,
                                 __nv_bfloat16* __restrict__ l)
{
    __shared__ float t[32][33];
    const int b = blockIdx.z;
    const int n0 = blockIdx.x * 32, c0 = blockIdx.y * 32;
    const float* xb = x + (size_t)b * CCH * NPIX;
    #pragma unroll
    for (int k = 0; k < 4; k++) {
        const int c = c0 + threadIdx.y + k * 8;
        t[threadIdx.y + k * 8][threadIdx.x] = xb[(size_t)c * NPIX + n0 + threadIdx.x];
    }
    __syncthreads();
    const size_t ob = (size_t)b * NPIX * CCH;
    #pragma unroll
    for (int k = 0; k < 4; k++) {
        const int n = n0 + threadIdx.y + k * 8;
        const float v = t[threadIdx.x][threadIdx.y + k * 8];
        const size_t idx = ob + (size_t)n * CCH + c0 + threadIdx.x;
        __nv_bfloat16 hh = __float2bfloat16(v);
        h[idx] = hh;
        l[idx] = __float2bfloat16(v - __bfloat162float(hh));
    }
}

__global__ __launch_bounds__(256) void softmax_split(
    const float* __restrict__ fp, __nv_bfloat16* __restrict__ h, __nv_bfloat16* __restrict__ l)
{
    const int row = blockIdx.x;        // b*256 + c
    const int b = row >> 8, c = row & 255;
    const int d = threadIdx.x;
    float v = 0.f;
    #pragma unroll
    for (int s = 0; s < 4; s++)
        v += fp[((size_t)(b * 4 + s)) * (CI * CI) + c * CI + d];
    __shared__ float red[256];
    red[d] = v; __syncthreads();
    for (int o = 128; o > 0; o >>= 1) {
        if (d < o) red[d] = fmaxf(red[d], red[d + o]);
        __syncthreads();
    }
    const float mx = red[0];
    __syncthreads();
    const float e = __expf(v - mx);
    red[d] = e; __syncthreads();
    for (int o = 128; o > 0; o >>= 1) {
        if (d < o) red[d] += red[d + o];
        __syncthreads();
    }
    const float p = e / red[0];
    const size_t idx = (size_t)row * CI + d;
    __nv_bfloat16 hh = __float2bfloat16(p);
    h[idx] = hh; l[idx] = __float2bfloat16(p - __bfloat162float(hh));
}

// =====================================================================
// BN (finalize folded in) + residual
// =====================================================================
__global__ __launch_bounds__(256) void bn_residual(
    const float* __restrict__ z, const float* __restrict__ x,
    const float* __restrict__ gamma, const float* __restrict__ beta,
    const float* __restrict__ stats, float* __restrict__ out)
{
    const size_t i = (size_t)blockIdx.x * blockDim.x + threadIdx.x;
    const int c = (int)((i >> 10) & (CCH - 1));
    const float cnt = (float)(BATCH * NPIX);
    const float m = stats[c] / cnt;
    const float var = stats[CCH + c] / cnt - m * m;
    const float r = rsqrtf(var + 1e-5f);
    const float g = gamma[c], bb = beta[c];
    const float4 zv = ((const float4*)z)[i];
    const float4 xv = ((const float4*)x)[i];
    float4 o;
    o.x = (zv.x - m) * r * g + bb + xv.x;
    o.y = (zv.y - m) * r * g + bb + xv.y;
    o.z = (zv.z - m) * r * g + bb + xv.z;
    o.w = (zv.w - m) * r * g + bb + xv.w;
    ((float4*)out)[i] = o;
}

// =====================================================================
// launch
// =====================================================================
extern "C" void kernel_launch(void* const* d_in, const int* in_sizes, int n_in,
                              void* d_out, int out_size)
{
    (void)in_sizes; (void)n_in; (void)out_size;
    const float* x     = (const float*)d_in[0];
    const float* g_w   = (const float*)d_in[1];
    const float* g_b   = (const float*)d_in[2];
    const float* th_w  = (const float*)d_in[3];
    const float* th_b  = (const float*)d_in[4];
    const float* ph_w  = (const float*)d_in[5];
    const float* ph_b  = (const float*)d_in[6];
    const float* W_w   = (const float*)d_in[7];
    const float* gamma = (const float*)d_in[9];
    const float* beta  = (const float*)d_in[10];
    float* out = (float*)d_out;

    __nv_bfloat16 *xt, *wtp, *gw, *ww, *tp, *gt, *fsm, *yt;
    float *fpart, *z, *stats, *tpb;
    cudaGetSymbolAddress((void**)&xt,    d_xt);
    cudaGetSymbolAddress((void**)&wtp,   d_wtp);
    cudaGetSymbolAddress((void**)&gw,    d_gw);
    cudaGetSymbolAddress((void**)&ww,    d_ww);
    cudaGetSymbolAddress((void**)&tp,    d_tp);
    cudaGetSymbolAddress((void**)&gt,    d_gt);
    cudaGetSymbolAddress((void**)&fpart, d_fpart);
    cudaGetSymbolAddress((void**)&fsm,   d_fsm);
    cudaGetSymbolAddress((void**)&yt,    d_yt);
    cudaGetSymbolAddress((void**)&z,     d_z);
    cudaGetSymbolAddress((void**)&stats, d_stats);
    cudaGetSymbolAddress((void**)&tpb,   d_tpb);

    __nv_bfloat16 *xt0 = xt, *xt1 = xt + XT_SZ;
    __nv_bfloat16 *wtp0 = wtp, *wtp1 = wtp + 512 * 512;
    __nv_bfloat16 *gw0 = gw, *gw1 = gw + CI * CCH;
    __nv_bfloat16 *ww0 = ww, *ww1 = ww + CCH * CI;
    __nv_bfloat16 *tp0 = tp, *tp1 = tp + TP_SZ;
    __nv_bfloat16 *gt0 = gt, *gt1 = gt + GT_SZ;
    __nv_bfloat16 *fs0 = fsm, *fs1 = fsm + F_SZ;
    __nv_bfloat16 *yt0 = yt, *yt1 = yt + YT_SZ;

    const int SMEM = 2 * 49152 + 1024;   // 2-stage, 64x128 tile: 99328 B
    cudaFuncSetAttribute(mma_nt<0>, cudaFuncAttributeMaxDynamicSharedMemorySize, SMEM);
    cudaFuncSetAttribute(mma_nt<1>, cudaFuncAttributeMaxDynamicSharedMemorySize, SMEM);

    // one prep launch: 4 weight splits + bias stack + stats zero
    prep_splits<<<(4 * 131072) / 256, 256>>>(
        th_w, ph_w, g_w, W_w,
        wtp0, wtp1, gw0, gw1, ww0, ww1,
        th_b, ph_b, tpb, stats);

    // xT 2-level split: (B, 4096, 512)
    transpose_split2<<<dim3(NPIX / 32, CCH / 32, BATCH), dim3(32, 8)>>>(x, xt0, xt1);

    // GEMM1a: tp[b](512,4096) = Wtp(512,512) @ xT[b]^T (+ [th_b;ph_b] per row), hi/lo out
    mma_nt<1><<<dim3(NPIX / 128, 512 / 64, BATCH), 128, SMEM>>>(
        wtp0, wtp1, xt0, xt1,
        nullptr, tp0, tp1, tpb, nullptr, nullptr,
        512, NPIX, CCH, 1, 0, (long long)NPIX * CCH, 512LL * NPIX);

    // GEMM1b: gT[b](4096,256) = xT[b] @ g_w^T (+ g_b per col), hi/lo out
    mma_nt<1><<<dim3(CI / 128, NPIX / 64, BATCH), 128, SMEM>>>(
        xt0, xt1, gw0, gw1,
        nullptr, gt0, gt1, nullptr, g_b, nullptr,
        NPIX, CI, CCH, 1, (long long)NPIX * CCH, 0, (long long)NPIX * CI);

    // GEMM2: f partials = theta @ phi^T, split-K 4, fp32 out
    mma_nt<0><<<dim3(CI / 128, CI / 64, BATCH * 4), 128, SMEM>>>(
        tp0, tp1,
        tp0 + (size_t)CI * NPIX, tp1 + (size_t)CI * NPIX,
        fpart, nullptr, nullptr, nullptr, nullptr, nullptr,
        CI, CI, NPIX, 4, 512LL * NPIX, 512LL * NPIX, (long long)CI * CI);

    // softmax (sums 4 partials) -> hi/lo bf16
    softmax_split<<<BATCH * CI, 256>>>(fpart, fs0, fs1);

    // GEMM3: yT[b](4096,256) = gT[b] @ fsm[b]^T, hi/lo out
    mma_nt<1><<<dim3(CI / 128, NPIX / 64, BATCH), 128, SMEM>>>(
        gt0, gt1, fs0, fs1,
        nullptr, yt0, yt1, nullptr, nullptr, nullptr,
        NPIX, CI, CI, 1, (long long)NPIX * CI, (long long)CI * CI, (long long)NPIX * CI);

    // GEMM4: z[b](512,4096) = W_w @ yT[b]^T (W_b dropped: cancels in BN),
    //        fp32 out + fused per-channel stats partials
    mma_nt<0><<<dim3(NPIX / 128, 512 / 64, BATCH), 128, SMEM>>>(
        ww0, ww1, yt0, yt1,
        z, nullptr, nullptr, nullptr, nullptr, stats,
        CCH, NPIX, CI, 1, 0, (long long)NPIX * CI, (long long)CCH * NPIX);

    // BN (finalize folded) + residual
    const size_t total4 = (size_t)BATCH * CCH * NPIX / 4;
    bn_residual<<<(unsigned)(total4 / 256), 256>>>(z, x, gamma, beta, stats, out);
}

// round 9
// speedup vs baseline: 4.1655x; 1.0367x over previous
#include <cuda_runtime.h>
#include <cuda_bf16.h>
#include <cstdint>

#define BATCH 16
#define CCH   512
#define CI    256
#define NPIX  4096
#define FSPLIT 8

// ---------------- scratch (device globals; no allocation allowed) ----------------
static const size_t XT_SZ  = (size_t)BATCH * NPIX * CCH;   // per level
static const size_t TP_SZ  = (size_t)BATCH * 512 * NPIX;
static const size_t GT_SZ  = (size_t)BATCH * NPIX * CI;
static const size_t F_SZ   = (size_t)BATCH * CI * CI;
static const size_t YT_SZ  = (size_t)BATCH * NPIX * CI;

__device__ __nv_bfloat16 d_xt [2][(size_t)BATCH * NPIX * CCH];   // 134 MB
__device__ __nv_bfloat16 d_wtp[2][512 * 512];
__device__ __nv_bfloat16 d_gw [2][CI * CCH];
__device__ __nv_bfloat16 d_ww [2][CCH * CI];
__device__ __nv_bfloat16 d_tp [2][(size_t)BATCH * 512 * NPIX];   // 134 MB
__device__ __nv_bfloat16 d_gt [2][(size_t)BATCH * NPIX * CI];    // 67 MB
__device__ float         d_fpart[(size_t)FSPLIT * BATCH * CI * CI]; // 33.5 MB
__device__ __nv_bfloat16 d_fsm[2][(size_t)BATCH * CI * CI];
__device__ __nv_bfloat16 d_yt [2][(size_t)BATCH * NPIX * CI];    // 67 MB
__device__ float         d_z[(size_t)BATCH * CCH * NPIX];        // 134 MB
__device__ float         d_stats[2 * CCH];                       // raw partials
__device__ float         d_tpb[512];

// ---------------- helpers (arch-portable PTX only: sm_80+) ----------------
__device__ __forceinline__ uint32_t smem_u32(const void* p) {
    uint32_t a;
    asm("{ .reg .u64 t; cvta.to.shared.u64 t, %1; cvt.u32.u64 %0, t; }" : "=r"(a) : "l"(p));
    return a;
}
// SW64 swizzle for 64-byte rows: o ^ ((o>>3)&0x30)
#define SMEM_SWIZZLE_64B(o) ((o) ^ (((o) >> 3) & 0x30))

__device__ __forceinline__ void cpasync16(uint32_t dst, const void* src) {
    asm volatile("cp.async.cg.shared.global [%0], [%1], 16;" :: "r"(dst), "l"(src));
}
#define CP_COMMIT() asm volatile("cp.async.commit_group;" ::: "memory")

__device__ __forceinline__ void ldsm4(uint32_t addr, uint32_t& r0, uint32_t& r1,
                                      uint32_t& r2, uint32_t& r3) {
    asm volatile("ldmatrix.sync.aligned.m8n8.x4.shared.b16 {%0,%1,%2,%3}, [%4];"
                 : "=r"(r0), "=r"(r1), "=r"(r2), "=r"(r3) : "r"(addr));
}
__device__ __forceinline__ void mma16816(float* c, const uint32_t* a, uint32_t b0, uint32_t b1) {
    asm volatile(
        "mma.sync.aligned.m16n8k16.row.col.f32.bf16.bf16.f32 "
        "{%0,%1,%2,%3}, {%4,%5,%6,%7}, {%8,%9}, {%0,%1,%2,%3};"
        : "+f"(c[0]), "+f"(c[1]), "+f"(c[2]), "+f"(c[3])
        : "r"(a[0]), "r"(a[1]), "r"(a[2]), "r"(a[3]), "r"(b0), "r"(b1));
}

// =====================================================================
// NT GEMM on tensor cores (mma.sync bf16, fp32 acc), 2-level split inputs:
//   D[M,N] = A0*B0^T + A0*B1^T + A1*B0^T    (ll term dropped, ~2^-18)
// A,B: K-major (ld = K). CTA tile 64x128, 128 threads (4 warps, warp tile
// 32x64). K-chunk 32 (64-byte smem rows, SW64 swizzle), 3-stage cp.async
// pipeline, 72KB smem -> 3 CTAs/SM.
// MODE: 0 = fp32 out (optional fused per-row stats atomics), 1 = hi/lo bf16 out.
// grid = (N/128, M/64, batch*nsplit)
// =====================================================================
template <int MODE>
__global__ __launch_bounds__(128, 3) void mma_nt(
    const __nv_bfloat16* __restrict__ a0, const __nv_bfloat16* __restrict__ a1,
    const __nv_bfloat16* __restrict__ b0, const __nv_bfloat16* __restrict__ b1,
    float* __restrict__ cf,
    __nv_bfloat16* __restrict__ c0, __nv_bfloat16* __restrict__ c1,
    const float* __restrict__ biasRow, const float* __restrict__ biasCol,
    float* __restrict__ statsPart,
    int M, int N, int K, int nsplit,
    long long sA, long long sB, long long sC)
{
    // stage layout (64B rows): A0 64x64B=4K @0, A1 @4K, B0 128x64B=8K @8K, B1 @16K
    constexpr int stageBytes = 24576;       // 24KB; 3 stages = 72KB

    extern __shared__ char smraw[];
    const uint32_t smem_base = (smem_u32(smraw) + 1023u) & ~1023u;

    const int tid = threadIdx.x;
    const int wid = tid >> 5, lid = tid & 31;
    const int warpM = (wid & 1) * 32;       // 2 warps over M (64 rows)
    const int warpN = (wid >> 1) * 64;      // 2 warps over N (128 cols)

    const int bz = blockIdx.z;
    const int b  = bz / nsplit, sp = bz % nsplit;
    const int Ksub = K / nsplit;
    const int nk = Ksub / 32;
    const int k0base = sp * Ksub;
    const int mBase = blockIdx.y * 64;
    const int nBase = blockIdx.x * 128;

    const __nv_bfloat16* ta[4];
    ta[0] = a0 + (size_t)b * sA;
    ta[1] = a1 + (size_t)b * sA;
    ta[2] = b0 + (size_t)b * sB;
    ta[3] = b1 + (size_t)b * sB;

    auto loadChunk = [&](int ci, int st) {
        const int k0 = k0base + ci * 32;
        const uint32_t sb = smem_base + st * stageBytes;
        const uint32_t toff[4] = {0u, 4096u, 8192u, 16384u};
        #pragma unroll
        for (int t = 0; t < 4; t++) {
            const int rows = (t < 2) ? 64 : 128;
            const int rb   = (t < 2) ? mBase : nBase;
            const __nv_bfloat16* src = ta[t] + (size_t)rb * K + k0;
            const uint32_t tb = sb + toff[t];
            for (int i = tid; i < rows * 4; i += 128) {
                const int row = i >> 2, seg = i & 3;
                cpasync16(tb + SMEM_SWIZZLE_64B(row * 64 + seg * 16),
                          src + (size_t)row * K + seg * 8);
            }
        }
    };

    float acc[2][8][4];
    #pragma unroll
    for (int i = 0; i < 2; i++)
        #pragma unroll
        for (int j = 0; j < 8; j++)
            #pragma unroll
            for (int k = 0; k < 4; k++) acc[i][j][k] = 0.f;

    loadChunk(0, 0); CP_COMMIT();
    loadChunk(1, 1); CP_COMMIT();

    const int lRow = lid & 15;              // ldmatrix row within 16
    const int lHi  = (lid >> 4) & 1;        // ldmatrix 16B half select

    // precomputed swizzled row bases: addr = base + (colB ^ xr), colB = ks*32+lHi*16
    uint32_t baA[2], xrA[2], baB[4], xrB[4];
    #pragma unroll
    for (int mi = 0; mi < 2; mi++) {
        const int row = warpM + 16 * mi + lRow;
        baA[mi] = row * 64;
        xrA[mi] = (row & 6) * 8;
    }
    #pragma unroll
    for (int nj = 0; nj < 4; nj++) {
        const int row = warpN + 16 * nj + lRow;
        baB[nj] = row * 64;
        xrB[nj] = (row & 6) * 8;
    }
    const uint32_t colH = lHi * 16;

    for (int i = 0; i < nk; i++) {
        const uint32_t sb = smem_base + (i % 3) * stageBytes;
        asm volatile("cp.async.wait_group 1;" ::: "memory");
        __syncthreads();                    // chunk i resident; all done with i-1

        if (i + 2 < nk) { loadChunk(i + 2, (i + 2) % 3); CP_COMMIT(); }

        const uint32_t A0b = sb, A1b = sb + 4096;
        const uint32_t B0b = sb + 8192, B1b = sb + 16384;
        #pragma unroll
        for (int ks = 0; ks < 2; ks++) {
            const uint32_t colB = ks * 32 + colH;
            uint32_t fa0[2][4], fa1[2][4], fb0[4][4], fb1[4][4];
            #pragma unroll
            for (int mi = 0; mi < 2; mi++) {
                const uint32_t off = baA[mi] + (colB ^ xrA[mi]);
                ldsm4(A0b + off, fa0[mi][0], fa0[mi][1], fa0[mi][2], fa0[mi][3]);
                ldsm4(A1b + off, fa1[mi][0], fa1[mi][1], fa1[mi][2], fa1[mi][3]);
            }
            #pragma unroll
            for (int nj = 0; nj < 4; nj++) {
                const uint32_t off = baB[nj] + (colB ^ xrB[nj]);
                ldsm4(B0b + off, fb0[nj][0], fb0[nj][1], fb0[nj][2], fb0[nj][3]);
                ldsm4(B1b + off, fb1[nj][0], fb1[nj][1], fb1[nj][2], fb1[nj][3]);
            }
            #pragma unroll
            for (int mi = 0; mi < 2; mi++)
                #pragma unroll
                for (int jn = 0; jn < 8; jn++)
                    mma16816(acc[mi][jn], fa0[mi],
                             fb0[jn >> 1][jn & 1], fb0[jn >> 1][2 + (jn & 1)]);
            #pragma unroll
            for (int mi = 0; mi < 2; mi++)
                #pragma unroll
                for (int jn = 0; jn < 8; jn++)
                    mma16816(acc[mi][jn], fa0[mi],
                             fb1[jn >> 1][jn & 1], fb1[jn >> 1][2 + (jn & 1)]);
            #pragma unroll
            for (int mi = 0; mi < 2; mi++)
                #pragma unroll
                for (int jn = 0; jn < 8; jn++)
                    mma16816(acc[mi][jn], fa1[mi],
                             fb0[jn >> 1][jn & 1], fb0[jn >> 1][2 + (jn & 1)]);
        }
    }

    // ---- epilogue ----
    const int gr = lid >> 2;            // 0..7
    const int gc = (lid & 3) * 2;       // 0,2,4,6
    const size_t cOff = (size_t)bz * sC;

    #pragma unroll
    for (int mi = 0; mi < 2; mi++) {
        const int row0 = mBase + warpM + 16 * mi + gr;
        const int row1 = row0 + 8;
        const float br0 = biasRow ? biasRow[row0] : 0.f;
        const float br1 = biasRow ? biasRow[row1] : 0.f;
        float s0 = 0.f, q0 = 0.f, s1 = 0.f, q1 = 0.f;
        #pragma unroll
        for (int jn = 0; jn < 8; jn++) {
            const int col = nBase + warpN + 8 * jn + gc;
            float v00 = acc[mi][jn][0] + br0;
            float v01 = acc[mi][jn][1] + br0;
            float v10 = acc[mi][jn][2] + br1;
            float v11 = acc[mi][jn][3] + br1;
            if (biasCol) {
                const float bc0 = biasCol[col], bc1 = biasCol[col + 1];
                v00 += bc0; v01 += bc1; v10 += bc0; v11 += bc1;
            }
            const size_t base0 = cOff + (size_t)row0 * N + col;
            const size_t base1 = cOff + (size_t)row1 * N + col;
            if (MODE == 0) {
                *(float2*)(cf + base0) = make_float2(v00, v01);
                *(float2*)(cf + base1) = make_float2(v10, v11);
                if (statsPart) {
                    s0 += v00 + v01; q0 += v00 * v00 + v01 * v01;
                    s1 += v10 + v11; q1 += v10 * v10 + v11 * v11;
                }
            } else {
                float vv[2][2] = {{v00, v01}, {v10, v11}};
                const size_t bb[2] = {base0, base1};
                #pragma unroll
                for (int r = 0; r < 2; r++) {
                    __nv_bfloat16 h0 = __float2bfloat16(vv[r][0]);
                    __nv_bfloat16 h1 = __float2bfloat16(vv[r][1]);
                    float r0 = vv[r][0] - __bfloat162float(h0);
                    float r1 = vv[r][1] - __bfloat162float(h1);
                    __nv_bfloat162 th; th.x = h0; th.y = h1;
                    __nv_bfloat162 tl;
                    tl.x = __float2bfloat16(r0); tl.y = __float2bfloat16(r1);
                    *(__nv_bfloat162*)(c0 + bb[r]) = th;
                    *(__nv_bfloat162*)(c1 + bb[r]) = tl;
                }
            }
        }
        if (MODE == 0 && statsPart) {
            #pragma unroll
            for (int o = 1; o < 4; o <<= 1) {
                s0 += __shfl_xor_sync(0xFFFFFFFFu, s0, o);
                q0 += __shfl_xor_sync(0xFFFFFFFFu, q0, o);
                s1 += __shfl_xor_sync(0xFFFFFFFFu, s1, o);
                q1 += __shfl_xor_sync(0xFFFFFFFFu, q1, o);
            }
            if ((lid & 3) == 0) {
                atomicAdd(&statsPart[row0], s0);
                atomicAdd(&statsPart[CCH + row0], q0);
                atomicAdd(&statsPart[row1], s1);
                atomicAdd(&statsPart[CCH + row1], q1);
            }
        }
    }
}

// =====================================================================
// prep: all four weight splits + bias stack + stats zero (ONE launch)
// =====================================================================
__global__ void prep_splits(
    const float* __restrict__ th_w, const float* __restrict__ ph_w,
    const float* __restrict__ g_w,  const float* __restrict__ W_w,
    __nv_bfloat16* __restrict__ wtp0, __nv_bfloat16* __restrict__ wtp1,
    __nv_bfloat16* __restrict__ gw0,  __nv_bfloat16* __restrict__ gw1,
    __nv_bfloat16* __restrict__ ww0,  __nv_bfloat16* __restrict__ ww1,
    const float* __restrict__ th_b, const float* __restrict__ ph_b,
    float* __restrict__ tpb, float* __restrict__ stats)
{
    const int i = blockIdx.x * 256 + threadIdx.x;   // 0 .. 4*131072-1
    const int arr = i >> 17;
    const int off = i & 131071;
    const float* src;
    __nv_bfloat16 *dh, *dl;
    switch (arr) {
        case 0:  src = th_w; dh = wtp0;          dl = wtp1;          break;
        case 1:  src = ph_w; dh = wtp0 + 131072; dl = wtp1 + 131072; break;
        case 2:  src = g_w;  dh = gw0;           dl = gw1;           break;
        default: src = W_w;  dh = ww0;           dl = ww1;           break;
    }
    const float v = src[off];
    const __nv_bfloat16 hh = __float2bfloat16(v);
    dh[off] = hh;
    dl[off] = __float2bfloat16(v - __bfloat162float(hh));

    if (i < 512)  tpb[i]  = (i < 256) ? th_b[i] : ph_b[i - 256];
    if (i < 1024) stats[i] = 0.f;
}

// =====================================================================
// transpose + 2-level split of x
// =====================================================================
__global__ void transpose_split2(const float* __restrict__ x,
                                 __nv_bfloat16* __restrict__ h,
                                 __nv_bfloat16* __restrict__ l)
{
    __shared__ float t[32][33];
    const int b = blockIdx.z;
    const int n0 = blockIdx.x * 32, c0 = blockIdx.y * 32;
    const float* xb = x + (size_t)b * CCH * NPIX;
    #pragma unroll
    for (int k = 0; k < 4; k++) {
        const int c = c0 + threadIdx.y + k * 8;
        t[threadIdx.y + k * 8][threadIdx.x] = xb[(size_t)c * NPIX + n0 + threadIdx.x];
    }
    __syncthreads();
    const size_t ob = (size_t)b * NPIX * CCH;
    #pragma unroll
    for (int k = 0; k < 4; k++) {
        const int n = n0 + threadIdx.y + k * 8;
        const float v = t[threadIdx.x][threadIdx.y + k * 8];
        const size_t idx = ob + (size_t)n * CCH + c0 + threadIdx.x;
        __nv_bfloat16 hh = __float2bfloat16(v);
        h[idx] = hh;
        l[idx] = __float2bfloat16(v - __bfloat162float(hh));
    }
}

__global__ __launch_bounds__(256) void softmax_split(
    const float* __restrict__ fp, __nv_bfloat16* __restrict__ h, __nv_bfloat16* __restrict__ l)
{
    const int row = blockIdx.x;        // b*256 + c
    const int b = row >> 8, c = row & 255;
    const int d = threadIdx.x;
    float v = 0.f;
    #pragma unroll
    for (int s = 0; s < FSPLIT; s++)
        v += fp[((size_t)(b * FSPLIT + s)) * (CI * CI) + c * CI + d];
    __shared__ float red[256];
    red[d] = v; __syncthreads();
    for (int o = 128; o > 0; o >>= 1) {
        if (d < o) red[d] = fmaxf(red[d], red[d + o]);
        __syncthreads();
    }
    const float mx = red[0];
    __syncthreads();
    const float e = __expf(v - mx);
    red[d] = e; __syncthreads();
    for (int o = 128; o > 0; o >>= 1) {
        if (d < o) red[d] += red[d + o];
        __syncthreads();
    }
    const float p = e / red[0];
    const size_t idx = (size_t)row * CI + d;
    __nv_bfloat16 hh = __float2bfloat16(p);
    h[idx] = hh; l[idx] = __float2bfloat16(p - __bfloat162float(hh));
}

// =====================================================================
// BN (finalize folded in) + residual
// =====================================================================
__global__ __launch_bounds__(256) void bn_residual(
    const float* __restrict__ z, const float* __restrict__ x,
    const float* __restrict__ gamma, const float* __restrict__ beta,
    const float* __restrict__ stats, float* __restrict__ out)
{
    const size_t i = (size_t)blockIdx.x * blockDim.x + threadIdx.x;
    const int c = (int)((i >> 10) & (CCH - 1));
    const float cnt = (float)(BATCH * NPIX);
    const float m = stats[c] / cnt;
    const float var = stats[CCH + c] / cnt - m * m;
    const float r = rsqrtf(var + 1e-5f);
    const float g = gamma[c], bb = beta[c];
    const float4 zv = ((const float4*)z)[i];
    const float4 xv = ((const float4*)x)[i];
    float4 o;
    o.x = (zv.x - m) * r * g + bb + xv.x;
    o.y = (zv.y - m) * r * g + bb + xv.y;
    o.z = (zv.z - m) * r * g + bb + xv.z;
    o.w = (zv.w - m) * r * g + bb + xv.w;
    ((float4*)out)[i] = o;
}

// =====================================================================
// launch
// =====================================================================
extern "C" void kernel_launch(void* const* d_in, const int* in_sizes, int n_in,
                              void* d_out, int out_size)
{
    (void)in_sizes; (void)n_in; (void)out_size;
    const float* x     = (const float*)d_in[0];
    const float* g_w   = (const float*)d_in[1];
    const float* g_b   = (const float*)d_in[2];
    const float* th_w  = (const float*)d_in[3];
    const float* th_b  = (const float*)d_in[4];
    const float* ph_w  = (const float*)d_in[5];
    const float* ph_b  = (const float*)d_in[6];
    const float* W_w   = (const float*)d_in[7];
    const float* gamma = (const float*)d_in[9];
    const float* beta  = (const float*)d_in[10];
    float* out = (float*)d_out;

    __nv_bfloat16 *xt, *wtp, *gw, *ww, *tp, *gt, *fsm, *yt;
    float *fpart, *z, *stats, *tpb;
    cudaGetSymbolAddress((void**)&xt,    d_xt);
    cudaGetSymbolAddress((void**)&wtp,   d_wtp);
    cudaGetSymbolAddress((void**)&gw,    d_gw);
    cudaGetSymbolAddress((void**)&ww,    d_ww);
    cudaGetSymbolAddress((void**)&tp,    d_tp);
    cudaGetSymbolAddress((void**)&gt,    d_gt);
    cudaGetSymbolAddress((void**)&fpart, d_fpart);
    cudaGetSymbolAddress((void**)&fsm,   d_fsm);
    cudaGetSymbolAddress((void**)&yt,    d_yt);
    cudaGetSymbolAddress((void**)&z,     d_z);
    cudaGetSymbolAddress((void**)&stats, d_stats);
    cudaGetSymbolAddress((void**)&tpb,   d_tpb);

    __nv_bfloat16 *xt0 = xt, *xt1 = xt + XT_SZ;
    __nv_bfloat16 *wtp0 = wtp, *wtp1 = wtp + 512 * 512;
    __nv_bfloat16 *gw0 = gw, *gw1 = gw + CI * CCH;
    __nv_bfloat16 *ww0 = ww, *ww1 = ww + CCH * CI;
    __nv_bfloat16 *tp0 = tp, *tp1 = tp + TP_SZ;
    __nv_bfloat16 *gt0 = gt, *gt1 = gt + GT_SZ;
    __nv_bfloat16 *fs0 = fsm, *fs1 = fsm + F_SZ;
    __nv_bfloat16 *yt0 = yt, *yt1 = yt + YT_SZ;

    const int SMEM = 3 * 24576 + 1024;   // 3-stage, K-chunk 32: 74752 B -> 3 CTAs/SM
    cudaFuncSetAttribute(mma_nt<0>, cudaFuncAttributeMaxDynamicSharedMemorySize, SMEM);
    cudaFuncSetAttribute(mma_nt<1>, cudaFuncAttributeMaxDynamicSharedMemorySize, SMEM);

    // one prep launch: 4 weight splits + bias stack + stats zero
    prep_splits<<<(4 * 131072) / 256, 256>>>(
        th_w, ph_w, g_w, W_w,
        wtp0, wtp1, gw0, gw1, ww0, ww1,
        th_b, ph_b, tpb, stats);

    // xT 2-level split: (B, 4096, 512)
    transpose_split2<<<dim3(NPIX / 32, CCH / 32, BATCH), dim3(32, 8)>>>(x, xt0, xt1);

    // GEMM1a: tp[b](512,4096) = Wtp(512,512) @ xT[b]^T (+ [th_b;ph_b] per row), hi/lo out
    mma_nt<1><<<dim3(NPIX / 128, 512 / 64, BATCH), 128, SMEM>>>(
        wtp0, wtp1, xt0, xt1,
        nullptr, tp0, tp1, tpb, nullptr, nullptr,
        512, NPIX, CCH, 1, 0, (long long)NPIX * CCH, 512LL * NPIX);

    // GEMM1b: gT[b](4096,256) = xT[b] @ g_w^T (+ g_b per col), hi/lo out
    mma_nt<1><<<dim3(CI / 128, NPIX / 64, BATCH), 128, SMEM>>>(
        xt0, xt1, gw0, gw1,
        nullptr, gt0, gt1, nullptr, g_b, nullptr,
        NPIX, CI, CCH, 1, (long long)NPIX * CCH, 0, (long long)NPIX * CI);

    // GEMM2: f partials = theta @ phi^T, split-K 8, fp32 out
    mma_nt<0><<<dim3(CI / 128, CI / 64, BATCH * FSPLIT), 128, SMEM>>>(
        tp0, tp1,
        tp0 + (size_t)CI * NPIX, tp1 + (size_t)CI * NPIX,
        fpart, nullptr, nullptr, nullptr, nullptr, nullptr,
        CI, CI, NPIX, FSPLIT, 512LL * NPIX, 512LL * NPIX, (long long)CI * CI);

    // softmax (sums FSPLIT partials) -> hi/lo bf16
    softmax_split<<<BATCH * CI, 256>>>(fpart, fs0, fs1);

    // GEMM3: yT[b](4096,256) = gT[b] @ fsm[b]^T, hi/lo out
    mma_nt<1><<<dim3(CI / 128, NPIX / 64, BATCH), 128, SMEM>>>(
        gt0, gt1, fs0, fs1,
        nullptr, yt0, yt1, nullptr, nullptr, nullptr,
        NPIX, CI, CI, 1, (long long)NPIX * CI, (long long)CI * CI, (long long)NPIX * CI);

    // GEMM4: z[b](512,4096) = W_w @ yT[b]^T (W_b dropped: cancels in BN),
    //        fp32 out + fused per-channel stats partials
    mma_nt<0><<<dim3(NPIX / 128, 512 / 64, BATCH), 128, SMEM>>>(
        ww0, ww1, yt0, yt1,
        z, nullptr, nullptr, nullptr, nullptr, stats,
        CCH, NPIX, CI, 1, 0, (long long)NPIX * CI, (long long)CCH * NPIX);

    // BN (finalize folded) + residual
    const size_t total4 = (size_t)BATCH * CCH * NPIX / 4;
    bn_residual<<<(unsigned)(total4 / 256), 256>>>(z, x, gamma, beta, stats, out);
}

// round 10
// speedup vs baseline: 4.5495x; 1.0922x over previous
#include <cuda_runtime.h>
#include <cuda_bf16.h>
#include <cstdint>

#define BATCH 16
#define CCH   512
#define CI    256
#define NPIX  4096
#define FSPLIT 8

// ---------------- scratch (device globals; no allocation allowed) ----------------
static const size_t XT_SZ  = (size_t)BATCH * NPIX * CCH;   // per level
static const size_t TP_SZ  = (size_t)BATCH * 512 * NPIX;
static const size_t GT_SZ  = (size_t)BATCH * NPIX * CI;
static const size_t F_SZ   = (size_t)BATCH * CI * CI;
static const size_t YT_SZ  = (size_t)BATCH * NPIX * CI;

__device__ __nv_bfloat16 d_xt [2][(size_t)BATCH * NPIX * CCH];   // 134 MB
__device__ __nv_bfloat16 d_wtp[2][512 * 512];
__device__ __nv_bfloat16 d_gw [2][CI * CCH];
__device__ __nv_bfloat16 d_ww [2][CCH * CI];
__device__ __nv_bfloat16 d_tp [2][(size_t)BATCH * 512 * NPIX];   // 134 MB
__device__ __nv_bfloat16 d_gt [2][(size_t)BATCH * NPIX * CI];    // 67 MB
__device__ float         d_fpart[(size_t)FSPLIT * BATCH * CI * CI]; // 33.5 MB
__device__ __nv_bfloat16 d_fsm[2][(size_t)BATCH * CI * CI];
__device__ __nv_bfloat16 d_yt [2][(size_t)BATCH * NPIX * CI];    // 67 MB
__device__ float         d_z[(size_t)BATCH * CCH * NPIX];        // 134 MB
__device__ float         d_stats[2 * CCH];                       // raw partials
__device__ float         d_tpb[512];

// ---------------- helpers (arch-portable PTX only: sm_80+) ----------------
__device__ __forceinline__ uint32_t smem_u32(const void* p) {
    uint32_t a;
    asm("{ .reg .u64 t; cvta.to.shared.u64 t, %1; cvt.u32.u64 %0, t; }" : "=r"(a) : "l"(p));
    return a;
}
// SW64 swizzle for 64-byte rows: o ^ ((o>>3)&0x30)
#define SMEM_SWIZZLE_64B(o) ((o) ^ (((o) >> 3) & 0x30))

__device__ __forceinline__ void cpasync16(uint32_t dst, const void* src) {
    asm volatile("cp.async.cg.shared.global [%0], [%1], 16;" :: "r"(dst), "l"(src));
}
#define CP_COMMIT() asm volatile("cp.async.commit_group;" ::: "memory")

__device__ __forceinline__ void ldsm4(uint32_t addr, uint32_t& r0, uint32_t& r1,
                                      uint32_t& r2, uint32_t& r3) {
    asm volatile("ldmatrix.sync.aligned.m8n8.x4.shared.b16 {%0,%1,%2,%3}, [%4];"
                 : "=r"(r0), "=r"(r1), "=r"(r2), "=r"(r3) : "r"(addr));
}
__device__ __forceinline__ void mma16816(float* c, const uint32_t* a, uint32_t b0, uint32_t b1) {
    asm volatile(
        "mma.sync.aligned.m16n8k16.row.col.f32.bf16.bf16.f32 "
        "{%0,%1,%2,%3}, {%4,%5,%6,%7}, {%8,%9}, {%0,%1,%2,%3};"
        : "+f"(c[0]), "+f"(c[1]), "+f"(c[2]), "+f"(c[3])
        : "r"(a[0]), "r"(a[1]), "r"(a[2]), "r"(a[3]), "r"(b0), "r"(b1));
}

// =====================================================================
// NT GEMM on tensor cores (mma.sync bf16, fp32 acc), 2-level split inputs:
//   D[M,N] = A0*B0^T + A0*B1^T + A1*B0^T    (ll term dropped, ~2^-18)
// Shapes are TEMPLATE params -> all address math constant-folded.
// A,B: K-major (ld = Kv). CTA tile 64x128, 128 threads (4 warps, warp tile
// 32x64). K-chunk 32 (64-byte rows, SW64), 3-stage cp.async pipeline,
// 72KB smem -> 3 CTAs/SM. LDSM offsets precomputed (1 ADD per LDSM).
// MODE: 0 = fp32 out (optional fused stats atomics), 1 = hi/lo bf16 out.
// grid = (Nv/128, Mv/64, batch*NSPLIT)
// =====================================================================
template <int MODE, int Mv, int Nv, int Kv, int NSPLIT>
__global__ __launch_bounds__(128, 3) void mma_nt(
    const __nv_bfloat16* __restrict__ a0, const __nv_bfloat16* __restrict__ a1,
    const __nv_bfloat16* __restrict__ b0, const __nv_bfloat16* __restrict__ b1,
    float* __restrict__ cf,
    __nv_bfloat16* __restrict__ c0, __nv_bfloat16* __restrict__ c1,
    const float* __restrict__ biasRow, const float* __restrict__ biasCol,
    float* __restrict__ statsPart,
    long long sA, long long sB, long long sC)
{
    constexpr int stageBytes = 24576;       // A0 4K | A1 4K | B0 8K | B1 8K
    constexpr int Ksub = Kv / NSPLIT;
    constexpr int nk = Ksub / 32;

    extern __shared__ char smraw[];
    const uint32_t smem_base = (smem_u32(smraw) + 1023u) & ~1023u;

    const int tid = threadIdx.x;
    const int wid = tid >> 5, lid = tid & 31;
    const int warpM = (wid & 1) * 32;       // 2 warps over M (64 rows)
    const int warpN = (wid >> 1) * 64;      // 2 warps over N (128 cols)

    const int bz = blockIdx.z;
    const int b  = bz / NSPLIT, sp = bz % NSPLIT;
    const int k0base = sp * Ksub;
    const int mBase = blockIdx.y * 64;
    const int nBase = blockIdx.x * 128;

    const __nv_bfloat16* ta[4];
    ta[0] = a0 + (size_t)b * sA;
    ta[1] = a1 + (size_t)b * sA;
    ta[2] = b0 + (size_t)b * sB;
    ta[3] = b1 + (size_t)b * sB;

    auto loadChunk = [&](int ci, int st) {
        const int k0 = k0base + ci * 32;
        const uint32_t sb = smem_base + st * stageBytes;
        const uint32_t toff[4] = {0u, 4096u, 8192u, 16384u};
        #pragma unroll
        for (int t = 0; t < 4; t++) {
            const int rows = (t < 2) ? 64 : 128;
            const int rb   = (t < 2) ? mBase : nBase;
            const __nv_bfloat16* src = ta[t] + (size_t)rb * Kv + k0;
            const uint32_t tb = sb + toff[t];
            #pragma unroll
            for (int i0 = 0; i0 < rows * 4; i0 += 128) {
                const int i = i0 + tid;
                const int row = i >> 2, seg = i & 3;
                cpasync16(tb + SMEM_SWIZZLE_64B(row * 64 + seg * 16),
                          src + (size_t)row * Kv + seg * 8);
            }
        }
    };

    float acc[2][8][4];
    #pragma unroll
    for (int i = 0; i < 2; i++)
        #pragma unroll
        for (int j = 0; j < 8; j++)
            #pragma unroll
            for (int k = 0; k < 4; k++) acc[i][j][k] = 0.f;

    loadChunk(0, 0); CP_COMMIT();
    loadChunk(1, 1); CP_COMMIT();

    const int lRow = lid & 15;              // ldmatrix row within 16
    const uint32_t colH = ((lid >> 4) & 1) * 16;

    // precomputed FULL ldsm offsets (stage-relative): 1 ADD per LDSM at use
    uint32_t offA[2][2], offB[2][4];        // [ks][site]
    #pragma unroll
    for (int mi = 0; mi < 2; mi++) {
        const int row = warpM + 16 * mi + lRow;
        const uint32_t ba = row * 64, xr = (row & 6) * 8;
        offA[0][mi] = ba + (colH ^ xr);
        offA[1][mi] = ba + ((32 + colH) ^ xr);
    }
    #pragma unroll
    for (int nj = 0; nj < 4; nj++) {
        const int row = warpN + 16 * nj + lRow;
        const uint32_t ba = row * 64, xr = (row & 6) * 8;
        offB[0][nj] = ba + (colH ^ xr);
        offB[1][nj] = ba + ((32 + colH) ^ xr);
    }

#define COMPUTE_KS(KS)                                                          \
    {                                                                           \
        uint32_t fa0[2][4], fa1[2][4], fb0[4][4], fb1[4][4];                    \
        _Pragma("unroll")                                                       \
        for (int mi = 0; mi < 2; mi++) {                                        \
            const uint32_t off = offA[KS][mi];                                  \
            ldsm4(A0b + off, fa0[mi][0], fa0[mi][1], fa0[mi][2], fa0[mi][3]);   \
            ldsm4(A1b + off, fa1[mi][0], fa1[mi][1], fa1[mi][2], fa1[mi][3]);   \
        }                                                                       \
        _Pragma("unroll")                                                       \
        for (int nj = 0; nj < 4; nj++) {                                        \
            const uint32_t off = offB[KS][nj];                                  \
            ldsm4(B0b + off, fb0[nj][0], fb0[nj][1], fb0[nj][2], fb0[nj][3]);   \
            ldsm4(B1b + off, fb1[nj][0], fb1[nj][1], fb1[nj][2], fb1[nj][3]);   \
        }                                                                       \
        _Pragma("unroll")                                                       \
        for (int mi = 0; mi < 2; mi++)                                          \
            _Pragma("unroll")                                                   \
            for (int jn = 0; jn < 8; jn++)                                      \
                mma16816(acc[mi][jn], fa0[mi],                                  \
                         fb0[jn >> 1][jn & 1], fb0[jn >> 1][2 + (jn & 1)]);     \
        _Pragma("unroll")                                                       \
        for (int mi = 0; mi < 2; mi++)                                          \
            _Pragma("unroll")                                                   \
            for (int jn = 0; jn < 8; jn++)                                      \
                mma16816(acc[mi][jn], fa0[mi],                                  \
                         fb1[jn >> 1][jn & 1], fb1[jn >> 1][2 + (jn & 1)]);     \
        _Pragma("unroll")                                                       \
        for (int mi = 0; mi < 2; mi++)                                          \
            _Pragma("unroll")                                                   \
            for (int jn = 0; jn < 8; jn++)                                      \
                mma16816(acc[mi][jn], fa1[mi],                                  \
                         fb0[jn >> 1][jn & 1], fb0[jn >> 1][2 + (jn & 1)]);     \
    }

    #pragma unroll 1
    for (int i = 0; i < nk; i++) {
        const uint32_t sb = smem_base + (i % 3) * stageBytes;
        asm volatile("cp.async.wait_group 1;" ::: "memory");
        __syncthreads();                    // chunk i resident; all done with i-1

        const uint32_t A0b = sb, A1b = sb + 4096;
        const uint32_t B0b = sb + 8192, B1b = sb + 16384;

        COMPUTE_KS(0);
        if (i + 2 < nk) { loadChunk(i + 2, (i + 2) % 3); CP_COMMIT(); }
        COMPUTE_KS(1);
    }
#undef COMPUTE_KS

    // ---- epilogue ----
    const int gr = lid >> 2;            // 0..7
    const int gc = (lid & 3) * 2;       // 0,2,4,6
    const size_t cOff = (size_t)bz * sC;

    #pragma unroll
    for (int mi = 0; mi < 2; mi++) {
        const int row0 = mBase + warpM + 16 * mi + gr;
        const int row1 = row0 + 8;
        const float br0 = biasRow ? biasRow[row0] : 0.f;
        const float br1 = biasRow ? biasRow[row1] : 0.f;
        float s0 = 0.f, q0 = 0.f, s1 = 0.f, q1 = 0.f;
        #pragma unroll
        for (int jn = 0; jn < 8; jn++) {
            const int col = nBase + warpN + 8 * jn + gc;
            float v00 = acc[mi][jn][0] + br0;
            float v01 = acc[mi][jn][1] + br0;
            float v10 = acc[mi][jn][2] + br1;
            float v11 = acc[mi][jn][3] + br1;
            if (biasCol) {
                const float bc0 = biasCol[col], bc1 = biasCol[col + 1];
                v00 += bc0; v01 += bc1; v10 += bc0; v11 += bc1;
            }
            const size_t base0 = cOff + (size_t)row0 * Nv + col;
            const size_t base1 = cOff + (size_t)row1 * Nv + col;
            if (MODE == 0) {
                *(float2*)(cf + base0) = make_float2(v00, v01);
                *(float2*)(cf + base1) = make_float2(v10, v11);
                if (statsPart) {
                    s0 += v00 + v01; q0 += v00 * v00 + v01 * v01;
                    s1 += v10 + v11; q1 += v10 * v10 + v11 * v11;
                }
            } else {
                float vv[2][2] = {{v00, v01}, {v10, v11}};
                const size_t bb[2] = {base0, base1};
                #pragma unroll
                for (int r = 0; r < 2; r++) {
                    __nv_bfloat16 h0 = __float2bfloat16(vv[r][0]);
                    __nv_bfloat16 h1 = __float2bfloat16(vv[r][1]);
                    float r0 = vv[r][0] - __bfloat162float(h0);
                    float r1 = vv[r][1] - __bfloat162float(h1);
                    __nv_bfloat162 th; th.x = h0; th.y = h1;
                    __nv_bfloat162 tl;
                    tl.x = __float2bfloat16(r0); tl.y = __float2bfloat16(r1);
                    *(__nv_bfloat162*)(c0 + bb[r]) = th;
                    *(__nv_bfloat162*)(c1 + bb[r]) = tl;
                }
            }
        }
        if (MODE == 0 && statsPart) {
            #pragma unroll
            for (int o = 1; o < 4; o <<= 1) {
                s0 += __shfl_xor_sync(0xFFFFFFFFu, s0, o);
                q0 += __shfl_xor_sync(0xFFFFFFFFu, q0, o);
                s1 += __shfl_xor_sync(0xFFFFFFFFu, s1, o);
                q1 += __shfl_xor_sync(0xFFFFFFFFu, q1, o);
            }
            if ((lid & 3) == 0) {
                atomicAdd(&statsPart[row0], s0);
                atomicAdd(&statsPart[CCH + row0], q0);
                atomicAdd(&statsPart[row1], s1);
                atomicAdd(&statsPart[CCH + row1], q1);
            }
        }
    }
}

// =====================================================================
// prep: all four weight splits + bias stack + stats zero (ONE launch)
// =====================================================================
__global__ void prep_splits(
    const float* __restrict__ th_w, const float* __restrict__ ph_w,
    const float* __restrict__ g_w,  const float* __restrict__ W_w,
    __nv_bfloat16* __restrict__ wtp0, __nv_bfloat16* __restrict__ wtp1,
    __nv_bfloat16* __restrict__ gw0,  __nv_bfloat16* __restrict__ gw1,
    __nv_bfloat16* __restrict__ ww0,  __nv_bfloat16* __restrict__ ww1,
    const float* __restrict__ th_b, const float* __restrict__ ph_b,
    float* __restrict__ tpb, float* __restrict__ stats)
{
    const int i = blockIdx.x * 256 + threadIdx.x;   // 0 .. 4*131072-1
    const int arr = i >> 17;
    const int off = i & 131071;
    const float* src;
    __nv_bfloat16 *dh, *dl;
    switch (arr) {
        case 0:  src = th_w; dh = wtp0;          dl = wtp1;          break;
        case 1:  src = ph_w; dh = wtp0 + 131072; dl = wtp1 + 131072; break;
        case 2:  src = g_w;  dh = gw0;           dl = gw1;           break;
        default: src = W_w;  dh = ww0;           dl = ww1;           break;
    }
    const float v = src[off];
    const __nv_bfloat16 hh = __float2bfloat16(v);
    dh[off] = hh;
    dl[off] = __float2bfloat16(v - __bfloat162float(hh));

    if (i < 512)  tpb[i]  = (i < 256) ? th_b[i] : ph_b[i - 256];
    if (i < 1024) stats[i] = 0.f;
}

// =====================================================================
// transpose + 2-level split of x
// =====================================================================
__global__ void transpose_split2(const float* __restrict__ x,
                                 __nv_bfloat16* __restrict__ h,
                                 __nv_bfloat16* __restrict__ l)
{
    __shared__ float t[32][33];
    const int b = blockIdx.z;
    const int n0 = blockIdx.x * 32, c0 = blockIdx.y * 32;
    const float* xb = x + (size_t)b * CCH * NPIX;
    #pragma unroll
    for (int k = 0; k < 4; k++) {
        const int c = c0 + threadIdx.y + k * 8;
        t[threadIdx.y + k * 8][threadIdx.x] = xb[(size_t)c * NPIX + n0 + threadIdx.x];
    }
    __syncthreads();
    const size_t ob = (size_t)b * NPIX * CCH;
    #pragma unroll
    for (int k = 0; k < 4; k++) {
        const int n = n0 + threadIdx.y + k * 8;
        const float v = t[threadIdx.x][threadIdx.y + k * 8];
        const size_t idx = ob + (size_t)n * CCH + c0 + threadIdx.x;
        __nv_bfloat16 hh = __float2bfloat16(v);
        h[idx] = hh;
        l[idx] = __float2bfloat16(v - __bfloat162float(hh));
    }
}

__global__ __launch_bounds__(256) void softmax_split(
    const float* __restrict__ fp, __nv_bfloat16* __restrict__ h, __nv_bfloat16* __restrict__ l)
{
    const int row = blockIdx.x;        // b*256 + c
    const int b = row >> 8, c = row & 255;
    const int d = threadIdx.x;
    float v = 0.f;
    #pragma unroll
    for (int s = 0; s < FSPLIT; s++)
        v += fp[((size_t)(b * FSPLIT + s)) * (CI * CI) + c * CI + d];
    __shared__ float red[256];
    red[d] = v; __syncthreads();
    for (int o = 128; o > 0; o >>= 1) {
        if (d < o) red[d] = fmaxf(red[d], red[d + o]);
        __syncthreads();
    }
    const float mx = red[0];
    __syncthreads();
    const float e = __expf(v - mx);
    red[d] = e; __syncthreads();
    for (int o = 128; o > 0; o >>= 1) {
        if (d < o) red[d] += red[d + o];
        __syncthreads();
    }
    const float p = e / red[0];
    const size_t idx = (size_t)row * CI + d;
    __nv_bfloat16 hh = __float2bfloat16(p);
    h[idx] = hh; l[idx] = __float2bfloat16(p - __bfloat162float(hh));
}

// =====================================================================
// BN (finalize folded in) + residual
// =====================================================================
__global__ __launch_bounds__(256) void bn_residual(
    const float* __restrict__ z, const float* __restrict__ x,
    const float* __restrict__ gamma, const float* __restrict__ beta,
    const float* __restrict__ stats, float* __restrict__ out)
{
    const size_t i = (size_t)blockIdx.x * blockDim.x + threadIdx.x;
    const int c = (int)((i >> 10) & (CCH - 1));
    const float cnt = (float)(BATCH * NPIX);
    const float m = stats[c] / cnt;
    const float var = stats[CCH + c] / cnt - m * m;
    const float r = rsqrtf(var + 1e-5f);
    const float g = gamma[c], bb = beta[c];
    const float4 zv = ((const float4*)z)[i];
    const float4 xv = ((const float4*)x)[i];
    float4 o;
    o.x = (zv.x - m) * r * g + bb + xv.x;
    o.y = (zv.y - m) * r * g + bb + xv.y;
    o.z = (zv.z - m) * r * g + bb + xv.z;
    o.w = (zv.w - m) * r * g + bb + xv.w;
    ((float4*)out)[i] = o;
}

// =====================================================================
// launch
// =====================================================================
extern "C" void kernel_launch(void* const* d_in, const int* in_sizes, int n_in,
                              void* d_out, int out_size)
{
    (void)in_sizes; (void)n_in; (void)out_size;
    const float* x     = (const float*)d_in[0];
    const float* g_w   = (const float*)d_in[1];
    const float* g_b   = (const float*)d_in[2];
    const float* th_w  = (const float*)d_in[3];
    const float* th_b  = (const float*)d_in[4];
    const float* ph_w  = (const float*)d_in[5];
    const float* ph_b  = (const float*)d_in[6];
    const float* W_w   = (const float*)d_in[7];
    const float* gamma = (const float*)d_in[9];
    const float* beta  = (const float*)d_in[10];
    float* out = (float*)d_out;

    __nv_bfloat16 *xt, *wtp, *gw, *ww, *tp, *gt, *fsm, *yt;
    float *fpart, *z, *stats, *tpb;
    cudaGetSymbolAddress((void**)&xt,    d_xt);
    cudaGetSymbolAddress((void**)&wtp,   d_wtp);
    cudaGetSymbolAddress((void**)&gw,    d_gw);
    cudaGetSymbolAddress((void**)&ww,    d_ww);
    cudaGetSymbolAddress((void**)&tp,    d_tp);
    cudaGetSymbolAddress((void**)&gt,    d_gt);
    cudaGetSymbolAddress((void**)&fpart, d_fpart);
    cudaGetSymbolAddress((void**)&fsm,   d_fsm);
    cudaGetSymbolAddress((void**)&yt,    d_yt);
    cudaGetSymbolAddress((void**)&z,     d_z);
    cudaGetSymbolAddress((void**)&stats, d_stats);
    cudaGetSymbolAddress((void**)&tpb,   d_tpb);

    __nv_bfloat16 *xt0 = xt, *xt1 = xt + XT_SZ;
    __nv_bfloat16 *wtp0 = wtp, *wtp1 = wtp + 512 * 512;
    __nv_bfloat16 *gw0 = gw, *gw1 = gw + CI * CCH;
    __nv_bfloat16 *ww0 = ww, *ww1 = ww + CCH * CI;
    __nv_bfloat16 *tp0 = tp, *tp1 = tp + TP_SZ;
    __nv_bfloat16 *gt0 = gt, *gt1 = gt + GT_SZ;
    __nv_bfloat16 *fs0 = fsm, *fs1 = fsm + F_SZ;
    __nv_bfloat16 *yt0 = yt, *yt1 = yt + YT_SZ;

    const int SMEM = 3 * 24576 + 1024;   // 3-stage, K-chunk 32: 74752 B -> 3 CTAs/SM

    auto* k1a = mma_nt<1, 512,  NPIX, CCH, 1>;
    auto* k1b = mma_nt<1, NPIX, CI,   CCH, 1>;
    auto* k2  = mma_nt<0, CI,   CI,   NPIX, FSPLIT>;
    auto* k3  = mma_nt<1, NPIX, CI,   CI,  1>;
    auto* k4  = mma_nt<0, 512,  NPIX, CI,  1>;
    cudaFuncSetAttribute(k1a, cudaFuncAttributeMaxDynamicSharedMemorySize, SMEM);
    cudaFuncSetAttribute(k1b, cudaFuncAttributeMaxDynamicSharedMemorySize, SMEM);
    cudaFuncSetAttribute(k2,  cudaFuncAttributeMaxDynamicSharedMemorySize, SMEM);
    cudaFuncSetAttribute(k3,  cudaFuncAttributeMaxDynamicSharedMemorySize, SMEM);
    cudaFuncSetAttribute(k4,  cudaFuncAttributeMaxDynamicSharedMemorySize, SMEM);

    // one prep launch: 4 weight splits + bias stack + stats zero
    prep_splits<<<(4 * 131072) / 256, 256>>>(
        th_w, ph_w, g_w, W_w,
        wtp0, wtp1, gw0, gw1, ww0, ww1,
        th_b, ph_b, tpb, stats);

    // xT 2-level split: (B, 4096, 512)
    transpose_split2<<<dim3(NPIX / 32, CCH / 32, BATCH), dim3(32, 8)>>>(x, xt0, xt1);

    // GEMM1a: tp[b](512,4096) = Wtp(512,512) @ xT[b]^T (+ [th_b;ph_b] per row), hi/lo out
    k1a<<<dim3(NPIX / 128, 512 / 64, BATCH), 128, SMEM>>>(
        wtp0, wtp1, xt0, xt1,
        nullptr, tp0, tp1, tpb, nullptr, nullptr,
        0, (long long)NPIX * CCH, 512LL * NPIX);

    // GEMM1b: gT[b](4096,256) = xT[b] @ g_w^T (+ g_b per col), hi/lo out
    k1b<<<dim3(CI / 128, NPIX / 64, BATCH), 128, SMEM>>>(
        xt0, xt1, gw0, gw1,
        nullptr, gt0, gt1, nullptr, g_b, nullptr,
        (long long)NPIX * CCH, 0, (long long)NPIX * CI);

    // GEMM2: f partials = theta @ phi^T, split-K 8, fp32 out
    k2<<<dim3(CI / 128, CI / 64, BATCH * FSPLIT), 128, SMEM>>>(
        tp0, tp1,
        tp0 + (size_t)CI * NPIX, tp1 + (size_t)CI * NPIX,
        fpart, nullptr, nullptr, nullptr, nullptr, nullptr,
        512LL * NPIX, 512LL * NPIX, (long long)CI * CI);

    // softmax (sums FSPLIT partials) -> hi/lo bf16
    softmax_split<<<BATCH * CI, 256>>>(fpart, fs0, fs1);

    // GEMM3: yT[b](4096,256) = gT[b] @ fsm[b]^T, hi/lo out
    k3<<<dim3(CI / 128, NPIX / 64, BATCH), 128, SMEM>>>(
        gt0, gt1, fs0, fs1,
        nullptr, yt0, yt1, nullptr, nullptr, nullptr,
        (long long)NPIX * CI, (long long)CI * CI, (long long)NPIX * CI);

    // GEMM4: z[b](512,4096) = W_w @ yT[b]^T (W_b dropped: cancels in BN),
    //        fp32 out + fused per-channel stats partials
    k4<<<dim3(NPIX / 128, 512 / 64, BATCH), 128, SMEM>>>(
        ww0, ww1, yt0, yt1,
        z, nullptr, nullptr, nullptr, nullptr, stats,
        0, (long long)NPIX * CI, (long long)CCH * NPIX);

    // BN (finalize folded) + residual
    const size_t total4 = (size_t)BATCH * CCH * NPIX / 4;
    bn_residual<<<(unsigned)(total4 / 256), 256>>>(z, x, gamma, beta, stats, out);
}

// round 11
// speedup vs baseline: 4.7045x; 1.0341x over previous
#include <cuda_runtime.h>
#include <cuda_bf16.h>
#include <cstdint>

#define BATCH 16
#define CCH   512
#define CI    256
#define NPIX  4096
#define FSPLIT 8

// ---------------- scratch (device globals; no allocation allowed) ----------------
static const size_t XT_SZ  = (size_t)BATCH * NPIX * CCH;   // per level
static const size_t TP_SZ  = (size_t)BATCH * 512 * NPIX;
static const size_t GT_SZ  = (size_t)BATCH * NPIX * CI;
static const size_t F_SZ   = (size_t)BATCH * CI * CI;
static const size_t YT_SZ  = (size_t)BATCH * NPIX * CI;

__device__ __nv_bfloat16 d_xt [2][(size_t)BATCH * NPIX * CCH];   // 134 MB
__device__ __nv_bfloat16 d_wtp[2][512 * 512];
__device__ __nv_bfloat16 d_gw [2][CI * CCH];
__device__ __nv_bfloat16 d_ww [2][CCH * CI];
__device__ __nv_bfloat16 d_tp [2][(size_t)BATCH * 512 * NPIX];   // 134 MB
__device__ __nv_bfloat16 d_gt [2][(size_t)BATCH * NPIX * CI];    // 67 MB
__device__ float         d_fpart[(size_t)FSPLIT * BATCH * CI * CI]; // 33.5 MB
__device__ __nv_bfloat16 d_fsm[2][(size_t)BATCH * CI * CI];
__device__ __nv_bfloat16 d_yt [2][(size_t)BATCH * NPIX * CI];    // 67 MB
__device__ float         d_z[(size_t)BATCH * CCH * NPIX];        // 134 MB
__device__ float         d_stats[2 * CCH];                       // raw partials
__device__ float         d_tpb[512];

// ---------------- helpers (arch-portable PTX only: sm_80+) ----------------
__device__ __forceinline__ uint32_t smem_u32(const void* p) {
    uint32_t a;
    asm("{ .reg .u64 t; cvta.to.shared.u64 t, %1; cvt.u32.u64 %0, t; }" : "=r"(a) : "l"(p));
    return a;
}

__device__ __forceinline__ void cpasync16(uint32_t dst, const void* src) {
    asm volatile("cp.async.cg.shared.global [%0], [%1], 16;" :: "r"(dst), "l"(src));
}
#define CP_COMMIT() asm volatile("cp.async.commit_group;" ::: "memory")

__device__ __forceinline__ void ldsm4(uint32_t addr, uint32_t& r0, uint32_t& r1,
                                      uint32_t& r2, uint32_t& r3) {
    asm volatile("ldmatrix.sync.aligned.m8n8.x4.shared.b16 {%0,%1,%2,%3}, [%4];"
                 : "=r"(r0), "=r"(r1), "=r"(r2), "=r"(r3) : "r"(addr));
}
__device__ __forceinline__ void mma16816(float* c, const uint32_t* a, uint32_t b0, uint32_t b1) {
    asm volatile(
        "mma.sync.aligned.m16n8k16.row.col.f32.bf16.bf16.f32 "
        "{%0,%1,%2,%3}, {%4,%5,%6,%7}, {%8,%9}, {%0,%1,%2,%3};"
        : "+f"(c[0]), "+f"(c[1]), "+f"(c[2]), "+f"(c[3])
        : "r"(a[0]), "r"(a[1]), "r"(a[2]), "r"(a[3]), "r"(b0), "r"(b1));
}

// =====================================================================
// NT GEMM on tensor cores (mma.sync bf16, fp32 acc), 2-level split inputs:
//   D[M,N] = A0*B0^T + A0*B1^T + A1*B0^T    (ll term dropped, ~2^-18)
// Shapes are TEMPLATE params. A,B: K-major (ld = Kv). CTA tile 64x128,
// 128 threads (4 warps, warp tile 32x64). K-chunk 32 (64B rows, SW64),
// 3-stage cp.async pipeline, 72KB smem -> 3 CTAs/SM.
// ALL load/ldsm addressing precomputed in the prologue; the hot loop
// issues cp.async/ldsm from base+const only.
// MODE: 0 = fp32 out (optional fused stats atomics), 1 = hi/lo bf16 out.
// grid = (Nv/128, Mv/64, batch*NSPLIT)
// =====================================================================
template <int MODE, int Mv, int Nv, int Kv, int NSPLIT>
__global__ __launch_bounds__(128, 3) void mma_nt(
    const __nv_bfloat16* __restrict__ a0, const __nv_bfloat16* __restrict__ a1,
    const __nv_bfloat16* __restrict__ b0, const __nv_bfloat16* __restrict__ b1,
    float* __restrict__ cf,
    __nv_bfloat16* __restrict__ c0, __nv_bfloat16* __restrict__ c1,
    const float* __restrict__ biasRow, const float* __restrict__ biasCol,
    float* __restrict__ statsPart,
    long long sA, long long sB, long long sC)
{
    constexpr int stageBytes = 24576;       // A0 4K | A1 4K | B0 8K | B1 8K
    constexpr int Ksub = Kv / NSPLIT;
    constexpr int nk = Ksub / 32;

    extern __shared__ char smraw[];
    const uint32_t smem_base = (smem_u32(smraw) + 1023u) & ~1023u;

    const int tid = threadIdx.x;
    const int wid = tid >> 5, lid = tid & 31;
    const int warpM = (wid & 1) * 32;       // 2 warps over M (64 rows)
    const int warpN = (wid >> 1) * 64;      // 2 warps over N (128 cols)

    const int bz = blockIdx.z;
    const int b  = bz / NSPLIT, sp = bz % NSPLIT;
    const int k0base = sp * Ksub;
    const int mBase = blockIdx.y * 64;
    const int nBase = blockIdx.x * 128;

    // ---- precomputed cp.async addressing (prologue only) ----
    const int row0 = tid >> 2;              // 0..31
    const int segE = (tid & 3) * 8;         // element offset within 32-elem row chunk
    const __nv_bfloat16* srcA0 = a0 + (size_t)b * sA + (size_t)(mBase + row0) * Kv + k0base + segE;
    const __nv_bfloat16* srcA1 = a1 + (size_t)b * sA + (size_t)(mBase + row0) * Kv + k0base + segE;
    const __nv_bfloat16* srcB0 = b0 + (size_t)b * sB + (size_t)(nBase + row0) * Kv + k0base + segE;
    const __nv_bfloat16* srcB1 = b1 + (size_t)b * sB + (size_t)(nBase + row0) * Kv + k0base + segE;
    uint32_t dstO[4];                       // swizzled dst offsets, tile-local
    #pragma unroll
    for (int c = 0; c < 4; c++) {
        const int row = row0 + 32 * c;
        const uint32_t o = row * 64 + (tid & 3) * 16;
        dstO[c] = o ^ ((row & 6) * 8);      // SW64 swizzle, precomputed
    }

    auto loadChunk = [&](int ci, uint32_t sb) {
        const __nv_bfloat16* s0 = srcA0 + (size_t)ci * 32;
        const __nv_bfloat16* s1 = srcA1 + (size_t)ci * 32;
        const __nv_bfloat16* s2 = srcB0 + (size_t)ci * 32;
        const __nv_bfloat16* s3 = srcB1 + (size_t)ci * 32;
        #pragma unroll
        for (int c = 0; c < 2; c++) {       // A tiles: 64 rows
            cpasync16(sb + dstO[c],         s0 + (size_t)c * 32 * Kv);
            cpasync16(sb + 4096 + dstO[c],  s1 + (size_t)c * 32 * Kv);
        }
        #pragma unroll
        for (int c = 0; c < 4; c++) {       // B tiles: 128 rows
            cpasync16(sb + 8192 + dstO[c],  s2 + (size_t)c * 32 * Kv);
            cpasync16(sb + 16384 + dstO[c], s3 + (size_t)c * 32 * Kv);
        }
    };

    float acc[2][8][4];
    #pragma unroll
    for (int i = 0; i < 2; i++)
        #pragma unroll
        for (int j = 0; j < 8; j++)
            #pragma unroll
            for (int k = 0; k < 4; k++) acc[i][j][k] = 0.f;

    // rotating stage bases (no modulo in the loop)
    uint32_t sbs0 = smem_base, sbs1 = smem_base + stageBytes, sbs2 = smem_base + 2 * stageBytes;

    loadChunk(0, sbs0); CP_COMMIT();
    loadChunk(1, sbs1); CP_COMMIT();

    const int lRow = lid & 15;              // ldmatrix row within 16
    const uint32_t colH = ((lid >> 4) & 1) * 16;

    // precomputed FULL ldsm offsets (stage-relative): 1 ADD per LDSM at use
    uint32_t offA[2][2], offB[2][4];        // [ks][site]
    #pragma unroll
    for (int mi = 0; mi < 2; mi++) {
        const int row = warpM + 16 * mi + lRow;
        const uint32_t ba = row * 64, xr = (row & 6) * 8;
        offA[0][mi] = ba + (colH ^ xr);
        offA[1][mi] = ba + ((32 + colH) ^ xr);
    }
    #pragma unroll
    for (int nj = 0; nj < 4; nj++) {
        const int row = warpN + 16 * nj + lRow;
        const uint32_t ba = row * 64, xr = (row & 6) * 8;
        offB[0][nj] = ba + (colH ^ xr);
        offB[1][nj] = ba + ((32 + colH) ^ xr);
    }

#define COMPUTE_KS(KS)                                                          \
    {                                                                           \
        uint32_t fa0[2][4], fa1[2][4], fb0[4][4], fb1[4][4];                    \
        _Pragma("unroll")                                                       \
        for (int mi = 0; mi < 2; mi++) {                                        \
            const uint32_t off = offA[KS][mi];                                  \
            ldsm4(A0b + off, fa0[mi][0], fa0[mi][1], fa0[mi][2], fa0[mi][3]);   \
            ldsm4(A1b + off, fa1[mi][0], fa1[mi][1], fa1[mi][2], fa1[mi][3]);   \
        }                                                                       \
        _Pragma("unroll")                                                       \
        for (int nj = 0; nj < 4; nj++) {                                        \
            const uint32_t off = offB[KS][nj];                                  \
            ldsm4(B0b + off, fb0[nj][0], fb0[nj][1], fb0[nj][2], fb0[nj][3]);   \
            ldsm4(B1b + off, fb1[nj][0], fb1[nj][1], fb1[nj][2], fb1[nj][3]);   \
        }                                                                       \
        _Pragma("unroll")                                                       \
        for (int mi = 0; mi < 2; mi++)                                          \
            _Pragma("unroll")                                                   \
            for (int jn = 0; jn < 8; jn++)                                      \
                mma16816(acc[mi][jn], fa0[mi],                                  \
                         fb0[jn >> 1][jn & 1], fb0[jn >> 1][2 + (jn & 1)]);     \
        _Pragma("unroll")                                                       \
        for (int mi = 0; mi < 2; mi++)                                          \
            _Pragma("unroll")                                                   \
            for (int jn = 0; jn < 8; jn++)                                      \
                mma16816(acc[mi][jn], fa0[mi],                                  \
                         fb1[jn >> 1][jn & 1], fb1[jn >> 1][2 + (jn & 1)]);     \
        _Pragma("unroll")                                                       \
        for (int mi = 0; mi < 2; mi++)                                          \
            _Pragma("unroll")                                                   \
            for (int jn = 0; jn < 8; jn++)                                      \
                mma16816(acc[mi][jn], fa1[mi],                                  \
                         fb0[jn >> 1][jn & 1], fb0[jn >> 1][2 + (jn & 1)]);     \
    }

    #pragma unroll 1
    for (int i = 0; i < nk; i++) {
        asm volatile("cp.async.wait_group 1;" ::: "memory");
        __syncthreads();                    // chunk i resident; all done with i-1

        const uint32_t A0b = sbs0, A1b = sbs0 + 4096;
        const uint32_t B0b = sbs0 + 8192, B1b = sbs0 + 16384;

        COMPUTE_KS(0);
        if (i + 2 < nk) { loadChunk(i + 2, sbs2); CP_COMMIT(); }
        COMPUTE_KS(1);

        const uint32_t t = sbs0; sbs0 = sbs1; sbs1 = sbs2; sbs2 = t;   // rotate
    }
#undef COMPUTE_KS

    // ---- epilogue ----
    const int gr = lid >> 2;            // 0..7
    const int gc = (lid & 3) * 2;       // 0,2,4,6
    const size_t cOff = (size_t)bz * sC;

    #pragma unroll
    for (int mi = 0; mi < 2; mi++) {
        const int row0e = mBase + warpM + 16 * mi + gr;
        const int row1e = row0e + 8;
        const float br0 = biasRow ? biasRow[row0e] : 0.f;
        const float br1 = biasRow ? biasRow[row1e] : 0.f;
        float s0 = 0.f, q0 = 0.f, s1 = 0.f, q1 = 0.f;
        #pragma unroll
        for (int jn = 0; jn < 8; jn++) {
            const int col = nBase + warpN + 8 * jn + gc;
            float v00 = acc[mi][jn][0] + br0;
            float v01 = acc[mi][jn][1] + br0;
            float v10 = acc[mi][jn][2] + br1;
            float v11 = acc[mi][jn][3] + br1;
            if (biasCol) {
                const float bc0 = biasCol[col], bc1 = biasCol[col + 1];
                v00 += bc0; v01 += bc1; v10 += bc0; v11 += bc1;
            }
            const size_t base0 = cOff + (size_t)row0e * Nv + col;
            const size_t base1 = cOff + (size_t)row1e * Nv + col;
            if (MODE == 0) {
                *(float2*)(cf + base0) = make_float2(v00, v01);
                *(float2*)(cf + base1) = make_float2(v10, v11);
                if (statsPart) {
                    s0 += v00 + v01; q0 += v00 * v00 + v01 * v01;
                    s1 += v10 + v11; q1 += v10 * v10 + v11 * v11;
                }
            } else {
                float vv[2][2] = {{v00, v01}, {v10, v11}};
                const size_t bb[2] = {base0, base1};
                #pragma unroll
                for (int r = 0; r < 2; r++) {
                    __nv_bfloat16 h0 = __float2bfloat16(vv[r][0]);
                    __nv_bfloat16 h1 = __float2bfloat16(vv[r][1]);
                    float r0 = vv[r][0] - __bfloat162float(h0);
                    float r1 = vv[r][1] - __bfloat162float(h1);
                    __nv_bfloat162 th; th.x = h0; th.y = h1;
                    __nv_bfloat162 tl;
                    tl.x = __float2bfloat16(r0); tl.y = __float2bfloat16(r1);
                    *(__nv_bfloat162*)(c0 + bb[r]) = th;
                    *(__nv_bfloat162*)(c1 + bb[r]) = tl;
                }
            }
        }
        if (MODE == 0 && statsPart) {
            #pragma unroll
            for (int o = 1; o < 4; o <<= 1) {
                s0 += __shfl_xor_sync(0xFFFFFFFFu, s0, o);
                q0 += __shfl_xor_sync(0xFFFFFFFFu, q0, o);
                s1 += __shfl_xor_sync(0xFFFFFFFFu, s1, o);
                q1 += __shfl_xor_sync(0xFFFFFFFFu, q1, o);
            }
            if ((lid & 3) == 0) {
                atomicAdd(&statsPart[row0e], s0);
                atomicAdd(&statsPart[CCH + row0e], q0);
                atomicAdd(&statsPart[row1e], s1);
                atomicAdd(&statsPart[CCH + row1e], q1);
            }
        }
    }
}

// =====================================================================
// prep: all four weight splits + bias stack + stats zero (ONE launch)
// =====================================================================
__global__ void prep_splits(
    const float* __restrict__ th_w, const float* __restrict__ ph_w,
    const float* __restrict__ g_w,  const float* __restrict__ W_w,
    __nv_bfloat16* __restrict__ wtp0, __nv_bfloat16* __restrict__ wtp1,
    __nv_bfloat16* __restrict__ gw0,  __nv_bfloat16* __restrict__ gw1,
    __nv_bfloat16* __restrict__ ww0,  __nv_bfloat16* __restrict__ ww1,
    const float* __restrict__ th_b, const float* __restrict__ ph_b,
    float* __restrict__ tpb, float* __restrict__ stats)
{
    const int i = blockIdx.x * 256 + threadIdx.x;   // 0 .. 4*131072-1
    const int arr = i >> 17;
    const int off = i & 131071;
    const float* src;
    __nv_bfloat16 *dh, *dl;
    switch (arr) {
        case 0:  src = th_w; dh = wtp0;          dl = wtp1;          break;
        case 1:  src = ph_w; dh = wtp0 + 131072; dl = wtp1 + 131072; break;
        case 2:  src = g_w;  dh = gw0;           dl = gw1;           break;
        default: src = W_w;  dh = ww0;           dl = ww1;           break;
    }
    const float v = src[off];
    const __nv_bfloat16 hh = __float2bfloat16(v);
    dh[off] = hh;
    dl[off] = __float2bfloat16(v - __bfloat162float(hh));

    if (i < 512)  tpb[i]  = (i < 256) ? th_b[i] : ph_b[i - 256];
    if (i < 1024) stats[i] = 0.f;
}

// =====================================================================
// transpose + 2-level split of x
// =====================================================================
__global__ void transpose_split2(const float* __restrict__ x,
                                 __nv_bfloat16* __restrict__ h,
                                 __nv_bfloat16* __restrict__ l)
{
    __shared__ float t[32][33];
    const int b = blockIdx.z;
    const int n0 = blockIdx.x * 32, c0 = blockIdx.y * 32;
    const float* xb = x + (size_t)b * CCH * NPIX;
    #pragma unroll
    for (int k = 0; k < 4; k++) {
        const int c = c0 + threadIdx.y + k * 8;
        t[threadIdx.y + k * 8][threadIdx.x] = xb[(size_t)c * NPIX + n0 + threadIdx.x];
    }
    __syncthreads();
    const size_t ob = (size_t)b * NPIX * CCH;
    #pragma unroll
    for (int k = 0; k < 4; k++) {
        const int n = n0 + threadIdx.y + k * 8;
        const float v = t[threadIdx.x][threadIdx.y + k * 8];
        const size_t idx = ob + (size_t)n * CCH + c0 + threadIdx.x;
        __nv_bfloat16 hh = __float2bfloat16(v);
        h[idx] = hh;
        l[idx] = __float2bfloat16(v - __bfloat162float(hh));
    }
}

__global__ __launch_bounds__(256) void softmax_split(
    const float* __restrict__ fp, __nv_bfloat16* __restrict__ h, __nv_bfloat16* __restrict__ l)
{
    const int row = blockIdx.x;        // b*256 + c
    const int b = row >> 8, c = row & 255;
    const int d = threadIdx.x;
    float v = 0.f;
    #pragma unroll
    for (int s = 0; s < FSPLIT; s++)
        v += fp[((size_t)(b * FSPLIT + s)) * (CI * CI) + c * CI + d];
    __shared__ float red[256];
    red[d] = v; __syncthreads();
    for (int o = 128; o > 0; o >>= 1) {
        if (d < o) red[d] = fmaxf(red[d], red[d + o]);
        __syncthreads();
    }
    const float mx = red[0];
    __syncthreads();
    const float e = __expf(v - mx);
    red[d] = e; __syncthreads();
    for (int o = 128; o > 0; o >>= 1) {
        if (d < o) red[d] += red[d + o];
        __syncthreads();
    }
    const float p = e / red[0];
    const size_t idx = (size_t)row * CI + d;
    __nv_bfloat16 hh = __float2bfloat16(p);
    h[idx] = hh; l[idx] = __float2bfloat16(p - __bfloat162float(hh));
}

// =====================================================================
// BN (finalize folded in) + residual
// =====================================================================
__global__ __launch_bounds__(256) void bn_residual(
    const float* __restrict__ z, const float* __restrict__ x,
    const float* __restrict__ gamma, const float* __restrict__ beta,
    const float* __restrict__ stats, float* __restrict__ out)
{
    const size_t i = (size_t)blockIdx.x * blockDim.x + threadIdx.x;
    const int c = (int)((i >> 10) & (CCH - 1));
    const float cnt = (float)(BATCH * NPIX);
    const float m = stats[c] / cnt;
    const float var = stats[CCH + c] / cnt - m * m;
    const float r = rsqrtf(var + 1e-5f);
    const float g = gamma[c], bb = beta[c];
    const float4 zv = ((const float4*)z)[i];
    const float4 xv = ((const float4*)x)[i];
    float4 o;
    o.x = (zv.x - m) * r * g + bb + xv.x;
    o.y = (zv.y - m) * r * g + bb + xv.y;
    o.z = (zv.z - m) * r * g + bb + xv.z;
    o.w = (zv.w - m) * r * g + bb + xv.w;
    ((float4*)out)[i] = o;
}

// =====================================================================
// launch
// =====================================================================
extern "C" void kernel_launch(void* const* d_in, const int* in_sizes, int n_in,
                              void* d_out, int out_size)
{
    (void)in_sizes; (void)n_in; (void)out_size;
    const float* x     = (const float*)d_in[0];
    const float* g_w   = (const float*)d_in[1];
    const float* g_b   = (const float*)d_in[2];
    const float* th_w  = (const float*)d_in[3];
    const float* th_b  = (const float*)d_in[4];
    const float* ph_w  = (const float*)d_in[5];
    const float* ph_b  = (const float*)d_in[6];
    const float* W_w   = (const float*)d_in[7];
    const float* gamma = (const float*)d_in[9];
    const float* beta  = (const float*)d_in[10];
    float* out = (float*)d_out;

    __nv_bfloat16 *xt, *wtp, *gw, *ww, *tp, *gt, *fsm, *yt;
    float *fpart, *z, *stats, *tpb;
    cudaGetSymbolAddress((void**)&xt,    d_xt);
    cudaGetSymbolAddress((void**)&wtp,   d_wtp);
    cudaGetSymbolAddress((void**)&gw,    d_gw);
    cudaGetSymbolAddress((void**)&ww,    d_ww);
    cudaGetSymbolAddress((void**)&tp,    d_tp);
    cudaGetSymbolAddress((void**)&gt,    d_gt);
    cudaGetSymbolAddress((void**)&fpart, d_fpart);
    cudaGetSymbolAddress((void**)&fsm,   d_fsm);
    cudaGetSymbolAddress((void**)&yt,    d_yt);
    cudaGetSymbolAddress((void**)&z,     d_z);
    cudaGetSymbolAddress((void**)&stats, d_stats);
    cudaGetSymbolAddress((void**)&tpb,   d_tpb);

    __nv_bfloat16 *xt0 = xt, *xt1 = xt + XT_SZ;
    __nv_bfloat16 *wtp0 = wtp, *wtp1 = wtp + 512 * 512;
    __nv_bfloat16 *gw0 = gw, *gw1 = gw + CI * CCH;
    __nv_bfloat16 *ww0 = ww, *ww1 = ww + CCH * CI;
    __nv_bfloat16 *tp0 = tp, *tp1 = tp + TP_SZ;
    __nv_bfloat16 *gt0 = gt, *gt1 = gt + GT_SZ;
    __nv_bfloat16 *fs0 = fsm, *fs1 = fsm + F_SZ;
    __nv_bfloat16 *yt0 = yt, *yt1 = yt + YT_SZ;

    const int SMEM = 3 * 24576 + 1024;   // 3-stage, K-chunk 32: 74752 B -> 3 CTAs/SM

    auto* k1a = mma_nt<1, 512,  NPIX, CCH, 1>;
    auto* k1b = mma_nt<1, NPIX, CI,   CCH, 1>;
    auto* k2  = mma_nt<0, CI,   CI,   NPIX, FSPLIT>;
    auto* k3  = mma_nt<1, NPIX, CI,   CI,  1>;
    auto* k4  = mma_nt<0, 512,  NPIX, CI,  1>;
    cudaFuncSetAttribute(k1a, cudaFuncAttributeMaxDynamicSharedMemorySize, SMEM);
    cudaFuncSetAttribute(k1b, cudaFuncAttributeMaxDynamicSharedMemorySize, SMEM);
    cudaFuncSetAttribute(k2,  cudaFuncAttributeMaxDynamicSharedMemorySize, SMEM);
    cudaFuncSetAttribute(k3,  cudaFuncAttributeMaxDynamicSharedMemorySize, SMEM);
    cudaFuncSetAttribute(k4,  cudaFuncAttributeMaxDynamicSharedMemorySize, SMEM);

    // one prep launch: 4 weight splits + bias stack + stats zero
    prep_splits<<<(4 * 131072) / 256, 256>>>(
        th_w, ph_w, g_w, W_w,
        wtp0, wtp1, gw0, gw1, ww0, ww1,
        th_b, ph_b, tpb, stats);

    // xT 2-level split: (B, 4096, 512)
    transpose_split2<<<dim3(NPIX / 32, CCH / 32, BATCH), dim3(32, 8)>>>(x, xt0, xt1);

    // GEMM1a: tp[b](512,4096) = Wtp(512,512) @ xT[b]^T (+ [th_b;ph_b] per row), hi/lo out
    k1a<<<dim3(NPIX / 128, 512 / 64, BATCH), 128, SMEM>>>(
        wtp0, wtp1, xt0, xt1,
        nullptr, tp0, tp1, tpb, nullptr, nullptr,
        0, (long long)NPIX * CCH, 512LL * NPIX);

    // GEMM1b: gT[b](4096,256) = xT[b] @ g_w^T (+ g_b per col), hi/lo out
    k1b<<<dim3(CI / 128, NPIX / 64, BATCH), 128, SMEM>>>(
        xt0, xt1, gw0, gw1,
        nullptr, gt0, gt1, nullptr, g_b, nullptr,
        (long long)NPIX * CCH, 0, (long long)NPIX * CI);

    // GEMM2: f partials = theta @ phi^T, split-K 8, fp32 out
    k2<<<dim3(CI / 128, CI / 64, BATCH * FSPLIT), 128, SMEM>>>(
        tp0, tp1,
        tp0 + (size_t)CI * NPIX, tp1 + (size_t)CI * NPIX,
        fpart, nullptr, nullptr, nullptr, nullptr, nullptr,
        512LL * NPIX, 512LL * NPIX, (long long)CI * CI);

    // softmax (sums FSPLIT partials) -> hi/lo bf16
    softmax_split<<<BATCH * CI, 256>>>(fpart, fs0, fs1);

    // GEMM3: yT[b](4096,256) = gT[b] @ fsm[b]^T, hi/lo out
    k3<<<dim3(CI / 128, NPIX / 64, BATCH), 128, SMEM>>>(
        gt0, gt1, fs0, fs1,
        nullptr, yt0, yt1, nullptr, nullptr, nullptr,
        (long long)NPIX * CI, (long long)CI * CI, (long long)NPIX * CI);

    // GEMM4: z[b](512,4096) = W_w @ yT[b]^T (W_b dropped: cancels in BN),
    //        fp32 out + fused per-channel stats partials
    k4<<<dim3(NPIX / 128, 512 / 64, BATCH), 128, SMEM>>>(
        ww0, ww1, yt0, yt1,
        z, nullptr, nullptr, nullptr, nullptr, stats,
        0, (long long)NPIX * CI, (long long)CCH * NPIX);

    // BN (finalize folded) + residual
    const size_t total4 = (size_t)BATCH * CCH * NPIX / 4;
    bn_residual<<<(unsigned)(total4 / 256), 256>>>(z, x, gamma, beta, stats, out);
}

// round 12
// speedup vs baseline: 4.8116x; 1.0228x over previous
#include <cuda_runtime.h>
#include <cuda_bf16.h>
#include <cstdint>

#define BATCH 16
#define CCH   512
#define CI    256
#define NPIX  4096
#define FSPLIT 8

// ---------------- scratch (device globals; no allocation allowed) ----------------
static const size_t XT_SZ  = (size_t)BATCH * NPIX * CCH;   // per level
static const size_t TP_SZ  = (size_t)BATCH * 512 * NPIX;
static const size_t GT_SZ  = (size_t)BATCH * NPIX * CI;
static const size_t F_SZ   = (size_t)BATCH * CI * CI;
static const size_t YT_SZ  = (size_t)BATCH * NPIX * CI;

__device__ __nv_bfloat16 d_xt [2][(size_t)BATCH * NPIX * CCH];   // 134 MB
__device__ __nv_bfloat16 d_wtp[2][512 * 512];
__device__ __nv_bfloat16 d_gw [2][CI * CCH];
__device__ __nv_bfloat16 d_ww [2][CCH * CI];
__device__ __nv_bfloat16 d_tp [2][(size_t)BATCH * 512 * NPIX];   // 134 MB
__device__ __nv_bfloat16 d_gt [2][(size_t)BATCH * NPIX * CI];    // 67 MB
__device__ float         d_fpart[(size_t)FSPLIT * BATCH * CI * CI]; // 33.5 MB
__device__ __nv_bfloat16 d_fsm[2][(size_t)BATCH * CI * CI];
__device__ __nv_bfloat16 d_yt [2][(size_t)BATCH * NPIX * CI];    // 67 MB
__device__ float         d_z[(size_t)BATCH * CCH * NPIX];        // 134 MB
__device__ float         d_stats[2 * CCH];                       // raw partials
__device__ float         d_tpb[512];

// ---------------- helpers (arch-portable PTX only: sm_80+) ----------------
__device__ __forceinline__ uint32_t smem_u32(const void* p) {
    uint32_t a;
    asm("{ .reg .u64 t; cvta.to.shared.u64 t, %1; cvt.u32.u64 %0, t; }" : "=r"(a) : "l"(p));
    return a;
}

__device__ __forceinline__ void cpasync16(uint32_t dst, const void* src) {
    asm volatile("cp.async.cg.shared.global [%0], [%1], 16;" :: "r"(dst), "l"(src));
}
#define CP_COMMIT() asm volatile("cp.async.commit_group;" ::: "memory")

__device__ __forceinline__ void ldsm4(uint32_t addr, uint32_t& r0, uint32_t& r1,
                                      uint32_t& r2, uint32_t& r3) {
    asm volatile("ldmatrix.sync.aligned.m8n8.x4.shared.b16 {%0,%1,%2,%3}, [%4];"
                 : "=r"(r0), "=r"(r1), "=r"(r2), "=r"(r3) : "r"(addr));
}
__device__ __forceinline__ void mma16816(float* c, const uint32_t* a, uint32_t b0, uint32_t b1) {
    asm volatile(
        "mma.sync.aligned.m16n8k16.row.col.f32.bf16.bf16.f32 "
        "{%0,%1,%2,%3}, {%4,%5,%6,%7}, {%8,%9}, {%0,%1,%2,%3};"
        : "+f"(c[0]), "+f"(c[1]), "+f"(c[2]), "+f"(c[3])
        : "r"(a[0]), "r"(a[1]), "r"(a[2]), "r"(a[3]), "r"(b0), "r"(b1));
}

// =====================================================================
// NT GEMM on tensor cores (mma.sync bf16, fp32 acc), 2-level split inputs:
//   D[M,N] = A0*B0^T + A0*B1^T + A1*B0^T    (ll term dropped, ~2^-18)
// Shapes are TEMPLATE params. A,B: K-major (ld = Kv). CTA tile 64x128,
// 128 threads (4 warps, warp tile 32x64). K-chunk 32 (64B rows, SW64),
// 2-stage cp.async pipeline, 49KB smem -> 4 CTAs/SM (16 warps: latency
// hiding via occupancy). Fragment liveness reduced: products issued as
// A0B0 -> (load fb1) A0B1 -> (load fa1) A1B0, max 40 frag regs live.
// MODE: 0 = fp32 out (optional fused stats atomics), 1 = hi/lo bf16 out.
// grid = (Nv/128, Mv/64, batch*NSPLIT)
// =====================================================================
template <int MODE, int Mv, int Nv, int Kv, int NSPLIT>
__global__ __launch_bounds__(128, 4) void mma_nt(
    const __nv_bfloat16* __restrict__ a0, const __nv_bfloat16* __restrict__ a1,
    const __nv_bfloat16* __restrict__ b0, const __nv_bfloat16* __restrict__ b1,
    float* __restrict__ cf,
    __nv_bfloat16* __restrict__ c0, __nv_bfloat16* __restrict__ c1,
    const float* __restrict__ biasRow, const float* __restrict__ biasCol,
    float* __restrict__ statsPart,
    long long sA, long long sB, long long sC)
{
    constexpr int stageBytes = 24576;       // A0 4K | A1 4K | B0 8K | B1 8K
    constexpr int Ksub = Kv / NSPLIT;
    constexpr int nk = Ksub / 32;

    extern __shared__ char smraw[];
    const uint32_t smem_base = (smem_u32(smraw) + 1023u) & ~1023u;

    const int tid = threadIdx.x;
    const int wid = tid >> 5, lid = tid & 31;
    const int warpM = (wid & 1) * 32;       // 2 warps over M (64 rows)
    const int warpN = (wid >> 1) * 64;      // 2 warps over N (128 cols)

    const int bz = blockIdx.z;
    const int b  = bz / NSPLIT, sp = bz % NSPLIT;
    const int k0base = sp * Ksub;
    const int mBase = blockIdx.y * 64;
    const int nBase = blockIdx.x * 128;

    // ---- precomputed cp.async addressing (prologue only) ----
    const int row0 = tid >> 2;              // 0..31
    const int segE = (tid & 3) * 8;
    const __nv_bfloat16* srcA0 = a0 + (size_t)b * sA + (size_t)(mBase + row0) * Kv + k0base + segE;
    const __nv_bfloat16* srcA1 = a1 + (size_t)b * sA + (size_t)(mBase + row0) * Kv + k0base + segE;
    const __nv_bfloat16* srcB0 = b0 + (size_t)b * sB + (size_t)(nBase + row0) * Kv + k0base + segE;
    const __nv_bfloat16* srcB1 = b1 + (size_t)b * sB + (size_t)(nBase + row0) * Kv + k0base + segE;
    uint32_t dstO[4];                       // swizzled dst offsets, tile-local
    #pragma unroll
    for (int c = 0; c < 4; c++) {
        const int row = row0 + 32 * c;
        const uint32_t o = row * 64 + (tid & 3) * 16;
        dstO[c] = o ^ ((row & 6) * 8);      // SW64 swizzle, precomputed
    }

    auto loadChunk = [&](int ci, uint32_t sb) {
        const __nv_bfloat16* s0 = srcA0 + (size_t)ci * 32;
        const __nv_bfloat16* s1 = srcA1 + (size_t)ci * 32;
        const __nv_bfloat16* s2 = srcB0 + (size_t)ci * 32;
        const __nv_bfloat16* s3 = srcB1 + (size_t)ci * 32;
        #pragma unroll
        for (int c = 0; c < 2; c++) {       // A tiles: 64 rows
            cpasync16(sb + dstO[c],         s0 + (size_t)c * 32 * Kv);
            cpasync16(sb + 4096 + dstO[c],  s1 + (size_t)c * 32 * Kv);
        }
        #pragma unroll
        for (int c = 0; c < 4; c++) {       // B tiles: 128 rows
            cpasync16(sb + 8192 + dstO[c],  s2 + (size_t)c * 32 * Kv);
            cpasync16(sb + 16384 + dstO[c], s3 + (size_t)c * 32 * Kv);
        }
    };

    float acc[2][8][4];
    #pragma unroll
    for (int i = 0; i < 2; i++)
        #pragma unroll
        for (int j = 0; j < 8; j++)
            #pragma unroll
            for (int k = 0; k < 4; k++) acc[i][j][k] = 0.f;

    loadChunk(0, smem_base); CP_COMMIT();
    loadChunk(1, smem_base + stageBytes); CP_COMMIT();

    const int lRow = lid & 15;
    const uint32_t colH = ((lid >> 4) & 1) * 16;

    // precomputed FULL ldsm offsets (stage-relative): 1 ADD per LDSM at use
    uint32_t offA[2][2], offB[2][4];        // [ks][site]
    #pragma unroll
    for (int mi = 0; mi < 2; mi++) {
        const int row = warpM + 16 * mi + lRow;
        const uint32_t ba = row * 64, xr = (row & 6) * 8;
        offA[0][mi] = ba + (colH ^ xr);
        offA[1][mi] = ba + ((32 + colH) ^ xr);
    }
    #pragma unroll
    for (int nj = 0; nj < 4; nj++) {
        const int row = warpN + 16 * nj + lRow;
        const uint32_t ba = row * 64, xr = (row & 6) * 8;
        offB[0][nj] = ba + (colH ^ xr);
        offB[1][nj] = ba + ((32 + colH) ^ xr);
    }

// Product-ordered compute: A0B0 -> (load fb1) A0B1 (frees fb1) -> (load fa1) A1B0.
// Peak live frags: fa0(8)+fb0(16)+fb1(16)=40 regs.
#define COMPUTE_KS(KS)                                                          \
    {                                                                           \
        uint32_t fa0[2][4], fb0[4][4];                                          \
        _Pragma("unroll")                                                       \
        for (int mi = 0; mi < 2; mi++)                                          \
            ldsm4(A0b + offA[KS][mi],                                           \
                  fa0[mi][0], fa0[mi][1], fa0[mi][2], fa0[mi][3]);              \
        _Pragma("unroll")                                                       \
        for (int nj = 0; nj < 4; nj++)                                          \
            ldsm4(B0b + offB[KS][nj],                                           \
                  fb0[nj][0], fb0[nj][1], fb0[nj][2], fb0[nj][3]);              \
        _Pragma("unroll")                                                       \
        for (int mi = 0; mi < 2; mi++)                                          \
            _Pragma("unroll")                                                   \
            for (int jn = 0; jn < 8; jn++)                                      \
                mma16816(acc[mi][jn], fa0[mi],                                  \
                         fb0[jn >> 1][jn & 1], fb0[jn >> 1][2 + (jn & 1)]);     \
        {                                                                       \
            uint32_t fb1[4][4];                                                 \
            _Pragma("unroll")                                                   \
            for (int nj = 0; nj < 4; nj++)                                      \
                ldsm4(B1b + offB[KS][nj],                                       \
                      fb1[nj][0], fb1[nj][1], fb1[nj][2], fb1[nj][3]);          \
            _Pragma("unroll")                                                   \
            for (int mi = 0; mi < 2; mi++)                                      \
                _Pragma("unroll")                                               \
                for (int jn = 0; jn < 8; jn++)                                  \
                    mma16816(acc[mi][jn], fa0[mi],                              \
                             fb1[jn >> 1][jn & 1], fb1[jn >> 1][2 + (jn & 1)]); \
        }                                                                       \
        {                                                                       \
            uint32_t fa1[2][4];                                                 \
            _Pragma("unroll")                                                   \
            for (int mi = 0; mi < 2; mi++)                                      \
                ldsm4(A1b + offA[KS][mi],                                       \
                      fa1[mi][0], fa1[mi][1], fa1[mi][2], fa1[mi][3]);          \
            _Pragma("unroll")                                                   \
            for (int mi = 0; mi < 2; mi++)                                      \
                _Pragma("unroll")                                               \
                for (int jn = 0; jn < 8; jn++)                                  \
                    mma16816(acc[mi][jn], fa1[mi],                              \
                             fb0[jn >> 1][jn & 1], fb0[jn >> 1][2 + (jn & 1)]); \
        }                                                                       \
    }

    #pragma unroll 1
    for (int i = 0; i < nk; i++) {
        const uint32_t sb = smem_base + (i & 1) * stageBytes;
        asm volatile("cp.async.wait_group 1;" ::: "memory");
        __syncthreads();                    // chunk i resident

        const uint32_t A0b = sb, A1b = sb + 4096;
        const uint32_t B0b = sb + 8192, B1b = sb + 16384;

        COMPUTE_KS(0);
        COMPUTE_KS(1);

        __syncthreads();                    // all warps done with buffer i&1
        if (i + 2 < nk) { loadChunk(i + 2, sb); CP_COMMIT(); }
    }
#undef COMPUTE_KS

    // ---- epilogue ----
    const int gr = lid >> 2;            // 0..7
    const int gc = (lid & 3) * 2;       // 0,2,4,6
    const size_t cOff = (size_t)bz * sC;

    #pragma unroll
    for (int mi = 0; mi < 2; mi++) {
        const int row0e = mBase + warpM + 16 * mi + gr;
        const int row1e = row0e + 8;
        const float br0 = biasRow ? biasRow[row0e] : 0.f;
        const float br1 = biasRow ? biasRow[row1e] : 0.f;
        float s0 = 0.f, q0 = 0.f, s1 = 0.f, q1 = 0.f;
        #pragma unroll
        for (int jn = 0; jn < 8; jn++) {
            const int col = nBase + warpN + 8 * jn + gc;
            float v00 = acc[mi][jn][0] + br0;
            float v01 = acc[mi][jn][1] + br0;
            float v10 = acc[mi][jn][2] + br1;
            float v11 = acc[mi][jn][3] + br1;
            if (biasCol) {
                const float bc0 = biasCol[col], bc1 = biasCol[col + 1];
                v00 += bc0; v01 += bc1; v10 += bc0; v11 += bc1;
            }
            const size_t base0 = cOff + (size_t)row0e * Nv + col;
            const size_t base1 = cOff + (size_t)row1e * Nv + col;
            if (MODE == 0) {
                *(float2*)(cf + base0) = make_float2(v00, v01);
                *(float2*)(cf + base1) = make_float2(v10, v11);
                if (statsPart) {
                    s0 += v00 + v01; q0 += v00 * v00 + v01 * v01;
                    s1 += v10 + v11; q1 += v10 * v10 + v11 * v11;
                }
            } else {
                float vv[2][2] = {{v00, v01}, {v10, v11}};
                const size_t bb[2] = {base0, base1};
                #pragma unroll
                for (int r = 0; r < 2; r++) {
                    __nv_bfloat16 h0 = __float2bfloat16(vv[r][0]);
                    __nv_bfloat16 h1 = __float2bfloat16(vv[r][1]);
                    float r0 = vv[r][0] - __bfloat162float(h0);
                    float r1 = vv[r][1] - __bfloat162float(h1);
                    __nv_bfloat162 th; th.x = h0; th.y = h1;
                    __nv_bfloat162 tl;
                    tl.x = __float2bfloat16(r0); tl.y = __float2bfloat16(r1);
                    *(__nv_bfloat162*)(c0 + bb[r]) = th;
                    *(__nv_bfloat162*)(c1 + bb[r]) = tl;
                }
            }
        }
        if (MODE == 0 && statsPart) {
            #pragma unroll
            for (int o = 1; o < 4; o <<= 1) {
                s0 += __shfl_xor_sync(0xFFFFFFFFu, s0, o);
                q0 += __shfl_xor_sync(0xFFFFFFFFu, q0, o);
                s1 += __shfl_xor_sync(0xFFFFFFFFu, s1, o);
                q1 += __shfl_xor_sync(0xFFFFFFFFu, q1, o);
            }
            if ((lid & 3) == 0) {
                atomicAdd(&statsPart[row0e], s0);
                atomicAdd(&statsPart[CCH + row0e], q0);
                atomicAdd(&statsPart[row1e], s1);
                atomicAdd(&statsPart[CCH + row1e], q1);
            }
        }
    }
}

// =====================================================================
// prep: all four weight splits + bias stack + stats zero (ONE launch)
// =====================================================================
__global__ void prep_splits(
    const float* __restrict__ th_w, const float* __restrict__ ph_w,
    const float* __restrict__ g_w,  const float* __restrict__ W_w,
    __nv_bfloat16* __restrict__ wtp0, __nv_bfloat16* __restrict__ wtp1,
    __nv_bfloat16* __restrict__ gw0,  __nv_bfloat16* __restrict__ gw1,
    __nv_bfloat16* __restrict__ ww0,  __nv_bfloat16* __restrict__ ww1,
    const float* __restrict__ th_b, const float* __restrict__ ph_b,
    float* __restrict__ tpb, float* __restrict__ stats)
{
    const int i = blockIdx.x * 256 + threadIdx.x;   // 0 .. 4*131072-1
    const int arr = i >> 17;
    const int off = i & 131071;
    const float* src;
    __nv_bfloat16 *dh, *dl;
    switch (arr) {
        case 0:  src = th_w; dh = wtp0;          dl = wtp1;          break;
        case 1:  src = ph_w; dh = wtp0 + 131072; dl = wtp1 + 131072; break;
        case 2:  src = g_w;  dh = gw0;           dl = gw1;           break;
        default: src = W_w;  dh = ww0;           dl = ww1;           break;
    }
    const float v = src[off];
    const __nv_bfloat16 hh = __float2bfloat16(v);
    dh[off] = hh;
    dl[off] = __float2bfloat16(v - __bfloat162float(hh));

    if (i < 512)  tpb[i]  = (i < 256) ? th_b[i] : ph_b[i - 256];
    if (i < 1024) stats[i] = 0.f;
}

// =====================================================================
// transpose + 2-level split of x
// =====================================================================
__global__ void transpose_split2(const float* __restrict__ x,
                                 __nv_bfloat16* __restrict__ h,
                                 __nv_bfloat16* __restrict__ l)
{
    __shared__ float t[32][33];
    const int b = blockIdx.z;
    const int n0 = blockIdx.x * 32, c0 = blockIdx.y * 32;
    const float* xb = x + (size_t)b * CCH * NPIX;
    #pragma unroll
    for (int k = 0; k < 4; k++) {
        const int c = c0 + threadIdx.y + k * 8;
        t[threadIdx.y + k * 8][threadIdx.x] = xb[(size_t)c * NPIX + n0 + threadIdx.x];
    }
    __syncthreads();
    const size_t ob = (size_t)b * NPIX * CCH;
    #pragma unroll
    for (int k = 0; k < 4; k++) {
        const int n = n0 + threadIdx.y + k * 8;
        const float v = t[threadIdx.x][threadIdx.y + k * 8];
        const size_t idx = ob + (size_t)n * CCH + c0 + threadIdx.x;
        __nv_bfloat16 hh = __float2bfloat16(v);
        h[idx] = hh;
        l[idx] = __float2bfloat16(v - __bfloat162float(hh));
    }
}

__global__ __launch_bounds__(256) void softmax_split(
    const float* __restrict__ fp, __nv_bfloat16* __restrict__ h, __nv_bfloat16* __restrict__ l)
{
    const int row = blockIdx.x;        // b*256 + c
    const int b = row >> 8, c = row & 255;
    const int d = threadIdx.x;
    float v = 0.f;
    #pragma unroll
    for (int s = 0; s < FSPLIT; s++)
        v += fp[((size_t)(b * FSPLIT + s)) * (CI * CI) + c * CI + d];
    __shared__ float red[256];
    red[d] = v; __syncthreads();
    for (int o = 128; o > 0; o >>= 1) {
        if (d < o) red[d] = fmaxf(red[d], red[d + o]);
        __syncthreads();
    }
    const float mx = red[0];
    __syncthreads();
    const float e = __expf(v - mx);
    red[d] = e; __syncthreads();
    for (int o = 128; o > 0; o >>= 1) {
        if (d < o) red[d] += red[d + o];
        __syncthreads();
    }
    const float p = e / red[0];
    const size_t idx = (size_t)row * CI + d;
    __nv_bfloat16 hh = __float2bfloat16(p);
    h[idx] = hh; l[idx] = __float2bfloat16(p - __bfloat162float(hh));
}

// =====================================================================
// BN (finalize folded in) + residual
// =====================================================================
__global__ __launch_bounds__(256) void bn_residual(
    const float* __restrict__ z, const float* __restrict__ x,
    const float* __restrict__ gamma, const float* __restrict__ beta,
    const float* __restrict__ stats, float* __restrict__ out)
{
    const size_t i = (size_t)blockIdx.x * blockDim.x + threadIdx.x;
    const int c = (int)((i >> 10) & (CCH - 1));
    const float cnt = (float)(BATCH * NPIX);
    const float m = stats[c] / cnt;
    const float var = stats[CCH + c] / cnt - m * m;
    const float r = rsqrtf(var + 1e-5f);
    const float g = gamma[c], bb = beta[c];
    const float4 zv = ((const float4*)z)[i];
    const float4 xv = ((const float4*)x)[i];
    float4 o;
    o.x = (zv.x - m) * r * g + bb + xv.x;
    o.y = (zv.y - m) * r * g + bb + xv.y;
    o.z = (zv.z - m) * r * g + bb + xv.z;
    o.w = (zv.w - m) * r * g + bb + xv.w;
    ((float4*)out)[i] = o;
}

// =====================================================================
// launch
// =====================================================================
extern "C" void kernel_launch(void* const* d_in, const int* in_sizes, int n_in,
                              void* d_out, int out_size)
{
    (void)in_sizes; (void)n_in; (void)out_size;
    const float* x     = (const float*)d_in[0];
    const float* g_w   = (const float*)d_in[1];
    const float* g_b   = (const float*)d_in[2];
    const float* th_w  = (const float*)d_in[3];
    const float* th_b  = (const float*)d_in[4];
    const float* ph_w  = (const float*)d_in[5];
    const float* ph_b  = (const float*)d_in[6];
    const float* W_w   = (const float*)d_in[7];
    const float* gamma = (const float*)d_in[9];
    const float* beta  = (const float*)d_in[10];
    float* out = (float*)d_out;

    __nv_bfloat16 *xt, *wtp, *gw, *ww, *tp, *gt, *fsm, *yt;
    float *fpart, *z, *stats, *tpb;
    cudaGetSymbolAddress((void**)&xt,    d_xt);
    cudaGetSymbolAddress((void**)&wtp,   d_wtp);
    cudaGetSymbolAddress((void**)&gw,    d_gw);
    cudaGetSymbolAddress((void**)&ww,    d_ww);
    cudaGetSymbolAddress((void**)&tp,    d_tp);
    cudaGetSymbolAddress((void**)&gt,    d_gt);
    cudaGetSymbolAddress((void**)&fpart, d_fpart);
    cudaGetSymbolAddress((void**)&fsm,   d_fsm);
    cudaGetSymbolAddress((void**)&yt,    d_yt);
    cudaGetSymbolAddress((void**)&z,     d_z);
    cudaGetSymbolAddress((void**)&stats, d_stats);
    cudaGetSymbolAddress((void**)&tpb,   d_tpb);

    __nv_bfloat16 *xt0 = xt, *xt1 = xt + XT_SZ;
    __nv_bfloat16 *wtp0 = wtp, *wtp1 = wtp + 512 * 512;
    __nv_bfloat16 *gw0 = gw, *gw1 = gw + CI * CCH;
    __nv_bfloat16 *ww0 = ww, *ww1 = ww + CCH * CI;
    __nv_bfloat16 *tp0 = tp, *tp1 = tp + TP_SZ;
    __nv_bfloat16 *gt0 = gt, *gt1 = gt + GT_SZ;
    __nv_bfloat16 *fs0 = fsm, *fs1 = fsm + F_SZ;
    __nv_bfloat16 *yt0 = yt, *yt1 = yt + YT_SZ;

    const int SMEM = 2 * 24576 + 1024;   // 2-stage, K-chunk 32: 50176 B -> 4 CTAs/SM

    auto* k1a = mma_nt<1, 512,  NPIX, CCH, 1>;
    auto* k1b = mma_nt<1, NPIX, CI,   CCH, 1>;
    auto* k2  = mma_nt<0, CI,   CI,   NPIX, FSPLIT>;
    auto* k3  = mma_nt<1, NPIX, CI,   CI,  1>;
    auto* k4  = mma_nt<0, 512,  NPIX, CI,  1>;
    cudaFuncSetAttribute(k1a, cudaFuncAttributeMaxDynamicSharedMemorySize, SMEM);
    cudaFuncSetAttribute(k1b, cudaFuncAttributeMaxDynamicSharedMemorySize, SMEM);
    cudaFuncSetAttribute(k2,  cudaFuncAttributeMaxDynamicSharedMemorySize, SMEM);
    cudaFuncSetAttribute(k3,  cudaFuncAttributeMaxDynamicSharedMemorySize, SMEM);
    cudaFuncSetAttribute(k4,  cudaFuncAttributeMaxDynamicSharedMemorySize, SMEM);

    // one prep launch: 4 weight splits + bias stack + stats zero
    prep_splits<<<(4 * 131072) / 256, 256>>>(
        th_w, ph_w, g_w, W_w,
        wtp0, wtp1, gw0, gw1, ww0, ww1,
        th_b, ph_b, tpb, stats);

    // xT 2-level split: (B, 4096, 512)
    transpose_split2<<<dim3(NPIX / 32, CCH / 32, BATCH), dim3(32, 8)>>>(x, xt0, xt1);

    // GEMM1a: tp[b](512,4096) = Wtp(512,512) @ xT[b]^T (+ [th_b;ph_b] per row), hi/lo out
    k1a<<<dim3(NPIX / 128, 512 / 64, BATCH), 128, SMEM>>>(
        wtp0, wtp1, xt0, xt1,
        nullptr, tp0, tp1, tpb, nullptr, nullptr,
        0, (long long)NPIX * CCH, 512LL * NPIX);

    // GEMM1b: gT[b](4096,256) = xT[b] @ g_w^T (+ g_b per col), hi/lo out
    k1b<<<dim3(CI / 128, NPIX / 64, BATCH), 128, SMEM>>>(
        xt0, xt1, gw0, gw1,
        nullptr, gt0, gt1, nullptr, g_b, nullptr,
        (long long)NPIX * CCH, 0, (long long)NPIX * CI);

    // GEMM2: f partials = theta @ phi^T, split-K 8, fp32 out
    k2<<<dim3(CI / 128, CI / 64, BATCH * FSPLIT), 128, SMEM>>>(
        tp0, tp1,
        tp0 + (size_t)CI * NPIX, tp1 + (size_t)CI * NPIX,
        fpart, nullptr, nullptr, nullptr, nullptr, nullptr,
        512LL * NPIX, 512LL * NPIX, (long long)CI * CI);

    // softmax (sums FSPLIT partials) -> hi/lo bf16
    softmax_split<<<BATCH * CI, 256>>>(fpart, fs0, fs1);

    // GEMM3: yT[b](4096,256) = gT[b] @ fsm[b]^T, hi/lo out
    k3<<<dim3(CI / 128, NPIX / 64, BATCH), 128, SMEM>>>(
        gt0, gt1, fs0, fs1,
        nullptr, yt0, yt1, nullptr, nullptr, nullptr,
        (long long)NPIX * CI, (long long)CI * CI, (long long)NPIX * CI);

    // GEMM4: z[b](512,4096) = W_w @ yT[b]^T (W_b dropped: cancels in BN),
    //        fp32 out + fused per-channel stats partials
    k4<<<dim3(NPIX / 128, 512 / 64, BATCH), 128, SMEM>>>(
        ww0, ww1, yt0, yt1,
        z, nullptr, nullptr, nullptr, nullptr, stats,
        0, (long long)NPIX * CI, (long long)CCH * NPIX);

    // BN (finalize folded) + residual
    const size_t total4 = (size_t)BATCH * CCH * NPIX / 4;
    bn_residual<<<(unsigned)(total4 / 256), 256>>>(z, x, gamma, beta, stats, out);
}

// round 13
// speedup vs baseline: 4.8450x; 1.0069x over previous
#include <cuda_runtime.h>
#include <cuda_bf16.h>
#include <cstdint>

#define BATCH 16
#define CCH   512
#define CI    256
#define NPIX  4096
#define FSPLIT 8

// ---------------- scratch (device globals; no allocation allowed) ----------------
static const size_t XT_SZ  = (size_t)BATCH * NPIX * CCH;   // per level
static const size_t TP_SZ  = (size_t)BATCH * 512 * NPIX;
static const size_t GT_SZ  = (size_t)BATCH * NPIX * CI;
static const size_t F_SZ   = (size_t)BATCH * CI * CI;
static const size_t YT_SZ  = (size_t)BATCH * NPIX * CI;

__device__ __nv_bfloat16 d_xt [2][(size_t)BATCH * NPIX * CCH];   // 134 MB
__device__ __nv_bfloat16 d_wtp[2][512 * 512];
__device__ __nv_bfloat16 d_gw [2][CI * CCH];
__device__ __nv_bfloat16 d_ww [2][CCH * CI];
__device__ __nv_bfloat16 d_tp [2][(size_t)BATCH * 512 * NPIX];   // 134 MB
__device__ __nv_bfloat16 d_gt [2][(size_t)BATCH * NPIX * CI];    // 67 MB
__device__ float         d_fpart[(size_t)FSPLIT * BATCH * CI * CI]; // 33.5 MB
__device__ __nv_bfloat16 d_fsm[2][(size_t)BATCH * CI * CI];
__device__ __nv_bfloat16 d_yt [2][(size_t)BATCH * NPIX * CI];    // 67 MB
__device__ float         d_z[(size_t)BATCH * CCH * NPIX];        // 134 MB
__device__ float         d_stats[2 * CCH];                       // raw partials
__device__ float         d_tpb[512];

// ---------------- helpers (arch-portable PTX only: sm_80+) ----------------
__device__ __forceinline__ uint32_t smem_u32(const void* p) {
    uint32_t a;
    asm("{ .reg .u64 t; cvta.to.shared.u64 t, %1; cvt.u32.u64 %0, t; }" : "=r"(a) : "l"(p));
    return a;
}

__device__ __forceinline__ void cpasync16(uint32_t dst, const void* src) {
    asm volatile("cp.async.cg.shared.global [%0], [%1], 16;" :: "r"(dst), "l"(src));
}
#define CP_COMMIT() asm volatile("cp.async.commit_group;" ::: "memory")

__device__ __forceinline__ void ldsm4(uint32_t addr, uint32_t& r0, uint32_t& r1,
                                      uint32_t& r2, uint32_t& r3) {
    asm volatile("ldmatrix.sync.aligned.m8n8.x4.shared.b16 {%0,%1,%2,%3}, [%4];"
                 : "=r"(r0), "=r"(r1), "=r"(r2), "=r"(r3) : "r"(addr));
}
__device__ __forceinline__ void mma16816(float* c, const uint32_t* a, uint32_t b0, uint32_t b1) {
    asm volatile(
        "mma.sync.aligned.m16n8k16.row.col.f32.bf16.bf16.f32 "
        "{%0,%1,%2,%3}, {%4,%5,%6,%7}, {%8,%9}, {%0,%1,%2,%3};"
        : "+f"(c[0]), "+f"(c[1]), "+f"(c[2]), "+f"(c[3])
        : "r"(a[0]), "r"(a[1]), "r"(a[2]), "r"(a[3]), "r"(b0), "r"(b1));
}

// =====================================================================
// NT GEMM on tensor cores (mma.sync bf16, fp32 acc), 2-level split inputs:
//   D[M,N] = A0*B0^T + A0*B1^T + A1*B0^T    (ll term dropped, ~2^-18)
// Shapes are TEMPLATE params. A,B: K-major (ld = Kv). CTA tile 64x128,
// 128 threads (4 warps, warp tile 32x64). K-chunk 32 (64B rows, SW64),
// 2-stage cp.async pipeline with ONE __syncthreads per chunk:
//   wait_group(0) -> sync -> [batch1] -> issue loads(i+1) -> [rest]
// 49KB smem -> 4 CTAs/SM.
// MODE: 0 = fp32 out (optional fused stats atomics), 1 = hi/lo bf16 out.
// grid = (Nv/128, Mv/64, batch*NSPLIT)
// =====================================================================
template <int MODE, int Mv, int Nv, int Kv, int NSPLIT>
__global__ __launch_bounds__(128, 4) void mma_nt(
    const __nv_bfloat16* __restrict__ a0, const __nv_bfloat16* __restrict__ a1,
    const __nv_bfloat16* __restrict__ b0, const __nv_bfloat16* __restrict__ b1,
    float* __restrict__ cf,
    __nv_bfloat16* __restrict__ c0, __nv_bfloat16* __restrict__ c1,
    const float* __restrict__ biasRow, const float* __restrict__ biasCol,
    float* __restrict__ statsPart,
    long long sA, long long sB, long long sC)
{
    constexpr int stageBytes = 24576;       // A0 4K | A1 4K | B0 8K | B1 8K
    constexpr int Ksub = Kv / NSPLIT;
    constexpr int nk = Ksub / 32;

    extern __shared__ char smraw[];
    const uint32_t smem_base = (smem_u32(smraw) + 1023u) & ~1023u;

    const int tid = threadIdx.x;
    const int wid = tid >> 5, lid = tid & 31;
    const int warpM = (wid & 1) * 32;       // 2 warps over M (64 rows)
    const int warpN = (wid >> 1) * 64;      // 2 warps over N (128 cols)

    const int bz = blockIdx.z;
    const int b  = bz / NSPLIT, sp = bz % NSPLIT;
    const int k0base = sp * Ksub;
    const int mBase = blockIdx.y * 64;
    const int nBase = blockIdx.x * 128;

    // ---- precomputed cp.async addressing (prologue only) ----
    const int row0 = tid >> 2;              // 0..31
    const int segE = (tid & 3) * 8;
    const __nv_bfloat16* srcA0 = a0 + (size_t)b * sA + (size_t)(mBase + row0) * Kv + k0base + segE;
    const __nv_bfloat16* srcA1 = a1 + (size_t)b * sA + (size_t)(mBase + row0) * Kv + k0base + segE;
    const __nv_bfloat16* srcB0 = b0 + (size_t)b * sB + (size_t)(nBase + row0) * Kv + k0base + segE;
    const __nv_bfloat16* srcB1 = b1 + (size_t)b * sB + (size_t)(nBase + row0) * Kv + k0base + segE;
    uint32_t dstO[4];                       // swizzled dst offsets, tile-local
    #pragma unroll
    for (int c = 0; c < 4; c++) {
        const int row = row0 + 32 * c;
        const uint32_t o = row * 64 + (tid & 3) * 16;
        dstO[c] = o ^ ((row & 6) * 8);      // SW64 swizzle, precomputed
    }

    auto loadChunk = [&](int ci, uint32_t sb) {
        const __nv_bfloat16* s0 = srcA0 + (size_t)ci * 32;
        const __nv_bfloat16* s1 = srcA1 + (size_t)ci * 32;
        const __nv_bfloat16* s2 = srcB0 + (size_t)ci * 32;
        const __nv_bfloat16* s3 = srcB1 + (size_t)ci * 32;
        #pragma unroll
        for (int c = 0; c < 2; c++) {       // A tiles: 64 rows
            cpasync16(sb + dstO[c],         s0 + (size_t)c * 32 * Kv);
            cpasync16(sb + 4096 + dstO[c],  s1 + (size_t)c * 32 * Kv);
        }
        #pragma unroll
        for (int c = 0; c < 4; c++) {       // B tiles: 128 rows
            cpasync16(sb + 8192 + dstO[c],  s2 + (size_t)c * 32 * Kv);
            cpasync16(sb + 16384 + dstO[c], s3 + (size_t)c * 32 * Kv);
        }
    };

    float acc[2][8][4];
    #pragma unroll
    for (int i = 0; i < 2; i++)
        #pragma unroll
        for (int j = 0; j < 8; j++)
            #pragma unroll
            for (int k = 0; k < 4; k++) acc[i][j][k] = 0.f;

    loadChunk(0, smem_base); CP_COMMIT();

    const int lRow = lid & 15;
    const uint32_t colH = ((lid >> 4) & 1) * 16;

    // precomputed FULL ldsm offsets (stage-relative): 1 ADD per LDSM at use
    uint32_t offA[2][2], offB[2][4];        // [ks][site]
    #pragma unroll
    for (int mi = 0; mi < 2; mi++) {
        const int row = warpM + 16 * mi + lRow;
        const uint32_t ba = row * 64, xr = (row & 6) * 8;
        offA[0][mi] = ba + (colH ^ xr);
        offA[1][mi] = ba + ((32 + colH) ^ xr);
    }
    #pragma unroll
    for (int nj = 0; nj < 4; nj++) {
        const int row = warpN + 16 * nj + lRow;
        const uint32_t ba = row * 64, xr = (row & 6) * 8;
        offB[0][nj] = ba + (colH ^ xr);
        offB[1][nj] = ba + ((32 + colH) ^ xr);
    }

// One ks-step: product order A0B0 -> (load fb1) A0B1 -> (load fa1) A1B0.
// Peak live frags: fa0(8)+fb0(16)+fb1(16)=40 regs.
#define COMPUTE_KS(KS)                                                          \
    {                                                                           \
        uint32_t fa0[2][4], fb0[4][4];                                          \
        _Pragma("unroll")                                                       \
        for (int mi = 0; mi < 2; mi++)                                          \
            ldsm4(A0b + offA[KS][mi],                                           \
                  fa0[mi][0], fa0[mi][1], fa0[mi][2], fa0[mi][3]);              \
        _Pragma("unroll")                                                       \
        for (int nj = 0; nj < 4; nj++)                                          \
            ldsm4(B0b + offB[KS][nj],                                           \
                  fb0[nj][0], fb0[nj][1], fb0[nj][2], fb0[nj][3]);              \
        _Pragma("unroll")                                                       \
        for (int mi = 0; mi < 2; mi++)                                          \
            _Pragma("unroll")                                                   \
            for (int jn = 0; jn < 8; jn++)                                      \
                mma16816(acc[mi][jn], fa0[mi],                                  \
                         fb0[jn >> 1][jn & 1], fb0[jn >> 1][2 + (jn & 1)]);     \
        {                                                                       \
            uint32_t fb1[4][4];                                                 \
            _Pragma("unroll")                                                   \
            for (int nj = 0; nj < 4; nj++)                                      \
                ldsm4(B1b + offB[KS][nj],                                       \
                      fb1[nj][0], fb1[nj][1], fb1[nj][2], fb1[nj][3]);          \
            _Pragma("unroll")                                                   \
            for (int mi = 0; mi < 2; mi++)                                      \
                _Pragma("unroll")                                               \
                for (int jn = 0; jn < 8; jn++)                                  \
                    mma16816(acc[mi][jn], fa0[mi],                              \
                             fb1[jn >> 1][jn & 1], fb1[jn >> 1][2 + (jn & 1)]); \
        }                                                                       \
        {                                                                       \
            uint32_t fa1[2][4];                                                 \
            _Pragma("unroll")                                                   \
            for (int mi = 0; mi < 2; mi++)                                      \
                ldsm4(A1b + offA[KS][mi],                                       \
                      fa1[mi][0], fa1[mi][1], fa1[mi][2], fa1[mi][3]);          \
            _Pragma("unroll")                                                   \
            for (int mi = 0; mi < 2; mi++)                                      \
                _Pragma("unroll")                                               \
                for (int jn = 0; jn < 8; jn++)                                  \
                    mma16816(acc[mi][jn], fa1[mi],                              \
                             fb0[jn >> 1][jn & 1], fb0[jn >> 1][2 + (jn & 1)]); \
        }                                                                       \
    }

    #pragma unroll 1
    for (int i = 0; i < nk; i++) {
        const uint32_t sb = smem_base + (i & 1) * stageBytes;
        asm volatile("cp.async.wait_group 0;" ::: "memory");   // chunk i arrived
        __syncthreads();   // + all warps done reading the OTHER buffer (chunk i-1)

        const uint32_t A0b = sb, A1b = sb + 4096;
        const uint32_t B0b = sb + 8192, B1b = sb + 16384;

        COMPUTE_KS(0);
        // issue next chunk's loads into the other buffer mid-compute (safe: sync passed)
        if (i + 1 < nk) {
            loadChunk(i + 1, smem_base + ((i + 1) & 1) * stageBytes);
            CP_COMMIT();
        }
        COMPUTE_KS(1);
    }
#undef COMPUTE_KS

    // ---- epilogue ----
    const int gr = lid >> 2;            // 0..7
    const int gc = (lid & 3) * 2;       // 0,2,4,6
    const size_t cOff = (size_t)bz * sC;

    #pragma unroll
    for (int mi = 0; mi < 2; mi++) {
        const int row0e = mBase + warpM + 16 * mi + gr;
        const int row1e = row0e + 8;
        const float br0 = biasRow ? biasRow[row0e] : 0.f;
        const float br1 = biasRow ? biasRow[row1e] : 0.f;
        float s0 = 0.f, q0 = 0.f, s1 = 0.f, q1 = 0.f;
        #pragma unroll
        for (int jn = 0; jn < 8; jn++) {
            const int col = nBase + warpN + 8 * jn + gc;
            float v00 = acc[mi][jn][0] + br0;
            float v01 = acc[mi][jn][1] + br0;
            float v10 = acc[mi][jn][2] + br1;
            float v11 = acc[mi][jn][3] + br1;
            if (biasCol) {
                const float bc0 = biasCol[col], bc1 = biasCol[col + 1];
                v00 += bc0; v01 += bc1; v10 += bc0; v11 += bc1;
            }
            const size_t base0 = cOff + (size_t)row0e * Nv + col;
            const size_t base1 = cOff + (size_t)row1e * Nv + col;
            if (MODE == 0) {
                *(float2*)(cf + base0) = make_float2(v00, v01);
                *(float2*)(cf + base1) = make_float2(v10, v11);
                if (statsPart) {
                    s0 += v00 + v01; q0 += v00 * v00 + v01 * v01;
                    s1 += v10 + v11; q1 += v10 * v10 + v11 * v11;
                }
            } else {
                float vv[2][2] = {{v00, v01}, {v10, v11}};
                const size_t bb[2] = {base0, base1};
                #pragma unroll
                for (int r = 0; r < 2; r++) {
                    __nv_bfloat16 h0 = __float2bfloat16(vv[r][0]);
                    __nv_bfloat16 h1 = __float2bfloat16(vv[r][1]);
                    float r0 = vv[r][0] - __bfloat162float(h0);
                    float r1 = vv[r][1] - __bfloat162float(h1);
                    __nv_bfloat162 th; th.x = h0; th.y = h1;
                    __nv_bfloat162 tl;
                    tl.x = __float2bfloat16(r0); tl.y = __float2bfloat16(r1);
                    *(__nv_bfloat162*)(c0 + bb[r]) = th;
                    *(__nv_bfloat162*)(c1 + bb[r]) = tl;
                }
            }
        }
        if (MODE == 0 && statsPart) {
            #pragma unroll
            for (int o = 1; o < 4; o <<= 1) {
                s0 += __shfl_xor_sync(0xFFFFFFFFu, s0, o);
                q0 += __shfl_xor_sync(0xFFFFFFFFu, q0, o);
                s1 += __shfl_xor_sync(0xFFFFFFFFu, s1, o);
                q1 += __shfl_xor_sync(0xFFFFFFFFu, q1, o);
            }
            if ((lid & 3) == 0) {
                atomicAdd(&statsPart[row0e], s0);
                atomicAdd(&statsPart[CCH + row0e], q0);
                atomicAdd(&statsPart[row1e], s1);
                atomicAdd(&statsPart[CCH + row1e], q1);
            }
        }
    }
}

// =====================================================================
// prep: all four weight splits + bias stack + stats zero (ONE launch)
// =====================================================================
__global__ void prep_splits(
    const float* __restrict__ th_w, const float* __restrict__ ph_w,
    const float* __restrict__ g_w,  const float* __restrict__ W_w,
    __nv_bfloat16* __restrict__ wtp0, __nv_bfloat16* __restrict__ wtp1,
    __nv_bfloat16* __restrict__ gw0,  __nv_bfloat16* __restrict__ gw1,
    __nv_bfloat16* __restrict__ ww0,  __nv_bfloat16* __restrict__ ww1,
    const float* __restrict__ th_b, const float* __restrict__ ph_b,
    float* __restrict__ tpb, float* __restrict__ stats)
{
    const int i = blockIdx.x * 256 + threadIdx.x;   // 0 .. 4*131072-1
    const int arr = i >> 17;
    const int off = i & 131071;
    const float* src;
    __nv_bfloat16 *dh, *dl;
    switch (arr) {
        case 0:  src = th_w; dh = wtp0;          dl = wtp1;          break;
        case 1:  src = ph_w; dh = wtp0 + 131072; dl = wtp1 + 131072; break;
        case 2:  src = g_w;  dh = gw0;           dl = gw1;           break;
        default: src = W_w;  dh = ww0;           dl = ww1;           break;
    }
    const float v = src[off];
    const __nv_bfloat16 hh = __float2bfloat16(v);
    dh[off] = hh;
    dl[off] = __float2bfloat16(v - __bfloat162float(hh));

    if (i < 512)  tpb[i]  = (i < 256) ? th_b[i] : ph_b[i - 256];
    if (i < 1024) stats[i] = 0.f;
}

// =====================================================================
// transpose + 2-level split of x
// =====================================================================
__global__ void transpose_split2(const float* __restrict__ x,
                                 __nv_bfloat16* __restrict__ h,
                                 __nv_bfloat16* __restrict__ l)
{
    __shared__ float t[32][33];
    const int b = blockIdx.z;
    const int n0 = blockIdx.x * 32, c0 = blockIdx.y * 32;
    const float* xb = x + (size_t)b * CCH * NPIX;
    #pragma unroll
    for (int k = 0; k < 4; k++) {
        const int c = c0 + threadIdx.y + k * 8;
        t[threadIdx.y + k * 8][threadIdx.x] = xb[(size_t)c * NPIX + n0 + threadIdx.x];
    }
    __syncthreads();
    const size_t ob = (size_t)b * NPIX * CCH;
    #pragma unroll
    for (int k = 0; k < 4; k++) {
        const int n = n0 + threadIdx.y + k * 8;
        const float v = t[threadIdx.x][threadIdx.y + k * 8];
        const size_t idx = ob + (size_t)n * CCH + c0 + threadIdx.x;
        __nv_bfloat16 hh = __float2bfloat16(v);
        h[idx] = hh;
        l[idx] = __float2bfloat16(v - __bfloat162float(hh));
    }
}

__global__ __launch_bounds__(256) void softmax_split(
    const float* __restrict__ fp, __nv_bfloat16* __restrict__ h, __nv_bfloat16* __restrict__ l)
{
    const int row = blockIdx.x;        // b*256 + c
    const int b = row >> 8, c = row & 255;
    const int d = threadIdx.x;
    float v = 0.f;
    #pragma unroll
    for (int s = 0; s < FSPLIT; s++)
        v += fp[((size_t)(b * FSPLIT + s)) * (CI * CI) + c * CI + d];
    __shared__ float red[256];
    red[d] = v; __syncthreads();
    for (int o = 128; o > 0; o >>= 1) {
        if (d < o) red[d] = fmaxf(red[d], red[d + o]);
        __syncthreads();
    }
    const float mx = red[0];
    __syncthreads();
    const float e = __expf(v - mx);
    red[d] = e; __syncthreads();
    for (int o = 128; o > 0; o >>= 1) {
        if (d < o) red[d] += red[d + o];
        __syncthreads();
    }
    const float p = e / red[0];
    const size_t idx = (size_t)row * CI + d;
    __nv_bfloat16 hh = __float2bfloat16(p);
    h[idx] = hh; l[idx] = __float2bfloat16(p - __bfloat162float(hh));
}

// =====================================================================
// BN (finalize folded in) + residual
// =====================================================================
__global__ __launch_bounds__(256) void bn_residual(
    const float* __restrict__ z, const float* __restrict__ x,
    const float* __restrict__ gamma, const float* __restrict__ beta,
    const float* __restrict__ stats, float* __restrict__ out)
{
    const size_t i = (size_t)blockIdx.x * blockDim.x + threadIdx.x;
    const int c = (int)((i >> 10) & (CCH - 1));
    const float cnt = (float)(BATCH * NPIX);
    const float m = stats[c] / cnt;
    const float var = stats[CCH + c] / cnt - m * m;
    const float r = rsqrtf(var + 1e-5f);
    const float g = gamma[c], bb = beta[c];
    const float4 zv = ((const float4*)z)[i];
    const float4 xv = ((const float4*)x)[i];
    float4 o;
    o.x = (zv.x - m) * r * g + bb + xv.x;
    o.y = (zv.y - m) * r * g + bb + xv.y;
    o.z = (zv.z - m) * r * g + bb + xv.z;
    o.w = (zv.w - m) * r * g + bb + xv.w;
    ((float4*)out)[i] = o;
}

// =====================================================================
// launch
// =====================================================================
extern "C" void kernel_launch(void* const* d_in, const int* in_sizes, int n_in,
                              void* d_out, int out_size)
{
    (void)in_sizes; (void)n_in; (void)out_size;
    const float* x     = (const float*)d_in[0];
    const float* g_w   = (const float*)d_in[1];
    const float* g_b   = (const float*)d_in[2];
    const float* th_w  = (const float*)d_in[3];
    const float* th_b  = (const float*)d_in[4];
    const float* ph_w  = (const float*)d_in[5];
    const float* ph_b  = (const float*)d_in[6];
    const float* W_w   = (const float*)d_in[7];
    const float* gamma = (const float*)d_in[9];
    const float* beta  = (const float*)d_in[10];
    float* out = (float*)d_out;

    __nv_bfloat16 *xt, *wtp, *gw, *ww, *tp, *gt, *fsm, *yt;
    float *fpart, *z, *stats, *tpb;
    cudaGetSymbolAddress((void**)&xt,    d_xt);
    cudaGetSymbolAddress((void**)&wtp,   d_wtp);
    cudaGetSymbolAddress((void**)&gw,    d_gw);
    cudaGetSymbolAddress((void**)&ww,    d_ww);
    cudaGetSymbolAddress((void**)&tp,    d_tp);
    cudaGetSymbolAddress((void**)&gt,    d_gt);
    cudaGetSymbolAddress((void**)&fpart, d_fpart);
    cudaGetSymbolAddress((void**)&fsm,   d_fsm);
    cudaGetSymbolAddress((void**)&yt,    d_yt);
    cudaGetSymbolAddress((void**)&z,     d_z);
    cudaGetSymbolAddress((void**)&stats, d_stats);
    cudaGetSymbolAddress((void**)&tpb,   d_tpb);

    __nv_bfloat16 *xt0 = xt, *xt1 = xt + XT_SZ;
    __nv_bfloat16 *wtp0 = wtp, *wtp1 = wtp + 512 * 512;
    __nv_bfloat16 *gw0 = gw, *gw1 = gw + CI * CCH;
    __nv_bfloat16 *ww0 = ww, *ww1 = ww + CCH * CI;
    __nv_bfloat16 *tp0 = tp, *tp1 = tp + TP_SZ;
    __nv_bfloat16 *gt0 = gt, *gt1 = gt + GT_SZ;
    __nv_bfloat16 *fs0 = fsm, *fs1 = fsm + F_SZ;
    __nv_bfloat16 *yt0 = yt, *yt1 = yt + YT_SZ;

    const int SMEM = 2 * 24576 + 1024;   // 2-stage, K-chunk 32: 50176 B -> 4 CTAs/SM

    auto* k1a = mma_nt<1, 512,  NPIX, CCH, 1>;
    auto* k1b = mma_nt<1, NPIX, CI,   CCH, 1>;
    auto* k2  = mma_nt<0, CI,   CI,   NPIX, FSPLIT>;
    auto* k3  = mma_nt<1, NPIX, CI,   CI,  1>;
    auto* k4  = mma_nt<0, 512,  NPIX, CI,  1>;
    cudaFuncSetAttribute(k1a, cudaFuncAttributeMaxDynamicSharedMemorySize, SMEM);
    cudaFuncSetAttribute(k1b, cudaFuncAttributeMaxDynamicSharedMemorySize, SMEM);
    cudaFuncSetAttribute(k2,  cudaFuncAttributeMaxDynamicSharedMemorySize, SMEM);
    cudaFuncSetAttribute(k3,  cudaFuncAttributeMaxDynamicSharedMemorySize, SMEM);
    cudaFuncSetAttribute(k4,  cudaFuncAttributeMaxDynamicSharedMemorySize, SMEM);

    // one prep launch: 4 weight splits + bias stack + stats zero
    prep_splits<<<(4 * 131072) / 256, 256>>>(
        th_w, ph_w, g_w, W_w,
        wtp0, wtp1, gw0, gw1, ww0, ww1,
        th_b, ph_b, tpb, stats);

    // xT 2-level split: (B, 4096, 512)
    transpose_split2<<<dim3(NPIX / 32, CCH / 32, BATCH), dim3(32, 8)>>>(x, xt0, xt1);

    // GEMM1a: tp[b](512,4096) = Wtp(512,512) @ xT[b]^T (+ [th_b;ph_b] per row), hi/lo out
    k1a<<<dim3(NPIX / 128, 512 / 64, BATCH), 128, SMEM>>>(
        wtp0, wtp1, xt0, xt1,
        nullptr, tp0, tp1, tpb, nullptr, nullptr,
        0, (long long)NPIX * CCH, 512LL * NPIX);

    // GEMM1b: gT[b](4096,256) = xT[b] @ g_w^T (+ g_b per col), hi/lo out
    k1b<<<dim3(CI / 128, NPIX / 64, BATCH), 128, SMEM>>>(
        xt0, xt1, gw0, gw1,
        nullptr, gt0, gt1, nullptr, g_b, nullptr,
        (long long)NPIX * CCH, 0, (long long)NPIX * CI);

    // GEMM2: f partials = theta @ phi^T, split-K 8, fp32 out
    k2<<<dim3(CI / 128, CI / 64, BATCH * FSPLIT), 128, SMEM>>>(
        tp0, tp1,
        tp0 + (size_t)CI * NPIX, tp1 + (size_t)CI * NPIX,
        fpart, nullptr, nullptr, nullptr, nullptr, nullptr,
        512LL * NPIX, 512LL * NPIX, (long long)CI * CI);

    // softmax (sums FSPLIT partials) -> hi/lo bf16
    softmax_split<<<BATCH * CI, 256>>>(fpart, fs0, fs1);

    // GEMM3: yT[b](4096,256) = gT[b] @ fsm[b]^T, hi/lo out
    k3<<<dim3(CI / 128, NPIX / 64, BATCH), 128, SMEM>>>(
        gt0, gt1, fs0, fs1,
        nullptr, yt0, yt1, nullptr, nullptr, nullptr,
        (long long)NPIX * CI, (long long)CI * CI, (long long)NPIX * CI);

    // GEMM4: z[b](512,4096) = W_w @ yT[b]^T (W_b dropped: cancels in BN),
    //        fp32 out + fused per-channel stats partials
    k4<<<dim3(NPIX / 128, 512 / 64, BATCH), 128, SMEM>>>(
        ww0, ww1, yt0, yt1,
        z, nullptr, nullptr, nullptr, nullptr, stats,
        0, (long long)NPIX * CI, (long long)CCH * NPIX);

    // BN (finalize folded) + residual
    const size_t total4 = (size_t)BATCH * CCH * NPIX / 4;
    bn_residual<<<(unsigned)(total4 / 256), 256>>>(z, x, gamma, beta, stats, out);
}